// round 1
// baseline (speedup 1.0000x reference)
#include <cuda_runtime.h>
#include <math.h>

#define NTOK 8192
#define DIMC 1024
#define HIDC 2048
#define NRE  6

// ---- scratch (device globals: allocation-free) ----
__device__ float g_h[(size_t)NTOK * HIDC];       // 64 MB activation scratch
__device__ float g_comb[(size_t)NTOK * DIMC];    // 32 MB combined accumulator
__device__ int   g_list[NRE * NTOK];
__device__ float g_lw[NRE * NTOK];
__device__ int   g_cnt[NRE];
__device__ int   g_top1[NRE];
__device__ float g_psum[NRE];

__global__ void zero_kernel() {
    int t = threadIdx.x;
    if (t < NRE) { g_cnt[t] = 0; g_top1[t] = 0; g_psum[t] = 0.f; }
}

// ---- gate: logits, top-2 softmax, full softmax stats, expert gather lists ----
__global__ void __launch_bounds__(256) gate_kernel(const float* __restrict__ x,
                                                   const float* __restrict__ gw) {
    __shared__ float sgw[DIMC * NRE];  // 24 KB
    int tid = threadIdx.x;
    for (int i = tid; i < DIMC * NRE; i += 256) sgw[i] = gw[i];
    __syncthreads();

    int warp = tid >> 5, lane = tid & 31;
    int token = blockIdx.x * 8 + warp;
    if (token >= NTOK) return;
    const float* xr = x + (size_t)token * DIMC;

    float acc[NRE] = {0.f, 0.f, 0.f, 0.f, 0.f, 0.f};
    for (int k = lane; k < DIMC; k += 32) {
        float xv = xr[k];
#pragma unroll
        for (int e = 0; e < NRE; e++) acc[e] += xv * sgw[k * NRE + e];
    }
#pragma unroll
    for (int e = 0; e < NRE; e++)
#pragma unroll
        for (int o = 16; o > 0; o >>= 1)
            acc[e] += __shfl_xor_sync(0xffffffffu, acc[e], o);

    if (lane == 0) {
        // top-2 (first-index wins ties, matching jax top_k)
        int i0 = 0; float v0 = acc[0];
        for (int e = 1; e < NRE; e++) if (acc[e] > v0) { v0 = acc[e]; i0 = e; }
        int i1 = -1; float v1 = -1e30f;
        for (int e = 0; e < NRE; e++) if (e != i0 && acc[e] > v1) { v1 = acc[e]; i1 = e; }
        // softmax over the two selected logits
        float e2 = expf(v1 - v0);
        float inv = 1.0f / (1.0f + e2);
        float w0 = inv, w1 = e2 * inv;
        // full softmax for aux stats
        float p[NRE]; float s = 0.f;
        for (int e = 0; e < NRE; e++) { p[e] = expf(acc[e] - v0); s += p[e]; }
        float is = 1.0f / s;
        for (int e = 0; e < NRE; e++) atomicAdd(&g_psum[e], p[e] * is);
        atomicAdd(&g_top1[i0], 1);
        int p0 = atomicAdd(&g_cnt[i0], 1);
        g_list[i0 * NTOK + p0] = token; g_lw[i0 * NTOK + p0] = w0;
        int p1 = atomicAdd(&g_cnt[i1], 1);
        g_list[i1 * NTOK + p1] = token; g_lw[i1 * NTOK + p1] = w1;
    }
}

__global__ void aux_kernel(float* dst) {
    float a = 0.f;
    for (int e = 0; e < NRE; e++) {
        float f = (float)g_top1[e] / (float)NTOK;
        float pm = g_psum[e] / (float)NTOK;
        a += f * pm;
    }
    *dst = 0.01f * (float)NRE * a;
}

// ---- pass1: h[r,:] = silu(xg @ w1) * (xg @ w3) * scale  (dual GEMM, fused) ----
// 128x64 tile, BK=8, 256 threads, 8x4 micro per operand
__global__ void __launch_bounds__(256) pass1_kernel(
    const float* __restrict__ X,
    const float* __restrict__ W1,
    const float* __restrict__ W3,
    const int*   __restrict__ gidx,
    const float* __restrict__ gscale,
    const int*   __restrict__ cntPtr)
{
    const int M = cntPtr ? *cntPtr : NTOK;
    const int mBase = blockIdx.y * 128;
    if (mBase >= M) return;
    const int nBase = blockIdx.x * 64;

    __shared__ float As[8][128];
    __shared__ float B1s[8][64];
    __shared__ float B3s[8][64];
    __shared__ int sIdx[128];

    const int tid = threadIdx.x;
    if (tid < 128) {
        int r = mBase + tid;
        sIdx[tid] = (r < M) ? (gidx ? gidx[r] : r) : -1;
    }
    __syncthreads();

    const int aRow = tid >> 1;
    const int aCol = (tid & 1) << 2;
    const long aSrc = sIdx[aRow];
    const int bRow = (tid & 127) >> 4;
    const int bCol = (tid & 15) << 2;
    const int bsel = tid >> 7;
    const float* Bp = bsel ? W3 : W1;

    const int ty = tid >> 4, tx = tid & 15;

    float acc1[8][4], acc3[8][4];
#pragma unroll
    for (int i = 0; i < 8; i++)
#pragma unroll
        for (int j = 0; j < 4; j++) { acc1[i][j] = 0.f; acc3[i][j] = 0.f; }

    for (int k0 = 0; k0 < DIMC; k0 += 8) {
        float4 av = make_float4(0.f, 0.f, 0.f, 0.f);
        if (aSrc >= 0) av = *(const float4*)(X + aSrc * DIMC + k0 + aCol);
        As[aCol + 0][aRow] = av.x; As[aCol + 1][aRow] = av.y;
        As[aCol + 2][aRow] = av.z; As[aCol + 3][aRow] = av.w;
        float4 bv = *(const float4*)(Bp + (size_t)(k0 + bRow) * HIDC + nBase + bCol);
        if (bsel) *(float4*)&B3s[bRow][bCol] = bv;
        else      *(float4*)&B1s[bRow][bCol] = bv;
        __syncthreads();
#pragma unroll
        for (int kk = 0; kk < 8; kk++) {
            float a[8], b1v[4], b3v[4];
#pragma unroll
            for (int i = 0; i < 8; i++) a[i] = As[kk][ty * 8 + i];
#pragma unroll
            for (int j = 0; j < 4; j++) { b1v[j] = B1s[kk][tx * 4 + j]; b3v[j] = B3s[kk][tx * 4 + j]; }
#pragma unroll
            for (int i = 0; i < 8; i++)
#pragma unroll
                for (int j = 0; j < 4; j++) {
                    acc1[i][j] += a[i] * b1v[j];
                    acc3[i][j] += a[i] * b3v[j];
                }
        }
        __syncthreads();
    }

#pragma unroll
    for (int i = 0; i < 8; i++) {
        int r = mBase + ty * 8 + i;
        if (r < M) {
            float sc = gscale ? gscale[r] : 1.0f;
#pragma unroll
            for (int j = 0; j < 4; j++) {
                float u = acc1[i][j];
                float h = (u / (1.0f + __expf(-u))) * acc3[i][j] * sc;
                g_h[(size_t)r * HIDC + nBase + tx * 4 + j] = h;
            }
        }
    }
}

// ---- pass2 / out-proj: C[crow,:] (+)= A[r,:] @ B  (128x128 tile, BK=8) ----
__global__ void __launch_bounds__(256) pass2_kernel(
    const float* __restrict__ A, int lda, int K,
    const float* __restrict__ B,
    float* __restrict__ C,
    const int*  __restrict__ gidx,
    const int*  __restrict__ cntPtr,
    int accFlag)
{
    const int M = cntPtr ? *cntPtr : NTOK;
    const int mBase = blockIdx.y * 128;
    if (mBase >= M) return;
    const int nBase = blockIdx.x * 128;

    __shared__ float As[8][128];
    __shared__ float Bs[8][128];
    __shared__ int sIdx[128];

    const int tid = threadIdx.x;
    if (tid < 128) {
        int r = mBase + tid;
        sIdx[tid] = (r < M) ? (gidx ? gidx[r] : r) : -1;
    }
    __syncthreads();

    const int aRow = tid >> 1;
    const int aCol = (tid & 1) << 2;
    const bool aOK = (mBase + aRow) < M;
    const int bRow = tid >> 5;
    const int bCol = (tid & 31) << 2;
    const int ty = tid >> 4, tx = tid & 15;

    float acc[8][8];
#pragma unroll
    for (int i = 0; i < 8; i++)
#pragma unroll
        for (int j = 0; j < 8; j++) acc[i][j] = 0.f;

    for (int k0 = 0; k0 < K; k0 += 8) {
        float4 av = make_float4(0.f, 0.f, 0.f, 0.f);
        if (aOK) av = *(const float4*)(A + (size_t)(mBase + aRow) * lda + k0 + aCol);
        As[aCol + 0][aRow] = av.x; As[aCol + 1][aRow] = av.y;
        As[aCol + 2][aRow] = av.z; As[aCol + 3][aRow] = av.w;
        float4 bv = *(const float4*)(B + (size_t)(k0 + bRow) * DIMC + nBase + bCol);
        *(float4*)&Bs[bRow][bCol] = bv;
        __syncthreads();
#pragma unroll
        for (int kk = 0; kk < 8; kk++) {
            float a[8], b[8];
#pragma unroll
            for (int i = 0; i < 8; i++) a[i] = As[kk][ty * 8 + i];
#pragma unroll
            for (int j = 0; j < 8; j++) b[j] = Bs[kk][tx * 8 + j];
#pragma unroll
            for (int i = 0; i < 8; i++)
#pragma unroll
                for (int j = 0; j < 8; j++) acc[i][j] += a[i] * b[j];
        }
        __syncthreads();
    }

#pragma unroll
    for (int i = 0; i < 8; i++) {
        int r = mBase + ty * 8 + i;
        if (r < M) {
            int crow = sIdx[ty * 8 + i];
            float* cp = C + (size_t)crow * DIMC + nBase + tx * 8;
            if (accFlag) {
#pragma unroll
                for (int j = 0; j < 8; j++) cp[j] += acc[i][j];
            } else {
#pragma unroll
                for (int j = 0; j < 8; j++) cp[j] = acc[i][j];
            }
        }
    }
}

extern "C" void kernel_launch(void* const* d_in, const int* in_sizes, int n_in,
                              void* d_out, int out_size)
{
    const float* x      = (const float*)d_in[0];
    const float* w1_s   = (const float*)d_in[1];
    const float* w2_s   = (const float*)d_in[2];
    const float* w3_s   = (const float*)d_in[3];
    const float* w1_r   = (const float*)d_in[4];
    const float* w2_r   = (const float*)d_in[5];
    const float* w3_r   = (const float*)d_in[6];
    const float* gate_w = (const float*)d_in[7];
    const float* out_w  = (const float*)d_in[8];
    float* out = (float*)d_out;

    float *hbuf, *comb, *lw; int *list, *cnt;
    cudaGetSymbolAddress((void**)&hbuf, g_h);
    cudaGetSymbolAddress((void**)&comb, g_comb);
    cudaGetSymbolAddress((void**)&list, g_list);
    cudaGetSymbolAddress((void**)&lw,   g_lw);
    cudaGetSymbolAddress((void**)&cnt,  g_cnt);

    zero_kernel<<<1, 32>>>();
    gate_kernel<<<NTOK / 8, 256>>>(x, gate_w);
    if (out_size > NTOK * DIMC)
        aux_kernel<<<1, 1>>>(out + (out_size - 1));

    dim3 g1(HIDC / 64, NTOK / 128);   // (32, 64)
    dim3 g2(DIMC / 128, NTOK / 128);  // (8, 64)

    // shared experts (dense, all tokens)
    for (int e = 0; e < 2; e++) {
        pass1_kernel<<<g1, 256>>>(x,
            w1_s + (size_t)e * DIMC * HIDC,
            w3_s + (size_t)e * DIMC * HIDC,
            nullptr, nullptr, nullptr);
        pass2_kernel<<<g2, 256>>>(hbuf, HIDC, HIDC,
            w2_s + (size_t)e * HIDC * DIMC,
            comb, nullptr, nullptr, e > 0 ? 1 : 0);
    }
    // routed experts (sparse: gathered token lists, weight folded into pass1)
    for (int e = 0; e < NRE; e++) {
        pass1_kernel<<<g1, 256>>>(x,
            w1_r + (size_t)e * DIMC * HIDC,
            w3_r + (size_t)e * DIMC * HIDC,
            list + e * NTOK, lw + e * NTOK, cnt + e);
        pass2_kernel<<<g2, 256>>>(hbuf, HIDC, HIDC,
            w2_r + (size_t)e * HIDC * DIMC,
            comb, list + e * NTOK, cnt + e, 1);
    }
    // final projection: out = combined @ out_w
    pass2_kernel<<<g2, 256>>>(comb, DIMC, DIMC, out_w, out,
                              nullptr, nullptr, 0);
}

// round 2
// speedup vs baseline: 1.0008x; 1.0008x over previous
#include <cuda_runtime.h>
#include <math.h>

#define NTOK 8192
#define DIMC 1024
#define HIDC 2048
#define NRE  6

// ---- scratch (device globals: allocation-free) ----
__device__ float g_h[(size_t)NTOK * HIDC];       // 64 MB activation scratch
__device__ float g_comb[(size_t)NTOK * DIMC];    // 32 MB combined accumulator
__device__ int   g_list[NRE * NTOK];
__device__ float g_lw[NRE * NTOK];
__device__ int   g_cnt[NRE];
__device__ int   g_top1[NRE];
__device__ float g_psum[NRE];

__global__ void zero_kernel() {
    int t = threadIdx.x;
    if (t < NRE) { g_cnt[t] = 0; g_top1[t] = 0; g_psum[t] = 0.f; }
}

// ---- gate: logits, top-2 softmax, full softmax stats, expert gather lists ----
__global__ void __launch_bounds__(256) gate_kernel(const float* __restrict__ x,
                                                   const float* __restrict__ gw) {
    __shared__ float sgw[DIMC * NRE];  // 24 KB
    int tid = threadIdx.x;
    for (int i = tid; i < DIMC * NRE; i += 256) sgw[i] = gw[i];
    __syncthreads();

    int warp = tid >> 5, lane = tid & 31;
    int token = blockIdx.x * 8 + warp;
    if (token >= NTOK) return;
    const float* xr = x + (size_t)token * DIMC;

    float acc[NRE] = {0.f, 0.f, 0.f, 0.f, 0.f, 0.f};
    for (int k = lane; k < DIMC; k += 32) {
        float xv = xr[k];
#pragma unroll
        for (int e = 0; e < NRE; e++) acc[e] += xv * sgw[k * NRE + e];
    }
#pragma unroll
    for (int e = 0; e < NRE; e++)
#pragma unroll
        for (int o = 16; o > 0; o >>= 1)
            acc[e] += __shfl_xor_sync(0xffffffffu, acc[e], o);

    if (lane == 0) {
        // top-2 (first-index wins ties, matching jax top_k)
        int i0 = 0; float v0 = acc[0];
        for (int e = 1; e < NRE; e++) if (acc[e] > v0) { v0 = acc[e]; i0 = e; }
        int i1 = -1; float v1 = -1e30f;
        for (int e = 0; e < NRE; e++) if (e != i0 && acc[e] > v1) { v1 = acc[e]; i1 = e; }
        // softmax over the two selected logits
        float e2 = expf(v1 - v0);
        float inv = 1.0f / (1.0f + e2);
        float w0 = inv, w1 = e2 * inv;
        // full softmax for aux stats
        float p[NRE]; float s = 0.f;
        for (int e = 0; e < NRE; e++) { p[e] = expf(acc[e] - v0); s += p[e]; }
        float is = 1.0f / s;
        for (int e = 0; e < NRE; e++) atomicAdd(&g_psum[e], p[e] * is);
        atomicAdd(&g_top1[i0], 1);
        int p0 = atomicAdd(&g_cnt[i0], 1);
        g_list[i0 * NTOK + p0] = token; g_lw[i0 * NTOK + p0] = w0;
        int p1 = atomicAdd(&g_cnt[i1], 1);
        g_list[i1 * NTOK + p1] = token; g_lw[i1 * NTOK + p1] = w1;
    }
}

__global__ void aux_kernel(float* dst) {
    float a = 0.f;
    for (int e = 0; e < NRE; e++) {
        float f = (float)g_top1[e] / (float)NTOK;
        float pm = g_psum[e] / (float)NTOK;
        a += f * pm;
    }
    *dst = 0.01f * (float)NRE * a;
}

// ---- pass1: h[r,:] = silu(xg @ w1) * (xg @ w3) * scale  (dual GEMM, fused) ----
// 128x64 tile, BK=8, 256 threads, 8x4 micro per operand
__global__ void __launch_bounds__(256) pass1_kernel(
    const float* __restrict__ X,
    const float* __restrict__ W1,
    const float* __restrict__ W3,
    const int*   __restrict__ gidx,
    const float* __restrict__ gscale,
    const int*   __restrict__ cntPtr)
{
    const int M = cntPtr ? *cntPtr : NTOK;
    const int mBase = blockIdx.y * 128;
    if (mBase >= M) return;
    const int nBase = blockIdx.x * 64;

    __shared__ float As[8][128];
    __shared__ float B1s[8][64];
    __shared__ float B3s[8][64];
    __shared__ int sIdx[128];

    const int tid = threadIdx.x;
    if (tid < 128) {
        int r = mBase + tid;
        sIdx[tid] = (r < M) ? (gidx ? gidx[r] : r) : -1;
    }
    __syncthreads();

    const int aRow = tid >> 1;
    const int aCol = (tid & 1) << 2;
    const long aSrc = sIdx[aRow];
    const int bRow = (tid & 127) >> 4;
    const int bCol = (tid & 15) << 2;
    const int bsel = tid >> 7;
    const float* Bp = bsel ? W3 : W1;

    const int ty = tid >> 4, tx = tid & 15;

    float acc1[8][4], acc3[8][4];
#pragma unroll
    for (int i = 0; i < 8; i++)
#pragma unroll
        for (int j = 0; j < 4; j++) { acc1[i][j] = 0.f; acc3[i][j] = 0.f; }

    for (int k0 = 0; k0 < DIMC; k0 += 8) {
        float4 av = make_float4(0.f, 0.f, 0.f, 0.f);
        if (aSrc >= 0) av = *(const float4*)(X + aSrc * DIMC + k0 + aCol);
        As[aCol + 0][aRow] = av.x; As[aCol + 1][aRow] = av.y;
        As[aCol + 2][aRow] = av.z; As[aCol + 3][aRow] = av.w;
        float4 bv = *(const float4*)(Bp + (size_t)(k0 + bRow) * HIDC + nBase + bCol);
        if (bsel) *(float4*)&B3s[bRow][bCol] = bv;
        else      *(float4*)&B1s[bRow][bCol] = bv;
        __syncthreads();
#pragma unroll
        for (int kk = 0; kk < 8; kk++) {
            float a[8], b1v[4], b3v[4];
#pragma unroll
            for (int i = 0; i < 8; i++) a[i] = As[kk][ty * 8 + i];
#pragma unroll
            for (int j = 0; j < 4; j++) { b1v[j] = B1s[kk][tx * 4 + j]; b3v[j] = B3s[kk][tx * 4 + j]; }
#pragma unroll
            for (int i = 0; i < 8; i++)
#pragma unroll
                for (int j = 0; j < 4; j++) {
                    acc1[i][j] += a[i] * b1v[j];
                    acc3[i][j] += a[i] * b3v[j];
                }
        }
        __syncthreads();
    }

#pragma unroll
    for (int i = 0; i < 8; i++) {
        int r = mBase + ty * 8 + i;
        if (r < M) {
            float sc = gscale ? gscale[r] : 1.0f;
#pragma unroll
            for (int j = 0; j < 4; j++) {
                float u = acc1[i][j];
                float h = (u / (1.0f + __expf(-u))) * acc3[i][j] * sc;
                g_h[(size_t)r * HIDC + nBase + tx * 4 + j] = h;
            }
        }
    }
}

// ---- pass2 / out-proj: C[crow,:] (+)= A[r,:] @ B  (128x128 tile, BK=8) ----
__global__ void __launch_bounds__(256) pass2_kernel(
    const float* __restrict__ A, int lda, int K,
    const float* __restrict__ B,
    float* __restrict__ C,
    const int*  __restrict__ gidx,
    const int*  __restrict__ cntPtr,
    int accFlag)
{
    const int M = cntPtr ? *cntPtr : NTOK;
    const int mBase = blockIdx.y * 128;
    if (mBase >= M) return;
    const int nBase = blockIdx.x * 128;

    __shared__ float As[8][128];
    __shared__ float Bs[8][128];
    __shared__ int sIdx[128];

    const int tid = threadIdx.x;
    if (tid < 128) {
        int r = mBase + tid;
        sIdx[tid] = (r < M) ? (gidx ? gidx[r] : r) : -1;
    }
    __syncthreads();

    const int aRow = tid >> 1;
    const int aCol = (tid & 1) << 2;
    const bool aOK = (mBase + aRow) < M;
    const int bRow = tid >> 5;
    const int bCol = (tid & 31) << 2;
    const int ty = tid >> 4, tx = tid & 15;

    float acc[8][8];
#pragma unroll
    for (int i = 0; i < 8; i++)
#pragma unroll
        for (int j = 0; j < 8; j++) acc[i][j] = 0.f;

    for (int k0 = 0; k0 < K; k0 += 8) {
        float4 av = make_float4(0.f, 0.f, 0.f, 0.f);
        if (aOK) av = *(const float4*)(A + (size_t)(mBase + aRow) * lda + k0 + aCol);
        As[aCol + 0][aRow] = av.x; As[aCol + 1][aRow] = av.y;
        As[aCol + 2][aRow] = av.z; As[aCol + 3][aRow] = av.w;
        float4 bv = *(const float4*)(B + (size_t)(k0 + bRow) * DIMC + nBase + bCol);
        *(float4*)&Bs[bRow][bCol] = bv;
        __syncthreads();
#pragma unroll
        for (int kk = 0; kk < 8; kk++) {
            float a[8], b[8];
#pragma unroll
            for (int i = 0; i < 8; i++) a[i] = As[kk][ty * 8 + i];
#pragma unroll
            for (int j = 0; j < 8; j++) b[j] = Bs[kk][tx * 8 + j];
#pragma unroll
            for (int i = 0; i < 8; i++)
#pragma unroll
                for (int j = 0; j < 8; j++) acc[i][j] += a[i] * b[j];
        }
        __syncthreads();
    }

#pragma unroll
    for (int i = 0; i < 8; i++) {
        int r = mBase + ty * 8 + i;
        if (r < M) {
            int crow = sIdx[ty * 8 + i];
            float* cp = C + (size_t)crow * DIMC + nBase + tx * 8;
            if (accFlag) {
#pragma unroll
                for (int j = 0; j < 8; j++) cp[j] += acc[i][j];
            } else {
#pragma unroll
                for (int j = 0; j < 8; j++) cp[j] = acc[i][j];
            }
        }
    }
}

extern "C" void kernel_launch(void* const* d_in, const int* in_sizes, int n_in,
                              void* d_out, int out_size)
{
    const float* x      = (const float*)d_in[0];
    const float* w1_s   = (const float*)d_in[1];
    const float* w2_s   = (const float*)d_in[2];
    const float* w3_s   = (const float*)d_in[3];
    const float* w1_r   = (const float*)d_in[4];
    const float* w2_r   = (const float*)d_in[5];
    const float* w3_r   = (const float*)d_in[6];
    const float* gate_w = (const float*)d_in[7];
    const float* out_w  = (const float*)d_in[8];
    float* out = (float*)d_out;

    float *hbuf, *comb, *lw; int *list, *cnt;
    cudaGetSymbolAddress((void**)&hbuf, g_h);
    cudaGetSymbolAddress((void**)&comb, g_comb);
    cudaGetSymbolAddress((void**)&list, g_list);
    cudaGetSymbolAddress((void**)&lw,   g_lw);
    cudaGetSymbolAddress((void**)&cnt,  g_cnt);

    zero_kernel<<<1, 32>>>();
    gate_kernel<<<NTOK / 8, 256>>>(x, gate_w);
    if (out_size > NTOK * DIMC)
        aux_kernel<<<1, 1>>>(out + (out_size - 1));

    dim3 g1(HIDC / 64, NTOK / 128);   // (32, 64)
    dim3 g2(DIMC / 128, NTOK / 128);  // (8, 64)

    // shared experts (dense, all tokens)
    for (int e = 0; e < 2; e++) {
        pass1_kernel<<<g1, 256>>>(x,
            w1_s + (size_t)e * DIMC * HIDC,
            w3_s + (size_t)e * DIMC * HIDC,
            nullptr, nullptr, nullptr);
        pass2_kernel<<<g2, 256>>>(hbuf, HIDC, HIDC,
            w2_s + (size_t)e * HIDC * DIMC,
            comb, nullptr, nullptr, e > 0 ? 1 : 0);
    }
    // routed experts (sparse: gathered token lists, weight folded into pass1)
    for (int e = 0; e < NRE; e++) {
        pass1_kernel<<<g1, 256>>>(x,
            w1_r + (size_t)e * DIMC * HIDC,
            w3_r + (size_t)e * DIMC * HIDC,
            list + e * NTOK, lw + e * NTOK, cnt + e);
        pass2_kernel<<<g2, 256>>>(hbuf, HIDC, HIDC,
            w2_r + (size_t)e * HIDC * DIMC,
            comb, list + e * NTOK, cnt + e, 1);
    }
    // final projection: out = combined @ out_w
    pass2_kernel<<<g2, 256>>>(comb, DIMC, DIMC, out_w, out,
                              nullptr, nullptr, 0);
}

// round 4
// speedup vs baseline: 2.2607x; 2.2590x over previous
#include <cuda_runtime.h>
#include <cuda_bf16.h>
#include <math.h>
#include <stdint.h>

typedef __nv_bfloat16 bf16;

#define NTOK 8192
#define DIMC 1024
#define HIDC 2048
#define NRE  6

// weight arena offsets (elements; each expert matrix = 2M elements)
#define W1S_OFF 0ull
#define W3S_OFF (4ull<<20)
#define W2S_OFF (8ull<<20)
#define W1R_OFF (12ull<<20)
#define W3R_OFF (24ull<<20)
#define W2R_OFF (36ull<<20)
#define OUTW_OFF (48ull<<20)
#define WT_TOTAL (49ull<<20)

// ---- device global scratch (allocation-free) ----
__device__ bf16 g_wthi[WT_TOTAL];
__device__ bf16 g_wtlo[WT_TOTAL];
__device__ bf16 g_xhi[(size_t)NTOK * DIMC];
__device__ bf16 g_xlo[(size_t)NTOK * DIMC];
__device__ bf16 g_hhi[(size_t)NTOK * HIDC];   // also reused for comb hi
__device__ bf16 g_hlo[(size_t)NTOK * HIDC];   // also reused for comb lo
__device__ float g_comb[(size_t)NTOK * DIMC];
__device__ int   g_list[NRE * NTOK];
__device__ float g_lw[NRE * NTOK];
__device__ int   g_cnt[NRE];
__device__ int   g_top1[NRE];
__device__ float g_psum[NRE];

// ===================== helpers =====================
__device__ __forceinline__ uint32_t s2u(const void* p) {
    return (uint32_t)__cvta_generic_to_shared(p);
}
__device__ __forceinline__ void cpa(uint32_t s, const void* g) {
    asm volatile("cp.async.cg.shared.global [%0], [%1], 16;" :: "r"(s), "l"(g));
}
__device__ __forceinline__ void cpa_commit() {
    asm volatile("cp.async.commit_group;" ::: "memory");
}
__device__ __forceinline__ void ldsm4(uint32_t* r, uint32_t addr) {
    asm volatile("ldmatrix.sync.aligned.m8n8.x4.shared.b16 {%0,%1,%2,%3}, [%4];"
        : "=r"(r[0]), "=r"(r[1]), "=r"(r[2]), "=r"(r[3]) : "r"(addr));
}
__device__ __forceinline__ void mma16816(float* d, const uint32_t* a, const uint32_t* b) {
    asm volatile("mma.sync.aligned.m16n8k16.row.col.f32.bf16.bf16.f32 "
        "{%0,%1,%2,%3}, {%4,%5,%6,%7}, {%8,%9}, {%0,%1,%2,%3};"
        : "+f"(d[0]), "+f"(d[1]), "+f"(d[2]), "+f"(d[3])
        : "r"(a[0]), "r"(a[1]), "r"(a[2]), "r"(a[3]), "r"(b[0]), "r"(b[1]));
}
__device__ __forceinline__ void split2(float a, float b, uint32_t& hi, uint32_t& lo) {
    bf16 ha = __float2bfloat16_rn(a), hb = __float2bfloat16_rn(b);
    bf16 la = __float2bfloat16_rn(a - __bfloat162float(ha));
    bf16 lb = __float2bfloat16_rn(b - __bfloat162float(hb));
    __nv_bfloat162 H, L; H.x = ha; H.y = hb; L.x = la; L.y = lb;
    hi = *(uint32_t*)&H; lo = *(uint32_t*)&L;
}

// ===================== small kernels =====================
__global__ void zero_kernel() {
    int t = threadIdx.x;
    if (t < NRE) { g_cnt[t] = 0; g_top1[t] = 0; g_psum[t] = 0.f; }
}

__global__ void __launch_bounds__(256) gate_kernel(const float* __restrict__ x,
                                                   const float* __restrict__ gw) {
    __shared__ float sgw[DIMC * NRE];
    int tid = threadIdx.x;
    for (int i = tid; i < DIMC * NRE; i += 256) sgw[i] = gw[i];
    __syncthreads();
    int warp = tid >> 5, lane = tid & 31;
    int token = blockIdx.x * 8 + warp;
    if (token >= NTOK) return;
    const float* xr = x + (size_t)token * DIMC;
    float acc[NRE] = {0.f, 0.f, 0.f, 0.f, 0.f, 0.f};
    for (int k = lane; k < DIMC; k += 32) {
        float xv = xr[k];
#pragma unroll
        for (int e = 0; e < NRE; e++) acc[e] += xv * sgw[k * NRE + e];
    }
#pragma unroll
    for (int e = 0; e < NRE; e++)
#pragma unroll
        for (int o = 16; o > 0; o >>= 1)
            acc[e] += __shfl_xor_sync(0xffffffffu, acc[e], o);
    if (lane == 0) {
        int i0 = 0; float v0 = acc[0];
        for (int e = 1; e < NRE; e++) if (acc[e] > v0) { v0 = acc[e]; i0 = e; }
        int i1 = -1; float v1 = -1e30f;
        for (int e = 0; e < NRE; e++) if (e != i0 && acc[e] > v1) { v1 = acc[e]; i1 = e; }
        float e2 = expf(v1 - v0);
        float inv = 1.0f / (1.0f + e2);
        float w0 = inv, w1 = e2 * inv;
        float p[NRE]; float s = 0.f;
        for (int e = 0; e < NRE; e++) { p[e] = expf(acc[e] - v0); s += p[e]; }
        float is = 1.0f / s;
        for (int e = 0; e < NRE; e++) atomicAdd(&g_psum[e], p[e] * is);
        atomicAdd(&g_top1[i0], 1);
        int p0 = atomicAdd(&g_cnt[i0], 1);
        g_list[i0 * NTOK + p0] = token; g_lw[i0 * NTOK + p0] = w0;
        int p1 = atomicAdd(&g_cnt[i1], 1);
        g_list[i1 * NTOK + p1] = token; g_lw[i1 * NTOK + p1] = w1;
    }
}

__global__ void aux_kernel(float* dst) {
    float a = 0.f;
    for (int e = 0; e < NRE; e++) {
        float f = (float)g_top1[e] / (float)NTOK;
        float pm = g_psum[e] / (float)NTOK;
        a += f * pm;
    }
    *dst = 0.01f * (float)NRE * a;
}

// x (fp32) -> xhi/xlo bf16
__global__ void __launch_bounds__(256) convx_kernel(const float* __restrict__ x) {
    size_t i = (size_t)blockIdx.x * 256 + threadIdx.x;
    float v = x[i];
    bf16 h = __float2bfloat16_rn(v);
    g_xhi[i] = h;
    g_xlo[i] = __float2bfloat16_rn(v - __bfloat162float(h));
}

// comb (fp32) -> hhi/hlo bf16 (reuses h arena)
__global__ void __launch_bounds__(256) convc_kernel() {
    size_t i = (size_t)blockIdx.x * 256 + threadIdx.x;
    float v = g_comb[i];
    bf16 h = __float2bfloat16_rn(v);
    g_hhi[i] = h;
    g_hlo[i] = __float2bfloat16_rn(v - __bfloat162float(h));
}

// W [K][N] fp32 -> Whi/Wlo [N][K] bf16 (transpose + split)
__global__ void __launch_bounds__(256) convt_kernel(const float* __restrict__ in,
                                                    bf16* __restrict__ ohi,
                                                    bf16* __restrict__ olo,
                                                    int K, int N) {
    __shared__ float t[32][33];
    int k0 = blockIdx.y * 32, n0 = blockIdx.x * 32;
    int tx = threadIdx.x & 31, ty = threadIdx.x >> 5;
#pragma unroll
    for (int i = 0; i < 4; i++)
        t[ty + i * 8][tx] = in[(size_t)(k0 + ty + i * 8) * N + n0 + tx];
    __syncthreads();
#pragma unroll
    for (int i = 0; i < 4; i++) {
        float v = t[tx][ty + i * 8];
        bf16 h = __float2bfloat16_rn(v);
        size_t o = (size_t)(n0 + ty + i * 8) * K + k0 + tx;
        ohi[o] = h;
        olo[o] = __float2bfloat16_rn(v - __bfloat162float(h));
    }
}

// ===================== pass1: h = silu(x@W1)*(x@W3)*scale =====================
// tile 128M x 64N, dual B; warps 4(M) x 2(N), warp tile 32x32 per output.
// smem rows padded to 80B (32 k-elems + 8 pad) -> conflict-free ldmatrix.
#define P1_AH 0
#define P1_AL 10240
#define P1_B1H 20480
#define P1_B1L 25600
#define P1_B3H 30720
#define P1_B3L 35840
#define P1_STG 40960
#define P1_SIDX 81920
#define P1_SMEM 82432

__global__ void __launch_bounds__(256, 1) mm1_kernel(
    const bf16* __restrict__ W1hi, const bf16* __restrict__ W1lo,
    const bf16* __restrict__ W3hi, const bf16* __restrict__ W3lo,
    const int* __restrict__ gidx, const float* __restrict__ gscale,
    const int* __restrict__ cntPtr)
{
    extern __shared__ char smem[];
    const int M = cntPtr ? *cntPtr : NTOK;
    const int mBase = blockIdx.y * 128;
    if (mBase >= M) return;
    const int nBase = blockIdx.x * 64;
    const uint32_t sb = s2u(smem);
    const int tid = threadIdx.x;

    int* sIdx = (int*)(smem + P1_SIDX);
    if (tid < 128) {
        int r = mBase + tid;
        sIdx[tid] = (r < M) ? (gidx ? gidx[r] : r) : 0;
    }
    __syncthreads();

    auto load = [&](int buf, int k0) {
        uint32_t su = sb + buf * P1_STG;
#pragma unroll
        for (int it = 0; it < 2; it++) {
            int idx = tid + it * 256;
            int row = idx >> 2, seg = idx & 3;
            uint32_t so = row * 80 + seg * 16;
            size_t g = (size_t)sIdx[row] * DIMC + k0 + seg * 8;
            cpa(su + P1_AH + so, g_xhi + g);
            cpa(su + P1_AL + so, g_xlo + g);
        }
        {
            int row = tid >> 2, seg = tid & 3;
            uint32_t so = row * 80 + seg * 16;
            size_t g = (size_t)(nBase + row) * DIMC + k0 + seg * 8;
            cpa(su + P1_B1H + so, W1hi + g);
            cpa(su + P1_B1L + so, W1lo + g);
            cpa(su + P1_B3H + so, W3hi + g);
            cpa(su + P1_B3L + so, W3lo + g);
        }
        cpa_commit();
    };

    const int lane = tid & 31, wid = tid >> 5;
    const int wm = (wid & 3) * 32;
    const int wn = (wid >> 2) * 32;
    const int arow = (lane & 7) + ((lane >> 3) & 1) * 8;
    const int akh  = (lane >> 4) & 1;
    const int brow = (lane & 7) + ((lane >> 4) & 1) * 8;
    const int bkh  = (lane >> 3) & 1;

    float acc1[2][4][4], acc3[2][4][4];
#pragma unroll
    for (int i = 0; i < 2; i++)
#pragma unroll
        for (int j = 0; j < 4; j++)
#pragma unroll
            for (int k = 0; k < 4; k++) { acc1[i][j][k] = 0.f; acc3[i][j][k] = 0.f; }

    load(0, 0);
    const int nc = DIMC / 32;
    for (int c = 0; c < nc; c++) {
        if (c + 1 < nc) {
            load((c + 1) & 1, (c + 1) * 32);
            asm volatile("cp.async.wait_group 1;" ::: "memory");
        } else {
            asm volatile("cp.async.wait_group 0;" ::: "memory");
        }
        __syncthreads();
        uint32_t su = sb + (c & 1) * P1_STG;
#pragma unroll
        for (int s = 0; s < 2; s++) {
            uint32_t ah[2][4], al[2][4];
#pragma unroll
            for (int mi = 0; mi < 2; mi++) {
                uint32_t ao = (uint32_t)(wm + mi * 16 + arow) * 80 + s * 32 + akh * 16;
                ldsm4(ah[mi], su + P1_AH + ao);
                ldsm4(al[mi], su + P1_AL + ao);
            }
            uint32_t b1h[2][4], b1l[2][4], b3h[2][4], b3l[2][4];
#pragma unroll
            for (int np = 0; np < 2; np++) {
                uint32_t bo = (uint32_t)(wn + np * 16 + brow) * 80 + s * 32 + bkh * 16;
                ldsm4(b1h[np], su + P1_B1H + bo);
                ldsm4(b1l[np], su + P1_B1L + bo);
                ldsm4(b3h[np], su + P1_B3H + bo);
                ldsm4(b3l[np], su + P1_B3L + bo);
            }
#pragma unroll
            for (int mi = 0; mi < 2; mi++)
#pragma unroll
                for (int np = 0; np < 2; np++)
#pragma unroll
                    for (int h = 0; h < 2; h++) {
                        int nt = np * 2 + h;
                        mma16816(acc1[mi][nt], ah[mi], &b1h[np][h * 2]);
                        mma16816(acc1[mi][nt], ah[mi], &b1l[np][h * 2]);
                        mma16816(acc1[mi][nt], al[mi], &b1h[np][h * 2]);
                        mma16816(acc3[mi][nt], ah[mi], &b3h[np][h * 2]);
                        mma16816(acc3[mi][nt], ah[mi], &b3l[np][h * 2]);
                        mma16816(acc3[mi][nt], al[mi], &b3h[np][h * 2]);
                    }
        }
        __syncthreads();
    }

    // epilogue: silu(acc1)*acc3*scale -> g_hhi/g_hlo (slot-major)
#pragma unroll
    for (int mi = 0; mi < 2; mi++)
#pragma unroll
        for (int half = 0; half < 2; half++) {
            int slot = mBase + wm + mi * 16 + (lane >> 2) + half * 8;
            if (slot < M) {
                float sc = gscale ? gscale[slot] : 1.0f;
                size_t rb = (size_t)slot * HIDC + nBase + wn + (lane & 3) * 2;
#pragma unroll
                for (int nt = 0; nt < 4; nt++) {
                    float u0 = acc1[mi][nt][half * 2 + 0];
                    float u1 = acc1[mi][nt][half * 2 + 1];
                    float v0 = acc3[mi][nt][half * 2 + 0];
                    float v1 = acc3[mi][nt][half * 2 + 1];
                    float h0 = u0 / (1.f + __expf(-u0)) * v0 * sc;
                    float h1 = u1 / (1.f + __expf(-u1)) * v1 * sc;
                    uint32_t ph, pl; split2(h0, h1, ph, pl);
                    *(uint32_t*)(g_hhi + rb + nt * 8) = ph;
                    *(uint32_t*)(g_hlo + rb + nt * 8) = pl;
                }
            }
        }
}

// ===================== pass2: C[crow,:] op= h @ W  (tile 128x128) =====================
// warps 2(M) x 4(N), warp tile 64x32.
// mode: 0 = overwrite cout, 1 = accumulate cout (scatter via gidx), 2 = overwrite cout (no gather)
#define P2_AH 0
#define P2_AL 10240
#define P2_BH 20480
#define P2_BL 30720
#define P2_STG 40960
#define P2_SMEM 82432

__global__ void __launch_bounds__(256, 1) mm2_kernel(
    int K,
    const bf16* __restrict__ Bhi, const bf16* __restrict__ Blo,
    const int* __restrict__ gidx, const int* __restrict__ cntPtr,
    int mode, float* __restrict__ cout)
{
    extern __shared__ char smem[];
    const int M = cntPtr ? *cntPtr : NTOK;
    const int mBase = blockIdx.y * 128;
    if (mBase >= M) return;
    const int nBase = blockIdx.x * 128;
    const uint32_t sb = s2u(smem);
    const int tid = threadIdx.x;

    auto load = [&](int buf, int k0) {
        uint32_t su = sb + buf * P2_STG;
#pragma unroll
        for (int it = 0; it < 2; it++) {
            int idx = tid + it * 256;
            int row = idx >> 2, seg = idx & 3;
            uint32_t so = row * 80 + seg * 16;
            int ar = mBase + row; if (ar >= M) ar = mBase;
            size_t g = (size_t)ar * K + k0 + seg * 8;
            cpa(su + P2_AH + so, g_hhi + g);
            cpa(su + P2_AL + so, g_hlo + g);
        }
#pragma unroll
        for (int it = 0; it < 2; it++) {
            int idx = tid + it * 256;
            int row = idx >> 2, seg = idx & 3;
            uint32_t so = row * 80 + seg * 16;
            size_t g = (size_t)(nBase + row) * K + k0 + seg * 8;
            cpa(su + P2_BH + so, Bhi + g);
            cpa(su + P2_BL + so, Blo + g);
        }
        cpa_commit();
    };

    const int lane = tid & 31, wid = tid >> 5;
    const int wm = (wid & 1) * 64;
    const int wn = (wid >> 1) * 32;
    const int arow = (lane & 7) + ((lane >> 3) & 1) * 8;
    const int akh  = (lane >> 4) & 1;
    const int brow = (lane & 7) + ((lane >> 4) & 1) * 8;
    const int bkh  = (lane >> 3) & 1;

    float acc[4][4][4];
#pragma unroll
    for (int i = 0; i < 4; i++)
#pragma unroll
        for (int j = 0; j < 4; j++)
#pragma unroll
            for (int k = 0; k < 4; k++) acc[i][j][k] = 0.f;

    load(0, 0);
    const int nc = K / 32;
    for (int c = 0; c < nc; c++) {
        if (c + 1 < nc) {
            load((c + 1) & 1, (c + 1) * 32);
            asm volatile("cp.async.wait_group 1;" ::: "memory");
        } else {
            asm volatile("cp.async.wait_group 0;" ::: "memory");
        }
        __syncthreads();
        uint32_t su = sb + (c & 1) * P2_STG;
#pragma unroll
        for (int s = 0; s < 2; s++) {
            uint32_t ah[4][4], al[4][4];
#pragma unroll
            for (int mi = 0; mi < 4; mi++) {
                uint32_t ao = (uint32_t)(wm + mi * 16 + arow) * 80 + s * 32 + akh * 16;
                ldsm4(ah[mi], su + P2_AH + ao);
                ldsm4(al[mi], su + P2_AL + ao);
            }
            uint32_t bh[2][4], bl[2][4];
#pragma unroll
            for (int np = 0; np < 2; np++) {
                uint32_t bo = (uint32_t)(wn + np * 16 + brow) * 80 + s * 32 + bkh * 16;
                ldsm4(bh[np], su + P2_BH + bo);
                ldsm4(bl[np], su + P2_BL + bo);
            }
#pragma unroll
            for (int mi = 0; mi < 4; mi++)
#pragma unroll
                for (int np = 0; np < 2; np++)
#pragma unroll
                    for (int h = 0; h < 2; h++) {
                        int nt = np * 2 + h;
                        mma16816(acc[mi][nt], ah[mi], &bh[np][h * 2]);
                        mma16816(acc[mi][nt], ah[mi], &bl[np][h * 2]);
                        mma16816(acc[mi][nt], al[mi], &bh[np][h * 2]);
                    }
        }
        __syncthreads();
    }

#pragma unroll
    for (int mi = 0; mi < 4; mi++)
#pragma unroll
        for (int half = 0; half < 2; half++) {
            int slot = mBase + wm + mi * 16 + (lane >> 2) + half * 8;
            if (slot < M) {
                int crow = (mode == 1 && gidx) ? gidx[slot] : slot;
                float* cp = cout + (size_t)crow * DIMC + nBase + wn + (lane & 3) * 2;
#pragma unroll
                for (int nt = 0; nt < 4; nt++) {
                    float2 v = make_float2(acc[mi][nt][half * 2 + 0],
                                           acc[mi][nt][half * 2 + 1]);
                    if (mode == 1) {
                        float2 o = *(float2*)(cp + nt * 8);
                        v.x += o.x; v.y += o.y;
                    }
                    *(float2*)(cp + nt * 8) = v;
                }
            }
        }
}

// ===================== host =====================
extern "C" void kernel_launch(void* const* d_in, const int* in_sizes, int n_in,
                              void* d_out, int out_size)
{
    const float* x      = (const float*)d_in[0];
    const float* w1_s   = (const float*)d_in[1];
    const float* w2_s   = (const float*)d_in[2];
    const float* w3_s   = (const float*)d_in[3];
    const float* w1_r   = (const float*)d_in[4];
    const float* w2_r   = (const float*)d_in[5];
    const float* w3_r   = (const float*)d_in[6];
    const float* gate_w = (const float*)d_in[7];
    const float* out_w  = (const float*)d_in[8];
    float* out = (float*)d_out;

    bf16 *wthi, *wtlo;
    int *list, *cnt; float *lw, *comb;
    cudaGetSymbolAddress((void**)&wthi, g_wthi);
    cudaGetSymbolAddress((void**)&wtlo, g_wtlo);
    cudaGetSymbolAddress((void**)&list, g_list);
    cudaGetSymbolAddress((void**)&lw, g_lw);
    cudaGetSymbolAddress((void**)&cnt, g_cnt);
    cudaGetSymbolAddress((void**)&comb, g_comb);

    cudaFuncSetAttribute(mm1_kernel, cudaFuncAttributeMaxDynamicSharedMemorySize, P1_SMEM);
    cudaFuncSetAttribute(mm2_kernel, cudaFuncAttributeMaxDynamicSharedMemorySize, P2_SMEM);

    zero_kernel<<<1, 32>>>();
    gate_kernel<<<NTOK / 8, 256>>>(x, gate_w);
    if (out_size > NTOK * DIMC)
        aux_kernel<<<1, 1>>>(out + (out_size - 1));

    // conversions
    convx_kernel<<<(NTOK * DIMC) / 256, 256>>>(x);
    const size_t E2 = 2ull << 20;
    dim3 gHN(HIDC / 32, DIMC / 32);
    dim3 gNH(DIMC / 32, HIDC / 32);
    dim3 gNN(DIMC / 32, DIMC / 32);
    for (int e = 0; e < 2; e++) {
        convt_kernel<<<gHN, 256>>>(w1_s + e * E2, wthi + W1S_OFF + e * E2, wtlo + W1S_OFF + e * E2, DIMC, HIDC);
        convt_kernel<<<gHN, 256>>>(w3_s + e * E2, wthi + W3S_OFF + e * E2, wtlo + W3S_OFF + e * E2, DIMC, HIDC);
        convt_kernel<<<gNH, 256>>>(w2_s + e * E2, wthi + W2S_OFF + e * E2, wtlo + W2S_OFF + e * E2, HIDC, DIMC);
    }
    for (int e = 0; e < 6; e++) {
        convt_kernel<<<gHN, 256>>>(w1_r + e * E2, wthi + W1R_OFF + e * E2, wtlo + W1R_OFF + e * E2, DIMC, HIDC);
        convt_kernel<<<gHN, 256>>>(w3_r + e * E2, wthi + W3R_OFF + e * E2, wtlo + W3R_OFF + e * E2, DIMC, HIDC);
        convt_kernel<<<gNH, 256>>>(w2_r + e * E2, wthi + W2R_OFF + e * E2, wtlo + W2R_OFF + e * E2, HIDC, DIMC);
    }
    convt_kernel<<<gNN, 256>>>(out_w, wthi + OUTW_OFF, wtlo + OUTW_OFF, DIMC, DIMC);

    dim3 g1(HIDC / 64, NTOK / 128);   // (32, 64)
    dim3 g2(DIMC / 128, NTOK / 128);  // (8, 64)

    // shared experts (dense)
    for (int e = 0; e < 2; e++) {
        mm1_kernel<<<g1, 256, P1_SMEM>>>(
            wthi + W1S_OFF + e * E2, wtlo + W1S_OFF + e * E2,
            wthi + W3S_OFF + e * E2, wtlo + W3S_OFF + e * E2,
            nullptr, nullptr, nullptr);
        mm2_kernel<<<g2, 256, P2_SMEM>>>(
            HIDC, wthi + W2S_OFF + e * E2, wtlo + W2S_OFF + e * E2,
            nullptr, nullptr, e == 0 ? 0 : 1, comb);
    }
    // routed experts (sparse)
    for (int e = 0; e < 6; e++) {
        mm1_kernel<<<g1, 256, P1_SMEM>>>(
            wthi + W1R_OFF + e * E2, wtlo + W1R_OFF + e * E2,
            wthi + W3R_OFF + e * E2, wtlo + W3R_OFF + e * E2,
            list + e * NTOK, lw + e * NTOK, cnt + e);
        mm2_kernel<<<g2, 256, P2_SMEM>>>(
            HIDC, wthi + W2R_OFF + e * E2, wtlo + W2R_OFF + e * E2,
            list + e * NTOK, cnt + e, 1, comb);
    }
    // out projection: comb -> bf16 hi/lo (reuse h arena), then GEMM
    convc_kernel<<<(NTOK * DIMC) / 256, 256>>>();
    mm2_kernel<<<g2, 256, P2_SMEM>>>(
        DIMC, wthi + OUTW_OFF, wtlo + OUTW_OFF,
        nullptr, nullptr, 2, out);
}

// round 5
// speedup vs baseline: 2.4327x; 1.0761x over previous
#include <cuda_runtime.h>
#include <cuda_bf16.h>
#include <math.h>
#include <stdint.h>

typedef __nv_bfloat16 bf16;

#define NTOK 8192
#define DIMC 1024
#define HIDC 2048
#define NRE  6

#define W1S_OFF 0ull
#define W3S_OFF (4ull<<20)
#define W2S_OFF (8ull<<20)
#define W1R_OFF (12ull<<20)
#define W3R_OFF (24ull<<20)
#define W2R_OFF (36ull<<20)
#define OUTW_OFF (48ull<<20)
#define WT_TOTAL (49ull<<20)

__device__ bf16 g_wthi[WT_TOTAL];
__device__ bf16 g_wtlo[WT_TOTAL];
__device__ bf16 g_xhi[(size_t)NTOK * DIMC];
__device__ bf16 g_xlo[(size_t)NTOK * DIMC];
__device__ bf16 g_hhi[(size_t)NTOK * HIDC];   // also comb hi
__device__ bf16 g_hlo[(size_t)NTOK * HIDC];   // also comb lo
__device__ float g_comb[(size_t)NTOK * DIMC];
__device__ int   g_list[NRE * NTOK];
__device__ float g_lw[NRE * NTOK];
__device__ int   g_cnt[NRE];
__device__ int   g_top1[NRE];
__device__ float g_psum[NRE];

// ===================== helpers =====================
__device__ __forceinline__ uint32_t s2u(const void* p) {
    return (uint32_t)__cvta_generic_to_shared(p);
}
__device__ __forceinline__ void cpa(uint32_t s, const void* g) {
    asm volatile("cp.async.cg.shared.global [%0], [%1], 16;" :: "r"(s), "l"(g));
}
__device__ __forceinline__ void cpa_commit() {
    asm volatile("cp.async.commit_group;" ::: "memory");
}
__device__ __forceinline__ void ldsm4(uint32_t* r, uint32_t addr) {
    asm volatile("ldmatrix.sync.aligned.m8n8.x4.shared.b16 {%0,%1,%2,%3}, [%4];"
        : "=r"(r[0]), "=r"(r[1]), "=r"(r[2]), "=r"(r[3]) : "r"(addr));
}
__device__ __forceinline__ void mma16816(float* d, const uint32_t* a, const uint32_t* b) {
    asm volatile("mma.sync.aligned.m16n8k16.row.col.f32.bf16.bf16.f32 "
        "{%0,%1,%2,%3}, {%4,%5,%6,%7}, {%8,%9}, {%0,%1,%2,%3};"
        : "+f"(d[0]), "+f"(d[1]), "+f"(d[2]), "+f"(d[3])
        : "r"(a[0]), "r"(a[1]), "r"(a[2]), "r"(a[3]), "r"(b[0]), "r"(b[1]));
}
__device__ __forceinline__ void split2(float a, float b, uint32_t& hi, uint32_t& lo) {
    bf16 ha = __float2bfloat16_rn(a), hb = __float2bfloat16_rn(b);
    bf16 la = __float2bfloat16_rn(a - __bfloat162float(ha));
    bf16 lb = __float2bfloat16_rn(b - __bfloat162float(hb));
    __nv_bfloat162 H, L; H.x = ha; H.y = hb; L.x = la; L.y = lb;
    hi = *(uint32_t*)&H; lo = *(uint32_t*)&L;
}

// ===================== small kernels =====================
__global__ void zero_kernel() {
    int t = threadIdx.x;
    if (t < NRE) { g_cnt[t] = 0; g_top1[t] = 0; g_psum[t] = 0.f; }
}

__global__ void __launch_bounds__(256) gate_kernel(const float* __restrict__ x,
                                                   const float* __restrict__ gw) {
    __shared__ float sgw[DIMC * NRE];
    int tid = threadIdx.x;
    for (int i = tid; i < DIMC * NRE; i += 256) sgw[i] = gw[i];
    __syncthreads();
    int warp = tid >> 5, lane = tid & 31;
    int token = blockIdx.x * 8 + warp;
    if (token >= NTOK) return;
    const float* xr = x + (size_t)token * DIMC;
    float acc[NRE] = {0.f, 0.f, 0.f, 0.f, 0.f, 0.f};
    for (int k = lane; k < DIMC; k += 32) {
        float xv = xr[k];
#pragma unroll
        for (int e = 0; e < NRE; e++) acc[e] += xv * sgw[k * NRE + e];
    }
#pragma unroll
    for (int e = 0; e < NRE; e++)
#pragma unroll
        for (int o = 16; o > 0; o >>= 1)
            acc[e] += __shfl_xor_sync(0xffffffffu, acc[e], o);
    if (lane == 0) {
        int i0 = 0; float v0 = acc[0];
        for (int e = 1; e < NRE; e++) if (acc[e] > v0) { v0 = acc[e]; i0 = e; }
        int i1 = -1; float v1 = -1e30f;
        for (int e = 0; e < NRE; e++) if (e != i0 && acc[e] > v1) { v1 = acc[e]; i1 = e; }
        float e2 = expf(v1 - v0);
        float inv = 1.0f / (1.0f + e2);
        float w0 = inv, w1 = e2 * inv;
        float p[NRE]; float s = 0.f;
        for (int e = 0; e < NRE; e++) { p[e] = expf(acc[e] - v0); s += p[e]; }
        float is = 1.0f / s;
        for (int e = 0; e < NRE; e++) atomicAdd(&g_psum[e], p[e] * is);
        atomicAdd(&g_top1[i0], 1);
        int p0 = atomicAdd(&g_cnt[i0], 1);
        g_list[i0 * NTOK + p0] = token; g_lw[i0 * NTOK + p0] = w0;
        int p1 = atomicAdd(&g_cnt[i1], 1);
        g_list[i1 * NTOK + p1] = token; g_lw[i1 * NTOK + p1] = w1;
    }
}

__global__ void aux_kernel(float* dst) {
    float a = 0.f;
    for (int e = 0; e < NRE; e++) {
        float f = (float)g_top1[e] / (float)NTOK;
        float pm = g_psum[e] / (float)NTOK;
        a += f * pm;
    }
    *dst = 0.01f * (float)NRE * a;
}

__global__ void __launch_bounds__(256) convx_kernel(const float* __restrict__ x) {
    size_t i = (size_t)blockIdx.x * 256 + threadIdx.x;
    float v = x[i];
    bf16 h = __float2bfloat16_rn(v);
    g_xhi[i] = h;
    g_xlo[i] = __float2bfloat16_rn(v - __bfloat162float(h));
}

__global__ void __launch_bounds__(256) convc_kernel() {
    size_t i = (size_t)blockIdx.x * 256 + threadIdx.x;
    float v = g_comb[i];
    bf16 h = __float2bfloat16_rn(v);
    g_hhi[i] = h;
    g_hlo[i] = __float2bfloat16_rn(v - __bfloat162float(h));
}

// W [K][N] fp32 -> [N][K] bf16 hi/lo
__global__ void __launch_bounds__(256) convt_kernel(const float* __restrict__ in,
                                                    bf16* __restrict__ ohi,
                                                    bf16* __restrict__ olo,
                                                    int K, int N) {
    __shared__ float t[32][33];
    int k0 = blockIdx.y * 32, n0 = blockIdx.x * 32;
    int tx = threadIdx.x & 31, ty = threadIdx.x >> 5;
#pragma unroll
    for (int i = 0; i < 4; i++)
        t[ty + i * 8][tx] = in[(size_t)(k0 + ty + i * 8) * N + n0 + tx];
    __syncthreads();
#pragma unroll
    for (int i = 0; i < 4; i++) {
        float v = t[tx][ty + i * 8];
        bf16 h = __float2bfloat16_rn(v);
        size_t o = (size_t)(n0 + ty + i * 8) * K + k0 + tx;
        ohi[o] = h;
        olo[o] = __float2bfloat16_rn(v - __bfloat162float(h));
    }
}

// ===================== mm1: h = silu(x@W1)*(x@W3)*scale =====================
// tile 128M x 128N, chunk K=32, warps 4(M)x2(N), warp tile 32x64, pitch 80B
#define P1_AH 0
#define P1_AL 10240
#define P1_B1H 20480
#define P1_B1L 30720
#define P1_B3H 40960
#define P1_B3L 51200
#define P1_STG 61440
#define P1_SIDX 122880
#define P1_SMEM 123392

__global__ void __launch_bounds__(256, 1) mm1_kernel(
    const bf16* __restrict__ W1hi, const bf16* __restrict__ W1lo,
    const bf16* __restrict__ W3hi, const bf16* __restrict__ W3lo,
    const int* __restrict__ gidx, const float* __restrict__ gscale,
    const int* __restrict__ cntPtr)
{
    extern __shared__ char smem[];
    const int M = cntPtr ? *cntPtr : NTOK;
    const int mBase = blockIdx.y * 128;
    if (mBase >= M) return;
    const int nBase = blockIdx.x * 128;
    const uint32_t sb = s2u(smem);
    const int tid = threadIdx.x;

    int* sIdx = (int*)(smem + P1_SIDX);
    if (tid < 128) {
        int r = mBase + tid;
        sIdx[tid] = (r < M) ? (gidx ? gidx[r] : r) : 0;
    }
    __syncthreads();

    auto load = [&](int buf, int k0) {
        uint32_t su = sb + buf * P1_STG;
#pragma unroll
        for (int it = 0; it < 2; it++) {
            int idx = tid + it * 256;
            int row = idx >> 2, seg = idx & 3;
            uint32_t so = row * 80 + seg * 16;
            size_t g = (size_t)sIdx[row] * DIMC + k0 + seg * 8;
            cpa(su + P1_AH + so, g_xhi + g);
            cpa(su + P1_AL + so, g_xlo + g);
        }
#pragma unroll
        for (int it = 0; it < 2; it++) {
            int idx = tid + it * 256;
            int row = idx >> 2, seg = idx & 3;
            uint32_t so = row * 80 + seg * 16;
            size_t g = (size_t)(nBase + row) * DIMC + k0 + seg * 8;
            cpa(su + P1_B1H + so, W1hi + g);
            cpa(su + P1_B1L + so, W1lo + g);
            cpa(su + P1_B3H + so, W3hi + g);
            cpa(su + P1_B3L + so, W3lo + g);
        }
        cpa_commit();
    };

    const int lane = tid & 31, wid = tid >> 5;
    const int wm = (wid & 3) * 32;
    const int wn = (wid >> 2) * 64;
    const int arow = (lane & 7) + ((lane >> 3) & 1) * 8;
    const int akh  = (lane >> 4) & 1;
    const int brow = (lane & 7) + ((lane >> 4) & 1) * 8;
    const int bkh  = (lane >> 3) & 1;

    float acc1[2][8][4], acc3[2][8][4];
#pragma unroll
    for (int i = 0; i < 2; i++)
#pragma unroll
        for (int j = 0; j < 8; j++)
#pragma unroll
            for (int k = 0; k < 4; k++) { acc1[i][j][k] = 0.f; acc3[i][j][k] = 0.f; }

    load(0, 0);
    const int nc = DIMC / 32;
    for (int c = 0; c < nc; c++) {
        if (c + 1 < nc) {
            load((c + 1) & 1, (c + 1) * 32);
            asm volatile("cp.async.wait_group 1;" ::: "memory");
        } else {
            asm volatile("cp.async.wait_group 0;" ::: "memory");
        }
        __syncthreads();
        uint32_t su = sb + (c & 1) * P1_STG;
#pragma unroll
        for (int s = 0; s < 2; s++) {
            uint32_t ah[2][4], al[2][4];
#pragma unroll
            for (int mi = 0; mi < 2; mi++) {
                uint32_t ao = (uint32_t)(wm + mi * 16 + arow) * 80 + s * 32 + akh * 16;
                ldsm4(ah[mi], su + P1_AH + ao);
                ldsm4(al[mi], su + P1_AL + ao);
            }
#pragma unroll
            for (int np = 0; np < 4; np++) {
                uint32_t b1h[4], b1l[4], b3h[4], b3l[4];
                uint32_t bo = (uint32_t)(wn + np * 16 + brow) * 80 + s * 32 + bkh * 16;
                ldsm4(b1h, su + P1_B1H + bo);
                ldsm4(b1l, su + P1_B1L + bo);
                ldsm4(b3h, su + P1_B3H + bo);
                ldsm4(b3l, su + P1_B3L + bo);
#pragma unroll
                for (int mi = 0; mi < 2; mi++)
#pragma unroll
                    for (int h = 0; h < 2; h++) {
                        int nt = np * 2 + h;
                        mma16816(acc1[mi][nt], ah[mi], &b1h[h * 2]);
                        mma16816(acc1[mi][nt], ah[mi], &b1l[h * 2]);
                        mma16816(acc1[mi][nt], al[mi], &b1h[h * 2]);
                        mma16816(acc3[mi][nt], ah[mi], &b3h[h * 2]);
                        mma16816(acc3[mi][nt], ah[mi], &b3l[h * 2]);
                        mma16816(acc3[mi][nt], al[mi], &b3h[h * 2]);
                    }
            }
        }
        __syncthreads();
    }

#pragma unroll
    for (int mi = 0; mi < 2; mi++)
#pragma unroll
        for (int half = 0; half < 2; half++) {
            int slot = mBase + wm + mi * 16 + (lane >> 2) + half * 8;
            if (slot < M) {
                float sc = gscale ? gscale[slot] : 1.0f;
                size_t rb = (size_t)slot * HIDC + nBase + wn + (lane & 3) * 2;
#pragma unroll
                for (int nt = 0; nt < 8; nt++) {
                    float u0 = acc1[mi][nt][half * 2 + 0];
                    float u1 = acc1[mi][nt][half * 2 + 1];
                    float v0 = acc3[mi][nt][half * 2 + 0];
                    float v1 = acc3[mi][nt][half * 2 + 1];
                    float h0 = u0 / (1.f + __expf(-u0)) * v0 * sc;
                    float h1 = u1 / (1.f + __expf(-u1)) * v1 * sc;
                    uint32_t ph, pl; split2(h0, h1, ph, pl);
                    *(uint32_t*)(g_hhi + rb + nt * 8) = ph;
                    *(uint32_t*)(g_hlo + rb + nt * 8) = pl;
                }
            }
        }
}

// ===================== mm2: C[crow,:] op= h @ W  (tile 128x128, chunk 64) =====================
#define P2_AH 0
#define P2_AL 18432
#define P2_BH 36864
#define P2_BL 55296
#define P2_STG 73728
#define P2_SMEM 147968

__global__ void __launch_bounds__(256, 1) mm2_kernel(
    int K,
    const bf16* __restrict__ Bhi, const bf16* __restrict__ Blo,
    const int* __restrict__ gidx, const int* __restrict__ cntPtr,
    int mode, float* __restrict__ cout)
{
    extern __shared__ char smem[];
    const int M = cntPtr ? *cntPtr : NTOK;
    const int mBase = blockIdx.y * 128;
    if (mBase >= M) return;
    const int nBase = blockIdx.x * 128;
    const uint32_t sb = s2u(smem);
    const int tid = threadIdx.x;

    auto load = [&](int buf, int k0) {
        uint32_t su = sb + buf * P2_STG;
#pragma unroll
        for (int it = 0; it < 4; it++) {
            int idx = tid + it * 256;
            int row = idx >> 3, seg = idx & 7;
            uint32_t so = row * 144 + seg * 16;
            int ar = mBase + row; if (ar >= M) ar = mBase;
            size_t g = (size_t)ar * K + k0 + seg * 8;
            cpa(su + P2_AH + so, g_hhi + g);
            cpa(su + P2_AL + so, g_hlo + g);
        }
#pragma unroll
        for (int it = 0; it < 4; it++) {
            int idx = tid + it * 256;
            int row = idx >> 3, seg = idx & 7;
            uint32_t so = row * 144 + seg * 16;
            size_t g = (size_t)(nBase + row) * K + k0 + seg * 8;
            cpa(su + P2_BH + so, Bhi + g);
            cpa(su + P2_BL + so, Blo + g);
        }
        cpa_commit();
    };

    const int lane = tid & 31, wid = tid >> 5;
    const int wm = (wid & 1) * 64;
    const int wn = (wid >> 1) * 32;
    const int arow = (lane & 7) + ((lane >> 3) & 1) * 8;
    const int akh  = (lane >> 4) & 1;
    const int brow = (lane & 7) + ((lane >> 4) & 1) * 8;
    const int bkh  = (lane >> 3) & 1;

    float acc[4][4][4];
#pragma unroll
    for (int i = 0; i < 4; i++)
#pragma unroll
        for (int j = 0; j < 4; j++)
#pragma unroll
            for (int k = 0; k < 4; k++) acc[i][j][k] = 0.f;

    load(0, 0);
    const int nc = K / 64;
    for (int c = 0; c < nc; c++) {
        if (c + 1 < nc) {
            load((c + 1) & 1, (c + 1) * 64);
            asm volatile("cp.async.wait_group 1;" ::: "memory");
        } else {
            asm volatile("cp.async.wait_group 0;" ::: "memory");
        }
        __syncthreads();
        uint32_t su = sb + (c & 1) * P2_STG;
#pragma unroll
        for (int s = 0; s < 4; s++) {
            uint32_t ah[4][4], al[4][4];
#pragma unroll
            for (int mi = 0; mi < 4; mi++) {
                uint32_t ao = (uint32_t)(wm + mi * 16 + arow) * 144 + s * 32 + akh * 16;
                ldsm4(ah[mi], su + P2_AH + ao);
                ldsm4(al[mi], su + P2_AL + ao);
            }
#pragma unroll
            for (int np = 0; np < 2; np++) {
                uint32_t bh[4], bl[4];
                uint32_t bo = (uint32_t)(wn + np * 16 + brow) * 144 + s * 32 + bkh * 16;
                ldsm4(bh, su + P2_BH + bo);
                ldsm4(bl, su + P2_BL + bo);
#pragma unroll
                for (int mi = 0; mi < 4; mi++)
#pragma unroll
                    for (int h = 0; h < 2; h++) {
                        int nt = np * 2 + h;
                        mma16816(acc[mi][nt], ah[mi], &bh[h * 2]);
                        mma16816(acc[mi][nt], ah[mi], &bl[h * 2]);
                        mma16816(acc[mi][nt], al[mi], &bh[h * 2]);
                    }
            }
        }
        __syncthreads();
    }

#pragma unroll
    for (int mi = 0; mi < 4; mi++)
#pragma unroll
        for (int half = 0; half < 2; half++) {
            int slot = mBase + wm + mi * 16 + (lane >> 2) + half * 8;
            if (slot < M) {
                int crow = (mode == 1 && gidx) ? gidx[slot] : slot;
                float* cp = cout + (size_t)crow * DIMC + nBase + wn + (lane & 3) * 2;
#pragma unroll
                for (int nt = 0; nt < 4; nt++) {
                    float2 v = make_float2(acc[mi][nt][half * 2 + 0],
                                           acc[mi][nt][half * 2 + 1]);
                    if (mode == 1) {
                        float2 o = *(float2*)(cp + nt * 8);
                        v.x += o.x; v.y += o.y;
                    }
                    *(float2*)(cp + nt * 8) = v;
                }
            }
        }
}

// ===================== host =====================
extern "C" void kernel_launch(void* const* d_in, const int* in_sizes, int n_in,
                              void* d_out, int out_size)
{
    const float* x      = (const float*)d_in[0];
    const float* w1_s   = (const float*)d_in[1];
    const float* w2_s   = (const float*)d_in[2];
    const float* w3_s   = (const float*)d_in[3];
    const float* w1_r   = (const float*)d_in[4];
    const float* w2_r   = (const float*)d_in[5];
    const float* w3_r   = (const float*)d_in[6];
    const float* gate_w = (const float*)d_in[7];
    const float* out_w  = (const float*)d_in[8];
    float* out = (float*)d_out;

    bf16 *wthi, *wtlo;
    int *list, *cnt; float *lw, *comb;
    cudaGetSymbolAddress((void**)&wthi, g_wthi);
    cudaGetSymbolAddress((void**)&wtlo, g_wtlo);
    cudaGetSymbolAddress((void**)&list, g_list);
    cudaGetSymbolAddress((void**)&lw, g_lw);
    cudaGetSymbolAddress((void**)&cnt, g_cnt);
    cudaGetSymbolAddress((void**)&comb, g_comb);

    cudaFuncSetAttribute(mm1_kernel, cudaFuncAttributeMaxDynamicSharedMemorySize, P1_SMEM);
    cudaFuncSetAttribute(mm2_kernel, cudaFuncAttributeMaxDynamicSharedMemorySize, P2_SMEM);

    const size_t E2 = 2ull << 20;
    dim3 gHN(HIDC / 32, DIMC / 32);
    dim3 gNH(DIMC / 32, HIDC / 32);
    dim3 gNN(DIMC / 32, DIMC / 32);
    dim3 g1(HIDC / 128, NTOK / 128);  // (16, 64)
    dim3 g2(DIMC / 128, NTOK / 128);  // (8, 64)

    // launches 1-5: minimal prereqs so launch #6 is mm1 (ncu -s 5 -c 1)
    convx_kernel<<<(NTOK * DIMC) / 256, 256>>>(x);                                     // 1
    convt_kernel<<<gHN, 256>>>(w1_s, wthi + W1S_OFF, wtlo + W1S_OFF, DIMC, HIDC);      // 2
    convt_kernel<<<gHN, 256>>>(w3_s, wthi + W3S_OFF, wtlo + W3S_OFF, DIMC, HIDC);      // 3
    zero_kernel<<<1, 32>>>();                                                          // 4
    gate_kernel<<<NTOK / 8, 256>>>(x, gate_w);                                         // 5
    mm1_kernel<<<g1, 256, P1_SMEM>>>(                                                  // 6 (profiled)
        wthi + W1S_OFF, wtlo + W1S_OFF, wthi + W3S_OFF, wtlo + W3S_OFF,
        nullptr, nullptr, nullptr);

    if (out_size > NTOK * DIMC)
        aux_kernel<<<1, 1>>>(out + (out_size - 1));

    // remaining conversions
    convt_kernel<<<gHN, 256>>>(w1_s + E2, wthi + W1S_OFF + E2, wtlo + W1S_OFF + E2, DIMC, HIDC);
    convt_kernel<<<gHN, 256>>>(w3_s + E2, wthi + W3S_OFF + E2, wtlo + W3S_OFF + E2, DIMC, HIDC);
    for (int e = 0; e < 2; e++)
        convt_kernel<<<gNH, 256>>>(w2_s + e * E2, wthi + W2S_OFF + e * E2, wtlo + W2S_OFF + e * E2, HIDC, DIMC);
    for (int e = 0; e < 6; e++) {
        convt_kernel<<<gHN, 256>>>(w1_r + e * E2, wthi + W1R_OFF + e * E2, wtlo + W1R_OFF + e * E2, DIMC, HIDC);
        convt_kernel<<<gHN, 256>>>(w3_r + e * E2, wthi + W3R_OFF + e * E2, wtlo + W3R_OFF + e * E2, DIMC, HIDC);
        convt_kernel<<<gNH, 256>>>(w2_r + e * E2, wthi + W2R_OFF + e * E2, wtlo + W2R_OFF + e * E2, HIDC, DIMC);
    }
    convt_kernel<<<gNN, 256>>>(out_w, wthi + OUTW_OFF, wtlo + OUTW_OFF, DIMC, DIMC);

    // shared expert 0 pass2 (pass1 already launched above)
    mm2_kernel<<<g2, 256, P2_SMEM>>>(
        HIDC, wthi + W2S_OFF, wtlo + W2S_OFF, nullptr, nullptr, 0, comb);
    // shared expert 1
    mm1_kernel<<<g1, 256, P1_SMEM>>>(
        wthi + W1S_OFF + E2, wtlo + W1S_OFF + E2,
        wthi + W3S_OFF + E2, wtlo + W3S_OFF + E2,
        nullptr, nullptr, nullptr);
    mm2_kernel<<<g2, 256, P2_SMEM>>>(
        HIDC, wthi + W2S_OFF + E2, wtlo + W2S_OFF + E2, nullptr, nullptr, 1, comb);
    // routed experts
    for (int e = 0; e < 6; e++) {
        mm1_kernel<<<g1, 256, P1_SMEM>>>(
            wthi + W1R_OFF + e * E2, wtlo + W1R_OFF + e * E2,
            wthi + W3R_OFF + e * E2, wtlo + W3R_OFF + e * E2,
            list + e * NTOK, lw + e * NTOK, cnt + e);
        mm2_kernel<<<g2, 256, P2_SMEM>>>(
            HIDC, wthi + W2R_OFF + e * E2, wtlo + W2R_OFF + e * E2,
            list + e * NTOK, cnt + e, 1, comb);
    }
    // out projection
    convc_kernel<<<(NTOK * DIMC) / 256, 256>>>();
    mm2_kernel<<<g2, 256, P2_SMEM>>>(
        DIMC, wthi + OUTW_OFF, wtlo + OUTW_OFF, nullptr, nullptr, 2, out);
}

// round 6
// speedup vs baseline: 2.6076x; 1.0719x over previous
#include <cuda_runtime.h>
#include <cuda_bf16.h>
#include <math.h>
#include <stdint.h>

typedef __nv_bfloat16 bf16;

#define NTOK 8192
#define DIMC 1024
#define HIDC 2048
#define NRE  6

#define W1S_OFF 0ull
#define W3S_OFF (4ull<<20)
#define W2S_OFF (8ull<<20)
#define W1R_OFF (12ull<<20)
#define W3R_OFF (24ull<<20)
#define W2R_OFF (36ull<<20)
#define OUTW_OFF (48ull<<20)
#define WT_TOTAL (49ull<<20)

__device__ bf16 g_wthi[WT_TOTAL];
__device__ bf16 g_wtlo[WT_TOTAL];
__device__ bf16 g_xhi[(size_t)NTOK * DIMC];
__device__ bf16 g_xlo[(size_t)NTOK * DIMC];
__device__ bf16 g_hhi[(size_t)NTOK * HIDC];   // also comb hi
__device__ bf16 g_hlo[(size_t)NTOK * HIDC];   // also comb lo
__device__ float g_comb[(size_t)NTOK * DIMC];
__device__ int   g_list[NRE * NTOK];
__device__ float g_lw[NRE * NTOK];
__device__ int   g_cnt[NRE];
__device__ int   g_top1[NRE];
__device__ float g_psum[NRE];

// ===================== helpers =====================
__device__ __forceinline__ uint32_t s2u(const void* p) {
    return (uint32_t)__cvta_generic_to_shared(p);
}
__device__ __forceinline__ void cpa(uint32_t s, const void* g) {
    asm volatile("cp.async.cg.shared.global [%0], [%1], 16;" :: "r"(s), "l"(g));
}
__device__ __forceinline__ void cpa_commit() {
    asm volatile("cp.async.commit_group;" ::: "memory");
}
__device__ __forceinline__ void ldsm4(uint32_t* r, uint32_t addr) {
    asm volatile("ldmatrix.sync.aligned.m8n8.x4.shared.b16 {%0,%1,%2,%3}, [%4];"
        : "=r"(r[0]), "=r"(r[1]), "=r"(r[2]), "=r"(r[3]) : "r"(addr));
}
__device__ __forceinline__ void mma16816(float* d, const uint32_t* a, const uint32_t* b) {
    asm volatile("mma.sync.aligned.m16n8k16.row.col.f32.bf16.bf16.f32 "
        "{%0,%1,%2,%3}, {%4,%5,%6,%7}, {%8,%9}, {%0,%1,%2,%3};"
        : "+f"(d[0]), "+f"(d[1]), "+f"(d[2]), "+f"(d[3])
        : "r"(a[0]), "r"(a[1]), "r"(a[2]), "r"(a[3]), "r"(b[0]), "r"(b[1]));
}
__device__ __forceinline__ void split2(float a, float b, uint32_t& hi, uint32_t& lo) {
    bf16 ha = __float2bfloat16_rn(a), hb = __float2bfloat16_rn(b);
    bf16 la = __float2bfloat16_rn(a - __bfloat162float(ha));
    bf16 lb = __float2bfloat16_rn(b - __bfloat162float(hb));
    __nv_bfloat162 H, L; H.x = ha; H.y = hb; L.x = la; L.y = lb;
    hi = *(uint32_t*)&H; lo = *(uint32_t*)&L;
}

// ===================== small kernels =====================
__global__ void zero_kernel() {
    int t = threadIdx.x;
    if (t < NRE) { g_cnt[t] = 0; g_top1[t] = 0; g_psum[t] = 0.f; }
}

__global__ void __launch_bounds__(256) gate_kernel(const float* __restrict__ x,
                                                   const float* __restrict__ gw) {
    __shared__ float sgw[DIMC * NRE];
    int tid = threadIdx.x;
    for (int i = tid; i < DIMC * NRE; i += 256) sgw[i] = gw[i];
    __syncthreads();
    int warp = tid >> 5, lane = tid & 31;
    int token = blockIdx.x * 8 + warp;
    if (token >= NTOK) return;
    const float* xr = x + (size_t)token * DIMC;
    float acc[NRE] = {0.f, 0.f, 0.f, 0.f, 0.f, 0.f};
    for (int k = lane; k < DIMC; k += 32) {
        float xv = xr[k];
#pragma unroll
        for (int e = 0; e < NRE; e++) acc[e] += xv * sgw[k * NRE + e];
    }
#pragma unroll
    for (int e = 0; e < NRE; e++)
#pragma unroll
        for (int o = 16; o > 0; o >>= 1)
            acc[e] += __shfl_xor_sync(0xffffffffu, acc[e], o);
    if (lane == 0) {
        int i0 = 0; float v0 = acc[0];
        for (int e = 1; e < NRE; e++) if (acc[e] > v0) { v0 = acc[e]; i0 = e; }
        int i1 = -1; float v1 = -1e30f;
        for (int e = 0; e < NRE; e++) if (e != i0 && acc[e] > v1) { v1 = acc[e]; i1 = e; }
        float e2 = expf(v1 - v0);
        float inv = 1.0f / (1.0f + e2);
        float w0 = inv, w1 = e2 * inv;
        float p[NRE]; float s = 0.f;
        for (int e = 0; e < NRE; e++) { p[e] = expf(acc[e] - v0); s += p[e]; }
        float is = 1.0f / s;
        for (int e = 0; e < NRE; e++) atomicAdd(&g_psum[e], p[e] * is);
        atomicAdd(&g_top1[i0], 1);
        int p0 = atomicAdd(&g_cnt[i0], 1);
        g_list[i0 * NTOK + p0] = token; g_lw[i0 * NTOK + p0] = w0;
        int p1 = atomicAdd(&g_cnt[i1], 1);
        g_list[i1 * NTOK + p1] = token; g_lw[i1 * NTOK + p1] = w1;
    }
}

__global__ void aux_kernel(float* dst) {
    float a = 0.f;
    for (int e = 0; e < NRE; e++) {
        float f = (float)g_top1[e] / (float)NTOK;
        float pm = g_psum[e] / (float)NTOK;
        a += f * pm;
    }
    *dst = 0.01f * (float)NRE * a;
}

__global__ void __launch_bounds__(256) convx_kernel(const float* __restrict__ x) {
    size_t i = (size_t)blockIdx.x * 256 + threadIdx.x;
    float v = x[i];
    bf16 h = __float2bfloat16_rn(v);
    g_xhi[i] = h;
    g_xlo[i] = __float2bfloat16_rn(v - __bfloat162float(h));
}

__global__ void __launch_bounds__(256) convc_kernel() {
    size_t i = (size_t)blockIdx.x * 256 + threadIdx.x;
    float v = g_comb[i];
    bf16 h = __float2bfloat16_rn(v);
    g_hhi[i] = h;
    g_hlo[i] = __float2bfloat16_rn(v - __bfloat162float(h));
}

// W [K][N] fp32 -> [N][K] bf16 hi/lo
__global__ void __launch_bounds__(256) convt_kernel(const float* __restrict__ in,
                                                    bf16* __restrict__ ohi,
                                                    bf16* __restrict__ olo,
                                                    int K, int N) {
    __shared__ float t[32][33];
    int k0 = blockIdx.y * 32, n0 = blockIdx.x * 32;
    int tx = threadIdx.x & 31, ty = threadIdx.x >> 5;
#pragma unroll
    for (int i = 0; i < 4; i++)
        t[ty + i * 8][tx] = in[(size_t)(k0 + ty + i * 8) * N + n0 + tx];
    __syncthreads();
#pragma unroll
    for (int i = 0; i < 4; i++) {
        float v = t[tx][ty + i * 8];
        bf16 h = __float2bfloat16_rn(v);
        size_t o = (size_t)(n0 + ty + i * 8) * K + k0 + tx;
        ohi[o] = h;
        olo[o] = __float2bfloat16_rn(v - __bfloat162float(h));
    }
}

// ===================== mm1: h = silu(x@W1)*(x@W3)*scale =====================
// tile 128M x 128N, chunk K=64, warps 2(M)x4(N), warp tile 64x32, pitch 144B
#define P1_PITCH 144
#define P1_MAT   18432                 // 128 rows * 144B
#define P1_AH 0
#define P1_AL (P1_MAT)
#define P1_B1H (2*P1_MAT)
#define P1_B1L (3*P1_MAT)
#define P1_B3H (4*P1_MAT)
#define P1_B3L (5*P1_MAT)
#define P1_STG (6*P1_MAT)              // 110592
#define P1_SIDX (2*P1_STG)             // 221184
#define P1_SMEM (P1_SIDX + 512)        // 221696

__global__ void __launch_bounds__(256, 1) mm1_kernel(
    const bf16* __restrict__ W1hi, const bf16* __restrict__ W1lo,
    const bf16* __restrict__ W3hi, const bf16* __restrict__ W3lo,
    const int* __restrict__ gidx, const float* __restrict__ gscale,
    const int* __restrict__ cntPtr)
{
    extern __shared__ char smem[];
    const int M = cntPtr ? *cntPtr : NTOK;
    const int mBase = blockIdx.y * 128;
    if (mBase >= M) return;
    const int nBase = blockIdx.x * 128;
    const uint32_t sb = s2u(smem);
    const int tid = threadIdx.x;

    int* sIdx = (int*)(smem + P1_SIDX);
    if (tid < 128) {
        int r = mBase + tid;
        sIdx[tid] = (r < M) ? (gidx ? gidx[r] : r) : 0;
    }
    __syncthreads();

    auto load = [&](int buf, int k0) {
        uint32_t su = sb + buf * P1_STG;
#pragma unroll
        for (int it = 0; it < 4; it++) {
            int idx = tid + it * 256;
            int row = idx >> 3, seg = idx & 7;
            uint32_t so = row * P1_PITCH + seg * 16;
            size_t g = (size_t)sIdx[row] * DIMC + k0 + seg * 8;
            cpa(su + P1_AH + so, g_xhi + g);
            cpa(su + P1_AL + so, g_xlo + g);
        }
#pragma unroll
        for (int it = 0; it < 4; it++) {
            int idx = tid + it * 256;
            int row = idx >> 3, seg = idx & 7;
            uint32_t so = row * P1_PITCH + seg * 16;
            size_t g = (size_t)(nBase + row) * DIMC + k0 + seg * 8;
            cpa(su + P1_B1H + so, W1hi + g);
            cpa(su + P1_B1L + so, W1lo + g);
            cpa(su + P1_B3H + so, W3hi + g);
            cpa(su + P1_B3L + so, W3lo + g);
        }
        cpa_commit();
    };

    const int lane = tid & 31, wid = tid >> 5;
    const int wm = (wid & 1) * 64;
    const int wn = (wid >> 1) * 32;
    const int arow = (lane & 7) + ((lane >> 3) & 1) * 8;
    const int akh  = (lane >> 4) & 1;
    const int brow = (lane & 7) + ((lane >> 4) & 1) * 8;
    const int bkh  = (lane >> 3) & 1;

    float acc1[4][4][4], acc3[4][4][4];
#pragma unroll
    for (int i = 0; i < 4; i++)
#pragma unroll
        for (int j = 0; j < 4; j++)
#pragma unroll
            for (int k = 0; k < 4; k++) { acc1[i][j][k] = 0.f; acc3[i][j][k] = 0.f; }

    load(0, 0);
    const int nc = DIMC / 64;   // 16
    for (int c = 0; c < nc; c++) {
        if (c + 1 < nc) {
            load((c + 1) & 1, (c + 1) * 64);
            asm volatile("cp.async.wait_group 1;" ::: "memory");
        } else {
            asm volatile("cp.async.wait_group 0;" ::: "memory");
        }
        __syncthreads();
        uint32_t su = sb + (c & 1) * P1_STG;
#pragma unroll
        for (int s = 0; s < 4; s++) {
            uint32_t ah[4][4], al[4][4];
#pragma unroll
            for (int mi = 0; mi < 4; mi++) {
                uint32_t ao = (uint32_t)(wm + mi * 16 + arow) * P1_PITCH + s * 32 + akh * 16;
                ldsm4(ah[mi], su + P1_AH + ao);
                ldsm4(al[mi], su + P1_AL + ao);
            }
#pragma unroll
            for (int np = 0; np < 2; np++) {
                uint32_t b1h[4], b1l[4], b3h[4], b3l[4];
                uint32_t bo = (uint32_t)(wn + np * 16 + brow) * P1_PITCH + s * 32 + bkh * 16;
                ldsm4(b1h, su + P1_B1H + bo);
                ldsm4(b1l, su + P1_B1L + bo);
                ldsm4(b3h, su + P1_B3H + bo);
                ldsm4(b3l, su + P1_B3L + bo);
#pragma unroll
                for (int mi = 0; mi < 4; mi++)
#pragma unroll
                    for (int h = 0; h < 2; h++) {
                        int nt = np * 2 + h;
                        mma16816(acc1[mi][nt], ah[mi], &b1h[h * 2]);
                        mma16816(acc1[mi][nt], ah[mi], &b1l[h * 2]);
                        mma16816(acc1[mi][nt], al[mi], &b1h[h * 2]);
                        mma16816(acc3[mi][nt], ah[mi], &b3h[h * 2]);
                        mma16816(acc3[mi][nt], ah[mi], &b3l[h * 2]);
                        mma16816(acc3[mi][nt], al[mi], &b3h[h * 2]);
                    }
            }
        }
        __syncthreads();
    }

#pragma unroll
    for (int mi = 0; mi < 4; mi++)
#pragma unroll
        for (int half = 0; half < 2; half++) {
            int slot = mBase + wm + mi * 16 + (lane >> 2) + half * 8;
            if (slot < M) {
                float sc = gscale ? gscale[slot] : 1.0f;
                size_t rb = (size_t)slot * HIDC + nBase + wn + (lane & 3) * 2;
#pragma unroll
                for (int nt = 0; nt < 4; nt++) {
                    float u0 = acc1[mi][nt][half * 2 + 0];
                    float u1 = acc1[mi][nt][half * 2 + 1];
                    float v0 = acc3[mi][nt][half * 2 + 0];
                    float v1 = acc3[mi][nt][half * 2 + 1];
                    float h0 = u0 / (1.f + __expf(-u0)) * v0 * sc;
                    float h1 = u1 / (1.f + __expf(-u1)) * v1 * sc;
                    uint32_t ph, pl; split2(h0, h1, ph, pl);
                    *(uint32_t*)(g_hhi + rb + nt * 8) = ph;
                    *(uint32_t*)(g_hlo + rb + nt * 8) = pl;
                }
            }
        }
}

// ===================== mm2: C[crow,:] op= h @ W  (tile 128x128, chunk 64) =====================
#define P2_AH 0
#define P2_AL 18432
#define P2_BH 36864
#define P2_BL 55296
#define P2_STG 73728
#define P2_SMEM 147968

__global__ void __launch_bounds__(256, 1) mm2_kernel(
    int K,
    const bf16* __restrict__ Bhi, const bf16* __restrict__ Blo,
    const int* __restrict__ gidx, const int* __restrict__ cntPtr,
    int mode, float* __restrict__ cout)
{
    extern __shared__ char smem[];
    const int M = cntPtr ? *cntPtr : NTOK;
    const int mBase = blockIdx.y * 128;
    if (mBase >= M) return;
    const int nBase = blockIdx.x * 128;
    const uint32_t sb = s2u(smem);
    const int tid = threadIdx.x;

    auto load = [&](int buf, int k0) {
        uint32_t su = sb + buf * P2_STG;
#pragma unroll
        for (int it = 0; it < 4; it++) {
            int idx = tid + it * 256;
            int row = idx >> 3, seg = idx & 7;
            uint32_t so = row * 144 + seg * 16;
            int ar = mBase + row; if (ar >= M) ar = mBase;
            size_t g = (size_t)ar * K + k0 + seg * 8;
            cpa(su + P2_AH + so, g_hhi + g);
            cpa(su + P2_AL + so, g_hlo + g);
        }
#pragma unroll
        for (int it = 0; it < 4; it++) {
            int idx = tid + it * 256;
            int row = idx >> 3, seg = idx & 7;
            uint32_t so = row * 144 + seg * 16;
            size_t g = (size_t)(nBase + row) * K + k0 + seg * 8;
            cpa(su + P2_BH + so, Bhi + g);
            cpa(su + P2_BL + so, Blo + g);
        }
        cpa_commit();
    };

    const int lane = tid & 31, wid = tid >> 5;
    const int wm = (wid & 1) * 64;
    const int wn = (wid >> 1) * 32;
    const int arow = (lane & 7) + ((lane >> 3) & 1) * 8;
    const int akh  = (lane >> 4) & 1;
    const int brow = (lane & 7) + ((lane >> 4) & 1) * 8;
    const int bkh  = (lane >> 3) & 1;

    float acc[4][4][4];
#pragma unroll
    for (int i = 0; i < 4; i++)
#pragma unroll
        for (int j = 0; j < 4; j++)
#pragma unroll
            for (int k = 0; k < 4; k++) acc[i][j][k] = 0.f;

    load(0, 0);
    const int nc = K / 64;
    for (int c = 0; c < nc; c++) {
        if (c + 1 < nc) {
            load((c + 1) & 1, (c + 1) * 64);
            asm volatile("cp.async.wait_group 1;" ::: "memory");
        } else {
            asm volatile("cp.async.wait_group 0;" ::: "memory");
        }
        __syncthreads();
        uint32_t su = sb + (c & 1) * P2_STG;
#pragma unroll
        for (int s = 0; s < 4; s++) {
            uint32_t ah[4][4], al[4][4];
#pragma unroll
            for (int mi = 0; mi < 4; mi++) {
                uint32_t ao = (uint32_t)(wm + mi * 16 + arow) * 144 + s * 32 + akh * 16;
                ldsm4(ah[mi], su + P2_AH + ao);
                ldsm4(al[mi], su + P2_AL + ao);
            }
#pragma unroll
            for (int np = 0; np < 2; np++) {
                uint32_t bh[4], bl[4];
                uint32_t bo = (uint32_t)(wn + np * 16 + brow) * 144 + s * 32 + bkh * 16;
                ldsm4(bh, su + P2_BH + bo);
                ldsm4(bl, su + P2_BL + bo);
#pragma unroll
                for (int mi = 0; mi < 4; mi++)
#pragma unroll
                    for (int h = 0; h < 2; h++) {
                        int nt = np * 2 + h;
                        mma16816(acc[mi][nt], ah[mi], &bh[h * 2]);
                        mma16816(acc[mi][nt], ah[mi], &bl[h * 2]);
                        mma16816(acc[mi][nt], al[mi], &bh[h * 2]);
                    }
            }
        }
        __syncthreads();
    }

#pragma unroll
    for (int mi = 0; mi < 4; mi++)
#pragma unroll
        for (int half = 0; half < 2; half++) {
            int slot = mBase + wm + mi * 16 + (lane >> 2) + half * 8;
            if (slot < M) {
                int crow = (mode == 1 && gidx) ? gidx[slot] : slot;
                float* cp = cout + (size_t)crow * DIMC + nBase + wn + (lane & 3) * 2;
#pragma unroll
                for (int nt = 0; nt < 4; nt++) {
                    float2 v = make_float2(acc[mi][nt][half * 2 + 0],
                                           acc[mi][nt][half * 2 + 1]);
                    if (mode == 1) {
                        float2 o = *(float2*)(cp + nt * 8);
                        v.x += o.x; v.y += o.y;
                    }
                    *(float2*)(cp + nt * 8) = v;
                }
            }
        }
}

// ===================== host =====================
extern "C" void kernel_launch(void* const* d_in, const int* in_sizes, int n_in,
                              void* d_out, int out_size)
{
    const float* x      = (const float*)d_in[0];
    const float* w1_s   = (const float*)d_in[1];
    const float* w2_s   = (const float*)d_in[2];
    const float* w3_s   = (const float*)d_in[3];
    const float* w1_r   = (const float*)d_in[4];
    const float* w2_r   = (const float*)d_in[5];
    const float* w3_r   = (const float*)d_in[6];
    const float* gate_w = (const float*)d_in[7];
    const float* out_w  = (const float*)d_in[8];
    float* out = (float*)d_out;

    bf16 *wthi, *wtlo;
    int *list, *cnt; float *lw, *comb;
    cudaGetSymbolAddress((void**)&wthi, g_wthi);
    cudaGetSymbolAddress((void**)&wtlo, g_wtlo);
    cudaGetSymbolAddress((void**)&list, g_list);
    cudaGetSymbolAddress((void**)&lw, g_lw);
    cudaGetSymbolAddress((void**)&cnt, g_cnt);
    cudaGetSymbolAddress((void**)&comb, g_comb);

    cudaFuncSetAttribute(mm1_kernel, cudaFuncAttributeMaxDynamicSharedMemorySize, P1_SMEM);
    cudaFuncSetAttribute(mm2_kernel, cudaFuncAttributeMaxDynamicSharedMemorySize, P2_SMEM);

    const size_t E2 = 2ull << 20;
    dim3 gHN(HIDC / 32, DIMC / 32);
    dim3 gNH(DIMC / 32, HIDC / 32);
    dim3 gNN(DIMC / 32, DIMC / 32);
    dim3 g1(HIDC / 128, NTOK / 128);  // (16, 64)
    dim3 g2(DIMC / 128, NTOK / 128);  // (8, 64)

    // launches 1-3 are prereqs; #4 = mm1 (ncu captures 4th launch)
    convx_kernel<<<(NTOK * DIMC) / 256, 256>>>(x);                                     // 1
    convt_kernel<<<gHN, 256>>>(w1_s, wthi + W1S_OFF, wtlo + W1S_OFF, DIMC, HIDC);      // 2
    convt_kernel<<<gHN, 256>>>(w3_s, wthi + W3S_OFF, wtlo + W3S_OFF, DIMC, HIDC);      // 3
    mm1_kernel<<<g1, 256, P1_SMEM>>>(                                                  // 4 (profiled)
        wthi + W1S_OFF, wtlo + W1S_OFF, wthi + W3S_OFF, wtlo + W3S_OFF,
        nullptr, nullptr, nullptr);

    zero_kernel<<<1, 32>>>();
    gate_kernel<<<NTOK / 8, 256>>>(x, gate_w);
    if (out_size > NTOK * DIMC)
        aux_kernel<<<1, 1>>>(out + (out_size - 1));

    // remaining conversions
    convt_kernel<<<gHN, 256>>>(w1_s + E2, wthi + W1S_OFF + E2, wtlo + W1S_OFF + E2, DIMC, HIDC);
    convt_kernel<<<gHN, 256>>>(w3_s + E2, wthi + W3S_OFF + E2, wtlo + W3S_OFF + E2, DIMC, HIDC);
    for (int e = 0; e < 2; e++)
        convt_kernel<<<gNH, 256>>>(w2_s + e * E2, wthi + W2S_OFF + e * E2, wtlo + W2S_OFF + e * E2, HIDC, DIMC);
    for (int e = 0; e < 6; e++) {
        convt_kernel<<<gHN, 256>>>(w1_r + e * E2, wthi + W1R_OFF + e * E2, wtlo + W1R_OFF + e * E2, DIMC, HIDC);
        convt_kernel<<<gHN, 256>>>(w3_r + e * E2, wthi + W3R_OFF + e * E2, wtlo + W3R_OFF + e * E2, DIMC, HIDC);
        convt_kernel<<<gNH, 256>>>(w2_r + e * E2, wthi + W2R_OFF + e * E2, wtlo + W2R_OFF + e * E2, HIDC, DIMC);
    }
    convt_kernel<<<gNN, 256>>>(out_w, wthi + OUTW_OFF, wtlo + OUTW_OFF, DIMC, DIMC);

    // shared expert 0 pass2 (pass1 launched above)
    mm2_kernel<<<g2, 256, P2_SMEM>>>(
        HIDC, wthi + W2S_OFF, wtlo + W2S_OFF, nullptr, nullptr, 0, comb);
    // shared expert 1
    mm1_kernel<<<g1, 256, P1_SMEM>>>(
        wthi + W1S_OFF + E2, wtlo + W1S_OFF + E2,
        wthi + W3S_OFF + E2, wtlo + W3S_OFF + E2,
        nullptr, nullptr, nullptr);
    mm2_kernel<<<g2, 256, P2_SMEM>>>(
        HIDC, wthi + W2S_OFF + E2, wtlo + W2S_OFF + E2, nullptr, nullptr, 1, comb);
    // routed experts
    for (int e = 0; e < 6; e++) {
        mm1_kernel<<<g1, 256, P1_SMEM>>>(
            wthi + W1R_OFF + e * E2, wtlo + W1R_OFF + e * E2,
            wthi + W3R_OFF + e * E2, wtlo + W3R_OFF + e * E2,
            list + e * NTOK, lw + e * NTOK, cnt + e);
        mm2_kernel<<<g2, 256, P2_SMEM>>>(
            HIDC, wthi + W2R_OFF + e * E2, wtlo + W2R_OFF + e * E2,
            list + e * NTOK, cnt + e, 1, comb);
    }
    // out projection
    convc_kernel<<<(NTOK * DIMC) / 256, 256>>>();
    mm2_kernel<<<g2, 256, P2_SMEM>>>(
        DIMC, wthi + OUTW_OFF, wtlo + OUTW_OFF, nullptr, nullptr, 2, out);
}

// round 7
// speedup vs baseline: 3.6065x; 1.3831x over previous
#include <cuda_runtime.h>
#include <cuda_fp16.h>
#include <cuda_bf16.h>
#include <math.h>
#include <stdint.h>

typedef __half fp16;

#define NTOK 8192
#define DIMC 1024
#define HIDC 2048
#define NRE  6

#define W1S_OFF 0ull
#define W3S_OFF (4ull<<20)
#define W2S_OFF (8ull<<20)
#define W1R_OFF (12ull<<20)
#define W3R_OFF (24ull<<20)
#define W2R_OFF (36ull<<20)
#define OUTW_OFF (48ull<<20)
#define WT_TOTAL (49ull<<20)

__device__ fp16 g_wt[WT_TOTAL];                 // weights, single fp16, [N][K]
__device__ fp16 g_xhi[(size_t)NTOK * DIMC];
__device__ fp16 g_xlo[(size_t)NTOK * DIMC];
__device__ fp16 g_hhi[(size_t)NTOK * HIDC];     // also comb hi
__device__ fp16 g_hlo[(size_t)NTOK * HIDC];     // also comb lo
__device__ float g_comb[(size_t)NTOK * DIMC];
__device__ int   g_list[NRE * NTOK];
__device__ float g_lw[NRE * NTOK];
__device__ int   g_cnt[NRE];
__device__ int   g_top1[NRE];
__device__ float g_psum[NRE];

// ===================== helpers =====================
__device__ __forceinline__ uint32_t s2u(const void* p) {
    return (uint32_t)__cvta_generic_to_shared(p);
}
__device__ __forceinline__ void cpa(uint32_t s, const void* g) {
    asm volatile("cp.async.cg.shared.global [%0], [%1], 16;" :: "r"(s), "l"(g));
}
__device__ __forceinline__ void cpa_commit() {
    asm volatile("cp.async.commit_group;" ::: "memory");
}
__device__ __forceinline__ void ldsm4(uint32_t* r, uint32_t addr) {
    asm volatile("ldmatrix.sync.aligned.m8n8.x4.shared.b16 {%0,%1,%2,%3}, [%4];"
        : "=r"(r[0]), "=r"(r[1]), "=r"(r[2]), "=r"(r[3]) : "r"(addr));
}
__device__ __forceinline__ void mma16816(float* d, const uint32_t* a, const uint32_t* b) {
    asm volatile("mma.sync.aligned.m16n8k16.row.col.f32.f16.f16.f32 "
        "{%0,%1,%2,%3}, {%4,%5,%6,%7}, {%8,%9}, {%0,%1,%2,%3};"
        : "+f"(d[0]), "+f"(d[1]), "+f"(d[2]), "+f"(d[3])
        : "r"(a[0]), "r"(a[1]), "r"(a[2]), "r"(a[3]), "r"(b[0]), "r"(b[1]));
}
__device__ __forceinline__ void split2h(float a, float b, uint32_t& hi, uint32_t& lo) {
    fp16 ha = __float2half_rn(a), hb = __float2half_rn(b);
    fp16 la = __float2half_rn(a - __half2float(ha));
    fp16 lb = __float2half_rn(b - __half2float(hb));
    __half2 H, L; H.x = ha; H.y = hb; L.x = la; L.y = lb;
    hi = *(uint32_t*)&H; lo = *(uint32_t*)&L;
}

// ===================== small kernels =====================
__global__ void zero_kernel() {
    int t = threadIdx.x;
    if (t < NRE) { g_cnt[t] = 0; g_top1[t] = 0; g_psum[t] = 0.f; }
}

__global__ void __launch_bounds__(256) gate_kernel(const float* __restrict__ x,
                                                   const float* __restrict__ gw) {
    __shared__ float sgw[DIMC * NRE];
    int tid = threadIdx.x;
    for (int i = tid; i < DIMC * NRE; i += 256) sgw[i] = gw[i];
    __syncthreads();
    int warp = tid >> 5, lane = tid & 31;
    int token = blockIdx.x * 8 + warp;
    if (token >= NTOK) return;
    const float* xr = x + (size_t)token * DIMC;
    float acc[NRE] = {0.f, 0.f, 0.f, 0.f, 0.f, 0.f};
    for (int k = lane; k < DIMC; k += 32) {
        float xv = xr[k];
#pragma unroll
        for (int e = 0; e < NRE; e++) acc[e] += xv * sgw[k * NRE + e];
    }
#pragma unroll
    for (int e = 0; e < NRE; e++)
#pragma unroll
        for (int o = 16; o > 0; o >>= 1)
            acc[e] += __shfl_xor_sync(0xffffffffu, acc[e], o);
    if (lane == 0) {
        int i0 = 0; float v0 = acc[0];
        for (int e = 1; e < NRE; e++) if (acc[e] > v0) { v0 = acc[e]; i0 = e; }
        int i1 = -1; float v1 = -1e30f;
        for (int e = 0; e < NRE; e++) if (e != i0 && acc[e] > v1) { v1 = acc[e]; i1 = e; }
        float e2 = expf(v1 - v0);
        float inv = 1.0f / (1.0f + e2);
        float w0 = inv, w1 = e2 * inv;
        float p[NRE]; float s = 0.f;
        for (int e = 0; e < NRE; e++) { p[e] = expf(acc[e] - v0); s += p[e]; }
        float is = 1.0f / s;
        for (int e = 0; e < NRE; e++) atomicAdd(&g_psum[e], p[e] * is);
        atomicAdd(&g_top1[i0], 1);
        int p0 = atomicAdd(&g_cnt[i0], 1);
        g_list[i0 * NTOK + p0] = token; g_lw[i0 * NTOK + p0] = w0;
        int p1 = atomicAdd(&g_cnt[i1], 1);
        g_list[i1 * NTOK + p1] = token; g_lw[i1 * NTOK + p1] = w1;
    }
}

__global__ void aux_kernel(float* dst) {
    float a = 0.f;
    for (int e = 0; e < NRE; e++) {
        float f = (float)g_top1[e] / (float)NTOK;
        float pm = g_psum[e] / (float)NTOK;
        a += f * pm;
    }
    *dst = 0.01f * (float)NRE * a;
}

__global__ void __launch_bounds__(256) convx_kernel(const float* __restrict__ x) {
    size_t i = (size_t)blockIdx.x * 256 + threadIdx.x;
    float v = x[i];
    fp16 h = __float2half_rn(v);
    g_xhi[i] = h;
    g_xlo[i] = __float2half_rn(v - __half2float(h));
}

__global__ void __launch_bounds__(256) convc_kernel() {
    size_t i = (size_t)blockIdx.x * 256 + threadIdx.x;
    float v = g_comb[i];
    fp16 h = __float2half_rn(v);
    g_hhi[i] = h;
    g_hlo[i] = __float2half_rn(v - __half2float(h));
}

// W [K][N] fp32 -> [N][K] fp16
__global__ void __launch_bounds__(256) convt_kernel(const float* __restrict__ in,
                                                    fp16* __restrict__ o,
                                                    int K, int N) {
    __shared__ float t[32][33];
    int k0 = blockIdx.y * 32, n0 = blockIdx.x * 32;
    int tx = threadIdx.x & 31, ty = threadIdx.x >> 5;
#pragma unroll
    for (int i = 0; i < 4; i++)
        t[ty + i * 8][tx] = in[(size_t)(k0 + ty + i * 8) * N + n0 + tx];
    __syncthreads();
#pragma unroll
    for (int i = 0; i < 4; i++)
        o[(size_t)(n0 + ty + i * 8) * K + k0 + tx] = __float2half_rn(t[tx][ty + i * 8]);
}

// ===================== mm1: h = silu(x@W1)*(x@W3)*scale =====================
// 128M x 128N, chunk K=64, 3-stage cp.async, warps 2(M)x4(N), pitch 144B
#define P1_PITCH 144
#define P1_MAT   18432
#define P1_AH 0
#define P1_AL (P1_MAT)
#define P1_B1 (2*P1_MAT)
#define P1_B3 (3*P1_MAT)
#define P1_STG (4*P1_MAT)              // 73728
#define P1_SIDX (3*P1_STG)             // 221184
#define P1_SMEM (P1_SIDX + 512)        // 221696

__global__ void __launch_bounds__(256, 1) mm1_kernel(
    const fp16* __restrict__ W1, const fp16* __restrict__ W3,
    const int* __restrict__ gidx, const float* __restrict__ gscale,
    const int* __restrict__ cntPtr)
{
    extern __shared__ char smem[];
    const int M = cntPtr ? *cntPtr : NTOK;
    const int mBase = blockIdx.y * 128;
    if (mBase >= M) return;
    const int nBase = blockIdx.x * 128;
    const uint32_t sb = s2u(smem);
    const int tid = threadIdx.x;

    int* sIdx = (int*)(smem + P1_SIDX);
    if (tid < 128) {
        int r = mBase + tid;
        sIdx[tid] = (r < M) ? (gidx ? gidx[r] : r) : 0;
    }
    __syncthreads();

    auto load = [&](int buf, int k0) {
        uint32_t su = sb + buf * P1_STG;
#pragma unroll
        for (int it = 0; it < 4; it++) {
            int idx = tid + it * 256;
            int row = idx >> 3, seg = idx & 7;
            uint32_t so = row * P1_PITCH + seg * 16;
            size_t g = (size_t)sIdx[row] * DIMC + k0 + seg * 8;
            cpa(su + P1_AH + so, g_xhi + g);
            cpa(su + P1_AL + so, g_xlo + g);
        }
#pragma unroll
        for (int it = 0; it < 4; it++) {
            int idx = tid + it * 256;
            int row = idx >> 3, seg = idx & 7;
            uint32_t so = row * P1_PITCH + seg * 16;
            size_t g = (size_t)(nBase + row) * DIMC + k0 + seg * 8;
            cpa(su + P1_B1 + so, W1 + g);
            cpa(su + P1_B3 + so, W3 + g);
        }
        cpa_commit();
    };

    const int lane = tid & 31, wid = tid >> 5;
    const int wm = (wid & 1) * 64;
    const int wn = (wid >> 1) * 32;
    const int arow = (lane & 7) + ((lane >> 3) & 1) * 8;
    const int akh  = (lane >> 4) & 1;
    const int brow = (lane & 7) + ((lane >> 4) & 1) * 8;
    const int bkh  = (lane >> 3) & 1;

    float acc1[4][4][4], acc3[4][4][4];
#pragma unroll
    for (int i = 0; i < 4; i++)
#pragma unroll
        for (int j = 0; j < 4; j++)
#pragma unroll
            for (int k = 0; k < 4; k++) { acc1[i][j][k] = 0.f; acc3[i][j][k] = 0.f; }

    const int nc = DIMC / 64;   // 16
    load(0, 0);
    load(1, 64);
    for (int c = 0; c < nc; c++) {
        if (c + 1 < nc) asm volatile("cp.async.wait_group 1;" ::: "memory");
        else            asm volatile("cp.async.wait_group 0;" ::: "memory");
        __syncthreads();
        if (c + 2 < nc) load((c + 2) % 3, (c + 2) * 64);
        uint32_t su = sb + (c % 3) * P1_STG;
#pragma unroll
        for (int s = 0; s < 4; s++) {
            uint32_t ah[4][4], al[4][4];
#pragma unroll
            for (int mi = 0; mi < 4; mi++) {
                uint32_t ao = (uint32_t)(wm + mi * 16 + arow) * P1_PITCH + s * 32 + akh * 16;
                ldsm4(ah[mi], su + P1_AH + ao);
                ldsm4(al[mi], su + P1_AL + ao);
            }
#pragma unroll
            for (int np = 0; np < 2; np++) {
                uint32_t b1[4], b3[4];
                uint32_t bo = (uint32_t)(wn + np * 16 + brow) * P1_PITCH + s * 32 + bkh * 16;
                ldsm4(b1, su + P1_B1 + bo);
                ldsm4(b3, su + P1_B3 + bo);
#pragma unroll
                for (int mi = 0; mi < 4; mi++)
#pragma unroll
                    for (int h = 0; h < 2; h++) {
                        int nt = np * 2 + h;
                        mma16816(acc1[mi][nt], ah[mi], &b1[h * 2]);
                        mma16816(acc1[mi][nt], al[mi], &b1[h * 2]);
                        mma16816(acc3[mi][nt], ah[mi], &b3[h * 2]);
                        mma16816(acc3[mi][nt], al[mi], &b3[h * 2]);
                    }
            }
        }
    }

#pragma unroll
    for (int mi = 0; mi < 4; mi++)
#pragma unroll
        for (int half = 0; half < 2; half++) {
            int slot = mBase + wm + mi * 16 + (lane >> 2) + half * 8;
            if (slot < M) {
                float sc = gscale ? gscale[slot] : 1.0f;
                size_t rb = (size_t)slot * HIDC + nBase + wn + (lane & 3) * 2;
#pragma unroll
                for (int nt = 0; nt < 4; nt++) {
                    float u0 = acc1[mi][nt][half * 2 + 0];
                    float u1 = acc1[mi][nt][half * 2 + 1];
                    float v0 = acc3[mi][nt][half * 2 + 0];
                    float v1 = acc3[mi][nt][half * 2 + 1];
                    float h0 = u0 / (1.f + __expf(-u0)) * v0 * sc;
                    float h1 = u1 / (1.f + __expf(-u1)) * v1 * sc;
                    uint32_t ph, pl; split2h(h0, h1, ph, pl);
                    *(uint32_t*)(g_hhi + rb + nt * 8) = ph;
                    *(uint32_t*)(g_hlo + rb + nt * 8) = pl;
                }
            }
        }
}

// ===================== mm2: C[crow,:] op= h @ W  (128x128, chunk 64, 3-stage) =====================
#define P2_AH 0
#define P2_AL 18432
#define P2_B  36864
#define P2_STG 55296
#define P2_SMEM (3*P2_STG)   // 165888

__global__ void __launch_bounds__(256, 1) mm2_kernel(
    int K,
    const fp16* __restrict__ B,
    const int* __restrict__ gidx, const int* __restrict__ cntPtr,
    int mode, float* __restrict__ cout)
{
    extern __shared__ char smem[];
    const int M = cntPtr ? *cntPtr : NTOK;
    const int mBase = blockIdx.y * 128;
    if (mBase >= M) return;
    const int nBase = blockIdx.x * 128;
    const uint32_t sb = s2u(smem);
    const int tid = threadIdx.x;

    auto load = [&](int buf, int k0) {
        uint32_t su = sb + buf * P2_STG;
#pragma unroll
        for (int it = 0; it < 4; it++) {
            int idx = tid + it * 256;
            int row = idx >> 3, seg = idx & 7;
            uint32_t so = row * 144 + seg * 16;
            int ar = mBase + row; if (ar >= M) ar = mBase;
            size_t g = (size_t)ar * K + k0 + seg * 8;
            cpa(su + P2_AH + so, g_hhi + g);
            cpa(su + P2_AL + so, g_hlo + g);
        }
#pragma unroll
        for (int it = 0; it < 4; it++) {
            int idx = tid + it * 256;
            int row = idx >> 3, seg = idx & 7;
            uint32_t so = row * 144 + seg * 16;
            size_t g = (size_t)(nBase + row) * K + k0 + seg * 8;
            cpa(su + P2_B + so, B + g);
        }
        cpa_commit();
    };

    const int lane = tid & 31, wid = tid >> 5;
    const int wm = (wid & 1) * 64;
    const int wn = (wid >> 1) * 32;
    const int arow = (lane & 7) + ((lane >> 3) & 1) * 8;
    const int akh  = (lane >> 4) & 1;
    const int brow = (lane & 7) + ((lane >> 4) & 1) * 8;
    const int bkh  = (lane >> 3) & 1;

    float acc[4][4][4];
#pragma unroll
    for (int i = 0; i < 4; i++)
#pragma unroll
        for (int j = 0; j < 4; j++)
#pragma unroll
            for (int k = 0; k < 4; k++) acc[i][j][k] = 0.f;

    const int nc = K / 64;
    load(0, 0);
    load(1, 64);
    for (int c = 0; c < nc; c++) {
        if (c + 1 < nc) asm volatile("cp.async.wait_group 1;" ::: "memory");
        else            asm volatile("cp.async.wait_group 0;" ::: "memory");
        __syncthreads();
        if (c + 2 < nc) load((c + 2) % 3, (c + 2) * 64);
        uint32_t su = sb + (c % 3) * P2_STG;
#pragma unroll
        for (int s = 0; s < 4; s++) {
            uint32_t ah[4][4], al[4][4];
#pragma unroll
            for (int mi = 0; mi < 4; mi++) {
                uint32_t ao = (uint32_t)(wm + mi * 16 + arow) * 144 + s * 32 + akh * 16;
                ldsm4(ah[mi], su + P2_AH + ao);
                ldsm4(al[mi], su + P2_AL + ao);
            }
#pragma unroll
            for (int np = 0; np < 2; np++) {
                uint32_t b[4];
                uint32_t bo = (uint32_t)(wn + np * 16 + brow) * 144 + s * 32 + bkh * 16;
                ldsm4(b, su + P2_B + bo);
#pragma unroll
                for (int mi = 0; mi < 4; mi++)
#pragma unroll
                    for (int h = 0; h < 2; h++) {
                        int nt = np * 2 + h;
                        mma16816(acc[mi][nt], ah[mi], &b[h * 2]);
                        mma16816(acc[mi][nt], al[mi], &b[h * 2]);
                    }
            }
        }
    }

#pragma unroll
    for (int mi = 0; mi < 4; mi++)
#pragma unroll
        for (int half = 0; half < 2; half++) {
            int slot = mBase + wm + mi * 16 + (lane >> 2) + half * 8;
            if (slot < M) {
                int crow = (mode == 1 && gidx) ? gidx[slot] : slot;
                float* cp = cout + (size_t)crow * DIMC + nBase + wn + (lane & 3) * 2;
#pragma unroll
                for (int nt = 0; nt < 4; nt++) {
                    float2 v = make_float2(acc[mi][nt][half * 2 + 0],
                                           acc[mi][nt][half * 2 + 1]);
                    if (mode == 1) {
                        float2 o = *(float2*)(cp + nt * 8);
                        v.x += o.x; v.y += o.y;
                    }
                    *(float2*)(cp + nt * 8) = v;
                }
            }
        }
}

// ===================== host =====================
extern "C" void kernel_launch(void* const* d_in, const int* in_sizes, int n_in,
                              void* d_out, int out_size)
{
    const float* x      = (const float*)d_in[0];
    const float* w1_s   = (const float*)d_in[1];
    const float* w2_s   = (const float*)d_in[2];
    const float* w3_s   = (const float*)d_in[3];
    const float* w1_r   = (const float*)d_in[4];
    const float* w2_r   = (const float*)d_in[5];
    const float* w3_r   = (const float*)d_in[6];
    const float* gate_w = (const float*)d_in[7];
    const float* out_w  = (const float*)d_in[8];
    float* out = (float*)d_out;

    fp16 *wt;
    int *list, *cnt; float *lw, *comb;
    cudaGetSymbolAddress((void**)&wt, g_wt);
    cudaGetSymbolAddress((void**)&list, g_list);
    cudaGetSymbolAddress((void**)&lw, g_lw);
    cudaGetSymbolAddress((void**)&cnt, g_cnt);
    cudaGetSymbolAddress((void**)&comb, g_comb);

    cudaFuncSetAttribute(mm1_kernel, cudaFuncAttributeMaxDynamicSharedMemorySize, P1_SMEM);
    cudaFuncSetAttribute(mm2_kernel, cudaFuncAttributeMaxDynamicSharedMemorySize, P2_SMEM);

    const size_t E2 = 2ull << 20;
    dim3 gHN(HIDC / 32, DIMC / 32);
    dim3 gNH(DIMC / 32, HIDC / 32);
    dim3 gNN(DIMC / 32, DIMC / 32);
    dim3 g1(HIDC / 128, NTOK / 128);  // (16, 64)
    dim3 g2(DIMC / 128, NTOK / 128);  // (8, 64)

    // launches 1-3 prereqs; #4 = mm1 (ncu captures 4th launch)
    convx_kernel<<<(NTOK * DIMC) / 256, 256>>>(x);                          // 1
    convt_kernel<<<gHN, 256>>>(w1_s, wt + W1S_OFF, DIMC, HIDC);             // 2
    convt_kernel<<<gHN, 256>>>(w3_s, wt + W3S_OFF, DIMC, HIDC);             // 3
    mm1_kernel<<<g1, 256, P1_SMEM>>>(                                       // 4 (profiled)
        wt + W1S_OFF, wt + W3S_OFF, nullptr, nullptr, nullptr);

    zero_kernel<<<1, 32>>>();
    gate_kernel<<<NTOK / 8, 256>>>(x, gate_w);
    if (out_size > NTOK * DIMC)
        aux_kernel<<<1, 1>>>(out + (out_size - 1));

    // remaining conversions
    convt_kernel<<<gHN, 256>>>(w1_s + E2, wt + W1S_OFF + E2, DIMC, HIDC);
    convt_kernel<<<gHN, 256>>>(w3_s + E2, wt + W3S_OFF + E2, DIMC, HIDC);
    for (int e = 0; e < 2; e++)
        convt_kernel<<<gNH, 256>>>(w2_s + e * E2, wt + W2S_OFF + e * E2, HIDC, DIMC);
    for (int e = 0; e < 6; e++) {
        convt_kernel<<<gHN, 256>>>(w1_r + e * E2, wt + W1R_OFF + e * E2, DIMC, HIDC);
        convt_kernel<<<gHN, 256>>>(w3_r + e * E2, wt + W3R_OFF + e * E2, DIMC, HIDC);
        convt_kernel<<<gNH, 256>>>(w2_r + e * E2, wt + W2R_OFF + e * E2, HIDC, DIMC);
    }
    convt_kernel<<<gNN, 256>>>(out_w, wt + OUTW_OFF, DIMC, DIMC);

    // shared expert 0 pass2 (pass1 launched above)
    mm2_kernel<<<g2, 256, P2_SMEM>>>(
        HIDC, wt + W2S_OFF, nullptr, nullptr, 0, comb);
    // shared expert 1
    mm1_kernel<<<g1, 256, P1_SMEM>>>(
        wt + W1S_OFF + E2, wt + W3S_OFF + E2, nullptr, nullptr, nullptr);
    mm2_kernel<<<g2, 256, P2_SMEM>>>(
        HIDC, wt + W2S_OFF + E2, nullptr, nullptr, 1, comb);
    // routed experts
    for (int e = 0; e < 6; e++) {
        mm1_kernel<<<g1, 256, P1_SMEM>>>(
            wt + W1R_OFF + e * E2, wt + W3R_OFF + e * E2,
            list + e * NTOK, lw + e * NTOK, cnt + e);
        mm2_kernel<<<g2, 256, P2_SMEM>>>(
            HIDC, wt + W2R_OFF + e * E2,
            list + e * NTOK, cnt + e, 1, comb);
    }
    // out projection
    convc_kernel<<<(NTOK * DIMC) / 256, 256>>>();
    mm2_kernel<<<g2, 256, P2_SMEM>>>(
        DIMC, wt + OUTW_OFF, nullptr, nullptr, 2, out);
}

// round 8
// speedup vs baseline: 6.1520x; 1.7058x over previous
#include <cuda_runtime.h>
#include <cuda_fp16.h>
#include <math.h>
#include <stdint.h>

typedef __half fp16;

#define NTOK 8192
#define DIMC 1024
#define HIDC 2048
#define NRE  6

#define W1S_OFF 0ull
#define W3S_OFF (4ull<<20)
#define W2S_OFF (8ull<<20)
#define W1R_OFF (12ull<<20)
#define W3R_OFF (24ull<<20)
#define W2R_OFF (36ull<<20)
#define OUTW_OFF (48ull<<20)
#define WT_TOTAL (49ull<<20)

__device__ fp16 g_wt[WT_TOTAL];              // weights fp16, [N][K]
__device__ fp16 g_x[(size_t)NTOK * DIMC];    // activations fp16
__device__ fp16 g_h[(size_t)NTOK * HIDC];    // hidden fp16 (also comb fp16)
__device__ float g_comb[(size_t)NTOK * DIMC];
__device__ int   g_list[NRE * NTOK];
__device__ float g_lw[NRE * NTOK];
__device__ int   g_cnt[NRE];
__device__ int   g_top1[NRE];
__device__ float g_psum[NRE];

// ===================== helpers =====================
__device__ __forceinline__ uint32_t s2u(const void* p) {
    return (uint32_t)__cvta_generic_to_shared(p);
}
__device__ __forceinline__ void cpa(uint32_t s, const void* g) {
    asm volatile("cp.async.cg.shared.global [%0], [%1], 16;" :: "r"(s), "l"(g));
}
__device__ __forceinline__ void cpa_commit() {
    asm volatile("cp.async.commit_group;" ::: "memory");
}
__device__ __forceinline__ void ldsm4(uint32_t* r, uint32_t addr) {
    asm volatile("ldmatrix.sync.aligned.m8n8.x4.shared.b16 {%0,%1,%2,%3}, [%4];"
        : "=r"(r[0]), "=r"(r[1]), "=r"(r[2]), "=r"(r[3]) : "r"(addr));
}
__device__ __forceinline__ void mma16816(float* d, const uint32_t* a, const uint32_t* b) {
    asm volatile("mma.sync.aligned.m16n8k16.row.col.f32.f16.f16.f32 "
        "{%0,%1,%2,%3}, {%4,%5,%6,%7}, {%8,%9}, {%0,%1,%2,%3};"
        : "+f"(d[0]), "+f"(d[1]), "+f"(d[2]), "+f"(d[3])
        : "r"(a[0]), "r"(a[1]), "r"(a[2]), "r"(a[3]), "r"(b[0]), "r"(b[1]));
}

// ===================== small kernels =====================
__global__ void zero_kernel() {
    int t = threadIdx.x;
    if (t < NRE) { g_cnt[t] = 0; g_top1[t] = 0; g_psum[t] = 0.f; }
}

__global__ void __launch_bounds__(256) gate_kernel(const float* __restrict__ x,
                                                   const float* __restrict__ gw) {
    __shared__ float sgw[DIMC * NRE];
    int tid = threadIdx.x;
    for (int i = tid; i < DIMC * NRE; i += 256) sgw[i] = gw[i];
    __syncthreads();
    int warp = tid >> 5, lane = tid & 31;
    int token = blockIdx.x * 8 + warp;
    if (token >= NTOK) return;
    const float* xr = x + (size_t)token * DIMC;
    float acc[NRE] = {0.f, 0.f, 0.f, 0.f, 0.f, 0.f};
    for (int k = lane; k < DIMC; k += 32) {
        float xv = xr[k];
#pragma unroll
        for (int e = 0; e < NRE; e++) acc[e] += xv * sgw[k * NRE + e];
    }
#pragma unroll
    for (int e = 0; e < NRE; e++)
#pragma unroll
        for (int o = 16; o > 0; o >>= 1)
            acc[e] += __shfl_xor_sync(0xffffffffu, acc[e], o);
    if (lane == 0) {
        int i0 = 0; float v0 = acc[0];
        for (int e = 1; e < NRE; e++) if (acc[e] > v0) { v0 = acc[e]; i0 = e; }
        int i1 = -1; float v1 = -1e30f;
        for (int e = 0; e < NRE; e++) if (e != i0 && acc[e] > v1) { v1 = acc[e]; i1 = e; }
        float e2 = expf(v1 - v0);
        float inv = 1.0f / (1.0f + e2);
        float w0 = inv, w1 = e2 * inv;
        float p[NRE]; float s = 0.f;
        for (int e = 0; e < NRE; e++) { p[e] = expf(acc[e] - v0); s += p[e]; }
        float is = 1.0f / s;
        for (int e = 0; e < NRE; e++) atomicAdd(&g_psum[e], p[e] * is);
        atomicAdd(&g_top1[i0], 1);
        int p0 = atomicAdd(&g_cnt[i0], 1);
        g_list[i0 * NTOK + p0] = token; g_lw[i0 * NTOK + p0] = w0;
        int p1 = atomicAdd(&g_cnt[i1], 1);
        g_list[i1 * NTOK + p1] = token; g_lw[i1 * NTOK + p1] = w1;
    }
}

__global__ void aux_kernel(float* dst) {
    float a = 0.f;
    for (int e = 0; e < NRE; e++) {
        float f = (float)g_top1[e] / (float)NTOK;
        float pm = g_psum[e] / (float)NTOK;
        a += f * pm;
    }
    *dst = 0.01f * (float)NRE * a;
}

__global__ void __launch_bounds__(256) convx_kernel(const float* __restrict__ x) {
    size_t i = ((size_t)blockIdx.x * 256 + threadIdx.x) * 2;
    float2 v = *(const float2*)(x + i);
    *(uint32_t*)(g_x + i) = *(uint32_t*)&__floats2half2_rn(v.x, v.y);
}

__global__ void __launch_bounds__(256) convc_kernel() {
    size_t i = ((size_t)blockIdx.x * 256 + threadIdx.x) * 2;
    float2 v = *(const float2*)(g_comb + i);
    *(uint32_t*)(g_h + i) = *(uint32_t*)&__floats2half2_rn(v.x, v.y);
}

// batched transpose+convert: up to 4 source arrays, z = matrix index
__global__ void __launch_bounds__(256) convt4_kernel(
    const float* s0, const float* s1, const float* s2, const float* s3,
    int c0, int c1, int c2,
    fp16* d, size_t o0, size_t o1, size_t o2, size_t o3,
    int K, int N)
{
    __shared__ float t[32][33];
    size_t msz = (size_t)K * N;
    int z = blockIdx.z;
    const float* src; fp16* dst;
    if (z < c0)                { src = s0 + (size_t)z * msz;             dst = d + o0 + (size_t)z * msz; }
    else if (z < c0 + c1)      { int i = z - c0;        src = s1 + (size_t)i * msz; dst = d + o1 + (size_t)i * msz; }
    else if (z < c0 + c1 + c2) { int i = z - c0 - c1;   src = s2 + (size_t)i * msz; dst = d + o2 + (size_t)i * msz; }
    else                       { int i = z - c0 - c1 - c2; src = s3 + (size_t)i * msz; dst = d + o3 + (size_t)i * msz; }

    int k0 = blockIdx.y * 32, n0 = blockIdx.x * 32;
    int tx = threadIdx.x & 31, ty = threadIdx.x >> 5;
#pragma unroll
    for (int i = 0; i < 4; i++)
        t[ty + i * 8][tx] = src[(size_t)(k0 + ty + i * 8) * N + n0 + tx];
    __syncthreads();
#pragma unroll
    for (int i = 0; i < 4; i++)
        dst[(size_t)(n0 + ty + i * 8) * K + k0 + tx] = __float2half_rn(t[tx][ty + i * 8]);
}

// ===================== mm1: h = silu(x@W1)*(x@W3)*scale =====================
// 128M x 128N, chunk K=64, 3-stage, warps 2(M)x4(N), pitch 144B
#define P1_PITCH 144
#define P1_MAT   18432
#define P1_A  0
#define P1_B1 (P1_MAT)
#define P1_B3 (2*P1_MAT)
#define P1_STG (3*P1_MAT)            // 55296
#define P1_SIDX (3*P1_STG)           // 165888
#define P1_SMEM (P1_SIDX + 512)      // 166400

__global__ void __launch_bounds__(256, 1) mm1_kernel(
    const fp16* __restrict__ W1, const fp16* __restrict__ W3,
    const int* __restrict__ gidx, const float* __restrict__ gscale,
    const int* __restrict__ cntPtr)
{
    extern __shared__ char smem[];
    const int M = cntPtr ? *cntPtr : NTOK;
    const int mBase = blockIdx.y * 128;
    if (mBase >= M) return;
    const int nBase = blockIdx.x * 128;
    const uint32_t sb = s2u(smem);
    const int tid = threadIdx.x;

    int* sIdx = (int*)(smem + P1_SIDX);
    if (tid < 128) {
        int r = mBase + tid;
        sIdx[tid] = (r < M) ? (gidx ? gidx[r] : r) : 0;
    }
    __syncthreads();

    auto load = [&](int buf, int k0) {
        uint32_t su = sb + buf * P1_STG;
#pragma unroll
        for (int it = 0; it < 4; it++) {
            int idx = tid + it * 256;
            int row = idx >> 3, seg = idx & 7;
            uint32_t so = row * P1_PITCH + seg * 16;
            size_t ga = (size_t)sIdx[row] * DIMC + k0 + seg * 8;
            cpa(su + P1_A + so, g_x + ga);
            size_t gw = (size_t)(nBase + row) * DIMC + k0 + seg * 8;
            cpa(su + P1_B1 + so, W1 + gw);
            cpa(su + P1_B3 + so, W3 + gw);
        }
        cpa_commit();
    };

    const int lane = tid & 31, wid = tid >> 5;
    const int wm = (wid & 1) * 64;
    const int wn = (wid >> 1) * 32;
    const int arow = (lane & 7) + ((lane >> 3) & 1) * 8;
    const int akh  = (lane >> 4) & 1;
    const int brow = (lane & 7) + ((lane >> 4) & 1) * 8;
    const int bkh  = (lane >> 3) & 1;

    float acc1[4][4][4], acc3[4][4][4];
#pragma unroll
    for (int i = 0; i < 4; i++)
#pragma unroll
        for (int j = 0; j < 4; j++)
#pragma unroll
            for (int k = 0; k < 4; k++) { acc1[i][j][k] = 0.f; acc3[i][j][k] = 0.f; }

    const int nc = DIMC / 64;   // 16
    load(0, 0);
    load(1, 64);
    for (int c = 0; c < nc; c++) {
        if (c + 1 < nc) asm volatile("cp.async.wait_group 1;" ::: "memory");
        else            asm volatile("cp.async.wait_group 0;" ::: "memory");
        __syncthreads();
        if (c + 2 < nc) load((c + 2) % 3, (c + 2) * 64);
        uint32_t su = sb + (c % 3) * P1_STG;
#pragma unroll
        for (int s = 0; s < 4; s++) {
            uint32_t a[4][4];
#pragma unroll
            for (int mi = 0; mi < 4; mi++) {
                uint32_t ao = (uint32_t)(wm + mi * 16 + arow) * P1_PITCH + s * 32 + akh * 16;
                ldsm4(a[mi], su + P1_A + ao);
            }
#pragma unroll
            for (int np = 0; np < 2; np++) {
                uint32_t b1[4], b3[4];
                uint32_t bo = (uint32_t)(wn + np * 16 + brow) * P1_PITCH + s * 32 + bkh * 16;
                ldsm4(b1, su + P1_B1 + bo);
                ldsm4(b3, su + P1_B3 + bo);
#pragma unroll
                for (int mi = 0; mi < 4; mi++)
#pragma unroll
                    for (int h = 0; h < 2; h++) {
                        int nt = np * 2 + h;
                        mma16816(acc1[mi][nt], a[mi], &b1[h * 2]);
                        mma16816(acc3[mi][nt], a[mi], &b3[h * 2]);
                    }
            }
        }
    }

#pragma unroll
    for (int mi = 0; mi < 4; mi++)
#pragma unroll
        for (int half = 0; half < 2; half++) {
            int slot = mBase + wm + mi * 16 + (lane >> 2) + half * 8;
            if (slot < M) {
                float sc = gscale ? gscale[slot] : 1.0f;
                size_t rb = (size_t)slot * HIDC + nBase + wn + (lane & 3) * 2;
#pragma unroll
                for (int nt = 0; nt < 4; nt++) {
                    float u0 = acc1[mi][nt][half * 2 + 0];
                    float u1 = acc1[mi][nt][half * 2 + 1];
                    float v0 = acc3[mi][nt][half * 2 + 0];
                    float v1 = acc3[mi][nt][half * 2 + 1];
                    float h0 = u0 / (1.f + __expf(-u0)) * v0 * sc;
                    float h1 = u1 / (1.f + __expf(-u1)) * v1 * sc;
                    __half2 hp = __floats2half2_rn(h0, h1);
                    *(uint32_t*)(g_h + rb + nt * 8) = *(uint32_t*)&hp;
                }
            }
        }
}

// ===================== mm2: C[crow,:] op= h @ W  (128x128, chunk 64, 3-stage, 2 CTA/SM) =====================
#define P2_A 0
#define P2_B 18432
#define P2_STG 36864
#define P2_SMEM (3*P2_STG)   // 110592

__global__ void __launch_bounds__(256, 2) mm2_kernel(
    int K,
    const fp16* __restrict__ B,
    const int* __restrict__ gidx, const int* __restrict__ cntPtr,
    int mode, float* __restrict__ cout)
{
    extern __shared__ char smem[];
    const int M = cntPtr ? *cntPtr : NTOK;
    const int mBase = blockIdx.y * 128;
    if (mBase >= M) return;
    const int nBase = blockIdx.x * 128;
    const uint32_t sb = s2u(smem);
    const int tid = threadIdx.x;

    auto load = [&](int buf, int k0) {
        uint32_t su = sb + buf * P2_STG;
#pragma unroll
        for (int it = 0; it < 4; it++) {
            int idx = tid + it * 256;
            int row = idx >> 3, seg = idx & 7;
            uint32_t so = row * 144 + seg * 16;
            int ar = mBase + row; if (ar >= M) ar = mBase;
            cpa(su + P2_A + so, g_h + (size_t)ar * K + k0 + seg * 8);
            cpa(su + P2_B + so, B + (size_t)(nBase + row) * K + k0 + seg * 8);
        }
        cpa_commit();
    };

    const int lane = tid & 31, wid = tid >> 5;
    const int wm = (wid & 1) * 64;
    const int wn = (wid >> 1) * 32;
    const int arow = (lane & 7) + ((lane >> 3) & 1) * 8;
    const int akh  = (lane >> 4) & 1;
    const int brow = (lane & 7) + ((lane >> 4) & 1) * 8;
    const int bkh  = (lane >> 3) & 1;

    float acc[4][4][4];
#pragma unroll
    for (int i = 0; i < 4; i++)
#pragma unroll
        for (int j = 0; j < 4; j++)
#pragma unroll
            for (int k = 0; k < 4; k++) acc[i][j][k] = 0.f;

    const int nc = K / 64;
    load(0, 0);
    load(1, 64);
    for (int c = 0; c < nc; c++) {
        if (c + 1 < nc) asm volatile("cp.async.wait_group 1;" ::: "memory");
        else            asm volatile("cp.async.wait_group 0;" ::: "memory");
        __syncthreads();
        if (c + 2 < nc) load((c + 2) % 3, (c + 2) * 64);
        uint32_t su = sb + (c % 3) * P2_STG;
#pragma unroll
        for (int s = 0; s < 4; s++) {
            uint32_t a[4][4];
#pragma unroll
            for (int mi = 0; mi < 4; mi++) {
                uint32_t ao = (uint32_t)(wm + mi * 16 + arow) * 144 + s * 32 + akh * 16;
                ldsm4(a[mi], su + P2_A + ao);
            }
#pragma unroll
            for (int np = 0; np < 2; np++) {
                uint32_t b[4];
                uint32_t bo = (uint32_t)(wn + np * 16 + brow) * 144 + s * 32 + bkh * 16;
                ldsm4(b, su + P2_B + bo);
#pragma unroll
                for (int mi = 0; mi < 4; mi++)
#pragma unroll
                    for (int h = 0; h < 2; h++)
                        mma16816(acc[mi][np * 2 + h], a[mi], &b[h * 2]);
            }
        }
    }

#pragma unroll
    for (int mi = 0; mi < 4; mi++)
#pragma unroll
        for (int half = 0; half < 2; half++) {
            int slot = mBase + wm + mi * 16 + (lane >> 2) + half * 8;
            if (slot < M) {
                int crow = (mode == 1 && gidx) ? gidx[slot] : slot;
                float* cp = cout + (size_t)crow * DIMC + nBase + wn + (lane & 3) * 2;
#pragma unroll
                for (int nt = 0; nt < 4; nt++) {
                    float2 v = make_float2(acc[mi][nt][half * 2 + 0],
                                           acc[mi][nt][half * 2 + 1]);
                    if (mode == 1) {
                        float2 o = *(float2*)(cp + nt * 8);
                        v.x += o.x; v.y += o.y;
                    }
                    *(float2*)(cp + nt * 8) = v;
                }
            }
        }
}

// ===================== host =====================
extern "C" void kernel_launch(void* const* d_in, const int* in_sizes, int n_in,
                              void* d_out, int out_size)
{
    const float* x      = (const float*)d_in[0];
    const float* w1_s   = (const float*)d_in[1];
    const float* w2_s   = (const float*)d_in[2];
    const float* w3_s   = (const float*)d_in[3];
    const float* w1_r   = (const float*)d_in[4];
    const float* w2_r   = (const float*)d_in[5];
    const float* w3_r   = (const float*)d_in[6];
    const float* gate_w = (const float*)d_in[7];
    const float* out_w  = (const float*)d_in[8];
    float* out = (float*)d_out;

    fp16 *wt;
    int *list, *cnt; float *lw, *comb;
    cudaGetSymbolAddress((void**)&wt, g_wt);
    cudaGetSymbolAddress((void**)&list, g_list);
    cudaGetSymbolAddress((void**)&lw, g_lw);
    cudaGetSymbolAddress((void**)&cnt, g_cnt);
    cudaGetSymbolAddress((void**)&comb, g_comb);

    cudaFuncSetAttribute(mm1_kernel, cudaFuncAttributeMaxDynamicSharedMemorySize, P1_SMEM);
    cudaFuncSetAttribute(mm2_kernel, cudaFuncAttributeMaxDynamicSharedMemorySize, P2_SMEM);

    const size_t E2 = 2ull << 20;
    dim3 g1(HIDC / 128, NTOK / 128);  // (16, 64)
    dim3 g2(DIMC / 128, NTOK / 128);  // (8, 64)

    // 1: activations
    convx_kernel<<<(NTOK * DIMC) / 512, 256>>>(x);
    // 2: all [DIMC->HIDC] weights (w1_s, w3_s, w1_r, w3_r = 16 matrices)
    {
        dim3 g(HIDC / 32, DIMC / 32, 16);
        convt4_kernel<<<g, 256>>>(w1_s, w3_s, w1_r, w3_r, 2, 2, 6,
                                  wt, W1S_OFF, W3S_OFF, W1R_OFF, W3R_OFF,
                                  DIMC, HIDC);
    }
    // 3: all [HIDC->DIMC] weights (w2_s, w2_r = 8 matrices)
    {
        dim3 g(DIMC / 32, HIDC / 32, 8);
        convt4_kernel<<<g, 256>>>(w2_s, w2_r, w2_r, w2_r, 2, 6, 0,
                                  wt, W2S_OFF, W2R_OFF, 0, 0,
                                  HIDC, DIMC);
    }
    // 4: mm1 shared expert 0 (profiled by ncu)
    mm1_kernel<<<g1, 256, P1_SMEM>>>(wt + W1S_OFF, wt + W3S_OFF,
                                     nullptr, nullptr, nullptr);

    // out_w conversion
    {
        dim3 g(DIMC / 32, DIMC / 32, 1);
        convt4_kernel<<<g, 256>>>(out_w, out_w, out_w, out_w, 1, 0, 0,
                                  wt, OUTW_OFF, 0, 0, 0, DIMC, DIMC);
    }
    zero_kernel<<<1, 32>>>();
    gate_kernel<<<NTOK / 8, 256>>>(x, gate_w);
    if (out_size > NTOK * DIMC)
        aux_kernel<<<1, 1>>>(out + (out_size - 1));

    // shared expert 0 pass2
    mm2_kernel<<<g2, 256, P2_SMEM>>>(HIDC, wt + W2S_OFF, nullptr, nullptr, 0, comb);
    // shared expert 1
    mm1_kernel<<<g1, 256, P1_SMEM>>>(wt + W1S_OFF + E2, wt + W3S_OFF + E2,
                                     nullptr, nullptr, nullptr);
    mm2_kernel<<<g2, 256, P2_SMEM>>>(HIDC, wt + W2S_OFF + E2, nullptr, nullptr, 1, comb);
    // routed experts
    for (int e = 0; e < 6; e++) {
        mm1_kernel<<<g1, 256, P1_SMEM>>>(
            wt + W1R_OFF + e * E2, wt + W3R_OFF + e * E2,
            list + e * NTOK, lw + e * NTOK, cnt + e);
        mm2_kernel<<<g2, 256, P2_SMEM>>>(
            HIDC, wt + W2R_OFF + e * E2, list + e * NTOK, cnt + e, 1, comb);
    }
    // out projection
    convc_kernel<<<(NTOK * DIMC) / 512, 256>>>();
    mm2_kernel<<<g2, 256, P2_SMEM>>>(DIMC, wt + OUTW_OFF, nullptr, nullptr, 2, out);
}

// round 9
// speedup vs baseline: 7.3791x; 1.1995x over previous
#include <cuda_runtime.h>
#include <cuda_fp16.h>
#include <math.h>
#include <stdint.h>

typedef __half fp16;

#define NTOK 8192
#define DIMC 1024
#define HIDC 2048
#define NRE  6
#define E2   (2ull<<20)

#define W1S_OFF 0ull
#define W3S_OFF (4ull<<20)
#define W2S_OFF (8ull<<20)
#define W1R_OFF (12ull<<20)
#define W3R_OFF (24ull<<20)
#define W2R_OFF (36ull<<20)
#define OUTW_OFF (48ull<<20)
#define WT_TOTAL (49ull<<20)

__device__ fp16 g_wt[WT_TOTAL];                      // weights fp16 [N][K]
__device__ fp16 g_x[(size_t)NTOK * DIMC];            // activations fp16
__device__ fp16 g_hall[8ull * NTOK * HIDC];          // h per expert slice (256MB)
__device__ float g_comb[(size_t)NTOK * DIMC];        // shared-expert sum fp32
__device__ float g_bufA[(size_t)NTOK * DIMC];        // routed top-1 contribution
__device__ float g_bufB[(size_t)NTOK * DIMC];        // routed top-2 contribution
__device__ fp16 g_hc[(size_t)NTOK * DIMC];           // combined fp16 for out-proj
__device__ int   g_list[NRE * NTOK];
__device__ float g_lw[NRE * NTOK];
__device__ int   g_lrank[NRE * NTOK];
__device__ int   g_cnt[NRE];
__device__ int   g_top1[NRE];
__device__ float g_psum[NRE];

// ===================== helpers =====================
__device__ __forceinline__ uint32_t s2u(const void* p) {
    return (uint32_t)__cvta_generic_to_shared(p);
}
__device__ __forceinline__ void cpa(uint32_t s, const void* g) {
    asm volatile("cp.async.cg.shared.global [%0], [%1], 16;" :: "r"(s), "l"(g));
}
__device__ __forceinline__ void cpa_commit() {
    asm volatile("cp.async.commit_group;" ::: "memory");
}
__device__ __forceinline__ void ldsm4(uint32_t* r, uint32_t addr) {
    asm volatile("ldmatrix.sync.aligned.m8n8.x4.shared.b16 {%0,%1,%2,%3}, [%4];"
        : "=r"(r[0]), "=r"(r[1]), "=r"(r[2]), "=r"(r[3]) : "r"(addr));
}
__device__ __forceinline__ void mma16816(float* d, const uint32_t* a, const uint32_t* b) {
    asm volatile("mma.sync.aligned.m16n8k16.row.col.f32.f16.f16.f32 "
        "{%0,%1,%2,%3}, {%4,%5,%6,%7}, {%8,%9}, {%0,%1,%2,%3};"
        : "+f"(d[0]), "+f"(d[1]), "+f"(d[2]), "+f"(d[3])
        : "r"(a[0]), "r"(a[1]), "r"(a[2]), "r"(a[3]), "r"(b[0]), "r"(b[1]));
}

// ===================== small kernels =====================
// convx also zeroes the gate counters (block 0)
__global__ void __launch_bounds__(256) convx_kernel(const float* __restrict__ x) {
    if (blockIdx.x == 0 && threadIdx.x < NRE) {
        g_cnt[threadIdx.x] = 0; g_top1[threadIdx.x] = 0; g_psum[threadIdx.x] = 0.f;
    }
    size_t i = ((size_t)blockIdx.x * 256 + threadIdx.x) * 2;
    float2 v = *(const float2*)(x + i);
    *(uint32_t*)(g_x + i) = *(uint32_t*)&__floats2half2_rn(v.x, v.y);
}

__global__ void __launch_bounds__(256) gate_kernel(const float* __restrict__ x,
                                                   const float* __restrict__ gw) {
    __shared__ float sgw[DIMC * NRE];
    int tid = threadIdx.x;
    for (int i = tid; i < DIMC * NRE; i += 256) sgw[i] = gw[i];
    __syncthreads();
    int warp = tid >> 5, lane = tid & 31;
    int token = blockIdx.x * 8 + warp;
    if (token >= NTOK) return;
    const float* xr = x + (size_t)token * DIMC;
    float acc[NRE] = {0.f, 0.f, 0.f, 0.f, 0.f, 0.f};
    for (int k = lane; k < DIMC; k += 32) {
        float xv = xr[k];
#pragma unroll
        for (int e = 0; e < NRE; e++) acc[e] += xv * sgw[k * NRE + e];
    }
#pragma unroll
    for (int e = 0; e < NRE; e++)
#pragma unroll
        for (int o = 16; o > 0; o >>= 1)
            acc[e] += __shfl_xor_sync(0xffffffffu, acc[e], o);
    if (lane == 0) {
        int i0 = 0; float v0 = acc[0];
        for (int e = 1; e < NRE; e++) if (acc[e] > v0) { v0 = acc[e]; i0 = e; }
        int i1 = -1; float v1 = -1e30f;
        for (int e = 0; e < NRE; e++) if (e != i0 && acc[e] > v1) { v1 = acc[e]; i1 = e; }
        float e2 = expf(v1 - v0);
        float inv = 1.0f / (1.0f + e2);
        float w0 = inv, w1 = e2 * inv;
        float p[NRE]; float s = 0.f;
        for (int e = 0; e < NRE; e++) { p[e] = expf(acc[e] - v0); s += p[e]; }
        float is = 1.0f / s;
        for (int e = 0; e < NRE; e++) atomicAdd(&g_psum[e], p[e] * is);
        atomicAdd(&g_top1[i0], 1);
        int p0 = atomicAdd(&g_cnt[i0], 1);
        g_list[i0 * NTOK + p0] = token; g_lw[i0 * NTOK + p0] = w0; g_lrank[i0 * NTOK + p0] = 0;
        int p1 = atomicAdd(&g_cnt[i1], 1);
        g_list[i1 * NTOK + p1] = token; g_lw[i1 * NTOK + p1] = w1; g_lrank[i1 * NTOK + p1] = 1;
    }
}

__global__ void aux_kernel(float* dst) {
    float a = 0.f;
    for (int e = 0; e < NRE; e++) {
        float f = (float)g_top1[e] / (float)NTOK;
        float pm = g_psum[e] / (float)NTOK;
        a += f * pm;
    }
    *dst = 0.01f * (float)NRE * a;
}

// all 25 weight matrices transposed+converted in one launch. z = matrix id
__global__ void __launch_bounds__(256) convt_all_kernel(
    const float* w1_s, const float* w3_s, const float* w2_s,
    const float* w1_r, const float* w3_r, const float* w2_r,
    const float* out_w)
{
    __shared__ float t[32][33];
    int z = blockIdx.z;
    int K, N; const float* src; fp16* dst;
    if (z < 16) {
        K = DIMC; N = HIDC;
        if (z < 2)       { src = w1_s + (size_t)z * E2;        dst = g_wt + W1S_OFF + (size_t)z * E2; }
        else if (z < 4)  { int e = z - 2;  src = w3_s + (size_t)e * E2; dst = g_wt + W3S_OFF + (size_t)e * E2; }
        else if (z < 10) { int e = z - 4;  src = w1_r + (size_t)e * E2; dst = g_wt + W1R_OFF + (size_t)e * E2; }
        else             { int e = z - 10; src = w3_r + (size_t)e * E2; dst = g_wt + W3R_OFF + (size_t)e * E2; }
    } else if (z < 24) {
        K = HIDC; N = DIMC;
        if (z < 18) { int e = z - 16; src = w2_s + (size_t)e * E2; dst = g_wt + W2S_OFF + (size_t)e * E2; }
        else        { int e = z - 18; src = w2_r + (size_t)e * E2; dst = g_wt + W2R_OFF + (size_t)e * E2; }
    } else {
        K = DIMC; N = DIMC; src = out_w; dst = g_wt + OUTW_OFF;
    }
    int k0 = blockIdx.y * 32, n0 = blockIdx.x * 32;
    if (k0 >= K || n0 >= N) return;
    int tx = threadIdx.x & 31, ty = threadIdx.x >> 5;
#pragma unroll
    for (int i = 0; i < 4; i++)
        t[ty + i * 8][tx] = src[(size_t)(k0 + ty + i * 8) * N + n0 + tx];
    __syncthreads();
#pragma unroll
    for (int i = 0; i < 4; i++)
        dst[(size_t)(n0 + ty + i * 8) * K + k0 + tx] = __float2half_rn(t[tx][ty + i * 8]);
}

// comb + bufA + bufB -> fp16
__global__ void __launch_bounds__(256) convc3_kernel() {
    size_t i = ((size_t)blockIdx.x * 256 + threadIdx.x) * 2;
    float2 a = *(const float2*)(g_comb + i);
    float2 b = *(const float2*)(g_bufA + i);
    float2 c = *(const float2*)(g_bufB + i);
    *(uint32_t*)(g_hc + i) = *(uint32_t*)&__floats2half2_rn(a.x + b.x + c.x, a.y + b.y + c.y);
}

// ===================== mm1_all: all 8 pass-1 GEMMs, z = expert slice =====================
// 128M x 128N, chunk K=64, 3-stage, warps 2(M)x4(N), pitch 144B
#define P1_PITCH 144
#define P1_MAT   18432
#define P1_A  0
#define P1_B1 (P1_MAT)
#define P1_B3 (2*P1_MAT)
#define P1_STG (3*P1_MAT)            // 55296
#define P1_SIDX (3*P1_STG)           // 165888
#define P1_SMEM (P1_SIDX + 512)      // 166400

__global__ void __launch_bounds__(256, 1) mm1_all_kernel()
{
    extern __shared__ char smem[];
    const int z = blockIdx.z;
    const fp16* W1; const fp16* W3;
    const int* gidx; const float* gscale; int M;
    if (z < 2) {
        W1 = g_wt + W1S_OFF + (size_t)z * E2;
        W3 = g_wt + W3S_OFF + (size_t)z * E2;
        gidx = nullptr; gscale = nullptr; M = NTOK;
    } else {
        int e = z - 2;
        W1 = g_wt + W1R_OFF + (size_t)e * E2;
        W3 = g_wt + W3R_OFF + (size_t)e * E2;
        gidx = g_list + e * NTOK; gscale = g_lw + e * NTOK; M = g_cnt[e];
    }
    fp16* hout = g_hall + (size_t)z * NTOK * HIDC;

    const int mBase = blockIdx.y * 128;
    if (mBase >= M) return;
    const int nBase = blockIdx.x * 128;
    const uint32_t sb = s2u(smem);
    const int tid = threadIdx.x;

    int* sIdx = (int*)(smem + P1_SIDX);
    if (tid < 128) {
        int r = mBase + tid;
        sIdx[tid] = (r < M) ? (gidx ? gidx[r] : r) : 0;
    }
    __syncthreads();

    auto load = [&](int buf, int k0) {
        uint32_t su = sb + buf * P1_STG;
#pragma unroll
        for (int it = 0; it < 4; it++) {
            int idx = tid + it * 256;
            int row = idx >> 3, seg = idx & 7;
            uint32_t so = row * P1_PITCH + seg * 16;
            size_t ga = (size_t)sIdx[row] * DIMC + k0 + seg * 8;
            cpa(su + P1_A + so, g_x + ga);
            size_t gw = (size_t)(nBase + row) * DIMC + k0 + seg * 8;
            cpa(su + P1_B1 + so, W1 + gw);
            cpa(su + P1_B3 + so, W3 + gw);
        }
        cpa_commit();
    };

    const int lane = tid & 31, wid = tid >> 5;
    const int wm = (wid & 1) * 64;
    const int wn = (wid >> 1) * 32;
    const int arow = (lane & 7) + ((lane >> 3) & 1) * 8;
    const int akh  = (lane >> 4) & 1;
    const int brow = (lane & 7) + ((lane >> 4) & 1) * 8;
    const int bkh  = (lane >> 3) & 1;

    float acc1[4][4][4], acc3[4][4][4];
#pragma unroll
    for (int i = 0; i < 4; i++)
#pragma unroll
        for (int j = 0; j < 4; j++)
#pragma unroll
            for (int k = 0; k < 4; k++) { acc1[i][j][k] = 0.f; acc3[i][j][k] = 0.f; }

    const int nc = DIMC / 64;   // 16
    load(0, 0);
    load(1, 64);
    for (int c = 0; c < nc; c++) {
        if (c + 1 < nc) asm volatile("cp.async.wait_group 1;" ::: "memory");
        else            asm volatile("cp.async.wait_group 0;" ::: "memory");
        __syncthreads();
        if (c + 2 < nc) load((c + 2) % 3, (c + 2) * 64);
        uint32_t su = sb + (c % 3) * P1_STG;
#pragma unroll
        for (int s = 0; s < 4; s++) {
            uint32_t a[4][4];
#pragma unroll
            for (int mi = 0; mi < 4; mi++) {
                uint32_t ao = (uint32_t)(wm + mi * 16 + arow) * P1_PITCH + s * 32 + akh * 16;
                ldsm4(a[mi], su + P1_A + ao);
            }
#pragma unroll
            for (int np = 0; np < 2; np++) {
                uint32_t b1[4], b3[4];
                uint32_t bo = (uint32_t)(wn + np * 16 + brow) * P1_PITCH + s * 32 + bkh * 16;
                ldsm4(b1, su + P1_B1 + bo);
                ldsm4(b3, su + P1_B3 + bo);
#pragma unroll
                for (int mi = 0; mi < 4; mi++)
#pragma unroll
                    for (int h = 0; h < 2; h++) {
                        int nt = np * 2 + h;
                        mma16816(acc1[mi][nt], a[mi], &b1[h * 2]);
                        mma16816(acc3[mi][nt], a[mi], &b3[h * 2]);
                    }
            }
        }
    }

#pragma unroll
    for (int mi = 0; mi < 4; mi++)
#pragma unroll
        for (int half = 0; half < 2; half++) {
            int slot = mBase + wm + mi * 16 + (lane >> 2) + half * 8;
            if (slot < M) {
                float sc = gscale ? gscale[slot] : 1.0f;
                size_t rb = (size_t)slot * HIDC + nBase + wn + (lane & 3) * 2;
#pragma unroll
                for (int nt = 0; nt < 4; nt++) {
                    float u0 = acc1[mi][nt][half * 2 + 0];
                    float u1 = acc1[mi][nt][half * 2 + 1];
                    float v0 = acc3[mi][nt][half * 2 + 0];
                    float v1 = acc3[mi][nt][half * 2 + 1];
                    float h0 = u0 / (1.f + __expf(-u0)) * v0 * sc;
                    float h1 = u1 / (1.f + __expf(-u1)) * v1 * sc;
                    __half2 hp = __floats2half2_rn(h0, h1);
                    *(uint32_t*)(hout + rb + nt * 8) = *(uint32_t*)&hp;
                }
            }
        }
}

// ===================== mm2 core (128x128, chunk 64, 3-stage) =====================
#define P2_A 0
#define P2_B 18432
#define P2_STG 36864
#define P2_SMEM (3*P2_STG)   // 110592

// mm2sh: shared experts 0+1 fused (acc carried across both K-loops), write comb fp32
__global__ void __launch_bounds__(256, 2) mm2sh_kernel()
{
    extern __shared__ char smem[];
    const int mBase = blockIdx.y * 128;
    const int nBase = blockIdx.x * 128;
    const uint32_t sb = s2u(smem);
    const int tid = threadIdx.x;

    const int lane = tid & 31, wid = tid >> 5;
    const int wm = (wid & 1) * 64;
    const int wn = (wid >> 1) * 32;
    const int arow = (lane & 7) + ((lane >> 3) & 1) * 8;
    const int akh  = (lane >> 4) & 1;
    const int brow = (lane & 7) + ((lane >> 4) & 1) * 8;
    const int bkh  = (lane >> 3) & 1;

    float acc[4][4][4];
#pragma unroll
    for (int i = 0; i < 4; i++)
#pragma unroll
        for (int j = 0; j < 4; j++)
#pragma unroll
            for (int k = 0; k < 4; k++) acc[i][j][k] = 0.f;

    for (int ss = 0; ss < 2; ss++) {
        const fp16* A = g_hall + (size_t)ss * NTOK * HIDC;
        const fp16* B = g_wt + W2S_OFF + (size_t)ss * E2;
        auto load = [&](int buf, int k0) {
            uint32_t su = sb + buf * P2_STG;
#pragma unroll
            for (int it = 0; it < 4; it++) {
                int idx = tid + it * 256;
                int row = idx >> 3, seg = idx & 7;
                uint32_t so = row * 144 + seg * 16;
                cpa(su + P2_A + so, A + (size_t)(mBase + row) * HIDC + k0 + seg * 8);
                cpa(su + P2_B + so, B + (size_t)(nBase + row) * HIDC + k0 + seg * 8);
            }
            cpa_commit();
        };
        const int nc = HIDC / 64;
        load(0, 0);
        load(1, 64);
        for (int c = 0; c < nc; c++) {
            if (c + 1 < nc) asm volatile("cp.async.wait_group 1;" ::: "memory");
            else            asm volatile("cp.async.wait_group 0;" ::: "memory");
            __syncthreads();
            if (c + 2 < nc) load((c + 2) % 3, (c + 2) * 64);
            uint32_t su = sb + (c % 3) * P2_STG;
#pragma unroll
            for (int s = 0; s < 4; s++) {
                uint32_t a[4][4];
#pragma unroll
                for (int mi = 0; mi < 4; mi++) {
                    uint32_t ao = (uint32_t)(wm + mi * 16 + arow) * 144 + s * 32 + akh * 16;
                    ldsm4(a[mi], su + P2_A + ao);
                }
#pragma unroll
                for (int np = 0; np < 2; np++) {
                    uint32_t b[4];
                    uint32_t bo = (uint32_t)(wn + np * 16 + brow) * 144 + s * 32 + bkh * 16;
                    ldsm4(b, su + P2_B + bo);
#pragma unroll
                    for (int mi = 0; mi < 4; mi++)
#pragma unroll
                        for (int h = 0; h < 2; h++)
                            mma16816(acc[mi][np * 2 + h], a[mi], &b[h * 2]);
                }
            }
        }
        __syncthreads();
    }

#pragma unroll
    for (int mi = 0; mi < 4; mi++)
#pragma unroll
        for (int half = 0; half < 2; half++) {
            int t = mBase + wm + mi * 16 + (lane >> 2) + half * 8;
            float* cp = g_comb + (size_t)t * DIMC + nBase + wn + (lane & 3) * 2;
#pragma unroll
            for (int nt = 0; nt < 4; nt++)
                *(float2*)(cp + nt * 8) = make_float2(acc[mi][nt][half * 2 + 0],
                                                      acc[mi][nt][half * 2 + 1]);
        }
}

// mm2rt: all 6 routed experts, z = expert; rows scatter to bufA (rank0) / bufB (rank1)
__global__ void __launch_bounds__(256, 2) mm2rt_kernel()
{
    extern __shared__ char smem[];
    const int e = blockIdx.z;
    const int M = g_cnt[e];
    const int mBase = blockIdx.y * 128;
    if (mBase >= M) return;
    const int nBase = blockIdx.x * 128;
    const fp16* A = g_hall + (size_t)(2 + e) * NTOK * HIDC;
    const fp16* B = g_wt + W2R_OFF + (size_t)e * E2;
    const uint32_t sb = s2u(smem);
    const int tid = threadIdx.x;

    auto load = [&](int buf, int k0) {
        uint32_t su = sb + buf * P2_STG;
#pragma unroll
        for (int it = 0; it < 4; it++) {
            int idx = tid + it * 256;
            int row = idx >> 3, seg = idx & 7;
            uint32_t so = row * 144 + seg * 16;
            int ar = mBase + row; if (ar >= M) ar = mBase;
            cpa(su + P2_A + so, A + (size_t)ar * HIDC + k0 + seg * 8);
            cpa(su + P2_B + so, B + (size_t)(nBase + row) * HIDC + k0 + seg * 8);
        }
        cpa_commit();
    };

    const int lane = tid & 31, wid = tid >> 5;
    const int wm = (wid & 1) * 64;
    const int wn = (wid >> 1) * 32;
    const int arow = (lane & 7) + ((lane >> 3) & 1) * 8;
    const int akh  = (lane >> 4) & 1;
    const int brow = (lane & 7) + ((lane >> 4) & 1) * 8;
    const int bkh  = (lane >> 3) & 1;

    float acc[4][4][4];
#pragma unroll
    for (int i = 0; i < 4; i++)
#pragma unroll
        for (int j = 0; j < 4; j++)
#pragma unroll
            for (int k = 0; k < 4; k++) acc[i][j][k] = 0.f;

    const int nc = HIDC / 64;
    load(0, 0);
    load(1, 64);
    for (int c = 0; c < nc; c++) {
        if (c + 1 < nc) asm volatile("cp.async.wait_group 1;" ::: "memory");
        else            asm volatile("cp.async.wait_group 0;" ::: "memory");
        __syncthreads();
        if (c + 2 < nc) load((c + 2) % 3, (c + 2) * 64);
        uint32_t su = sb + (c % 3) * P2_STG;
#pragma unroll
        for (int s = 0; s < 4; s++) {
            uint32_t a[4][4];
#pragma unroll
            for (int mi = 0; mi < 4; mi++) {
                uint32_t ao = (uint32_t)(wm + mi * 16 + arow) * 144 + s * 32 + akh * 16;
                ldsm4(a[mi], su + P2_A + ao);
            }
#pragma unroll
            for (int np = 0; np < 2; np++) {
                uint32_t b[4];
                uint32_t bo = (uint32_t)(wn + np * 16 + brow) * 144 + s * 32 + bkh * 16;
                ldsm4(b, su + P2_B + bo);
#pragma unroll
                for (int mi = 0; mi < 4; mi++)
#pragma unroll
                    for (int h = 0; h < 2; h++)
                        mma16816(acc[mi][np * 2 + h], a[mi], &b[h * 2]);
            }
        }
    }

#pragma unroll
    for (int mi = 0; mi < 4; mi++)
#pragma unroll
        for (int half = 0; half < 2; half++) {
            int slot = mBase + wm + mi * 16 + (lane >> 2) + half * 8;
            if (slot < M) {
                int t = g_list[e * NTOK + slot];
                int rk = g_lrank[e * NTOK + slot];
                float* base = rk ? g_bufB : g_bufA;
                float* cp = base + (size_t)t * DIMC + nBase + wn + (lane & 3) * 2;
#pragma unroll
                for (int nt = 0; nt < 4; nt++)
                    *(float2*)(cp + nt * 8) = make_float2(acc[mi][nt][half * 2 + 0],
                                                          acc[mi][nt][half * 2 + 1]);
            }
        }
}

// outproj: out = g_hc @ outw (K=1024), fp32 out
__global__ void __launch_bounds__(256, 2) outproj_kernel(float* __restrict__ out)
{
    extern __shared__ char smem[];
    const int mBase = blockIdx.y * 128;
    const int nBase = blockIdx.x * 128;
    const fp16* B = g_wt + OUTW_OFF;
    const uint32_t sb = s2u(smem);
    const int tid = threadIdx.x;

    auto load = [&](int buf, int k0) {
        uint32_t su = sb + buf * P2_STG;
#pragma unroll
        for (int it = 0; it < 4; it++) {
            int idx = tid + it * 256;
            int row = idx >> 3, seg = idx & 7;
            uint32_t so = row * 144 + seg * 16;
            cpa(su + P2_A + so, g_hc + (size_t)(mBase + row) * DIMC + k0 + seg * 8);
            cpa(su + P2_B + so, B + (size_t)(nBase + row) * DIMC + k0 + seg * 8);
        }
        cpa_commit();
    };

    const int lane = tid & 31, wid = tid >> 5;
    const int wm = (wid & 1) * 64;
    const int wn = (wid >> 1) * 32;
    const int arow = (lane & 7) + ((lane >> 3) & 1) * 8;
    const int akh  = (lane >> 4) & 1;
    const int brow = (lane & 7) + ((lane >> 4) & 1) * 8;
    const int bkh  = (lane >> 3) & 1;

    float acc[4][4][4];
#pragma unroll
    for (int i = 0; i < 4; i++)
#pragma unroll
        for (int j = 0; j < 4; j++)
#pragma unroll
            for (int k = 0; k < 4; k++) acc[i][j][k] = 0.f;

    const int nc = DIMC / 64;
    load(0, 0);
    load(1, 64);
    for (int c = 0; c < nc; c++) {
        if (c + 1 < nc) asm volatile("cp.async.wait_group 1;" ::: "memory");
        else            asm volatile("cp.async.wait_group 0;" ::: "memory");
        __syncthreads();
        if (c + 2 < nc) load((c + 2) % 3, (c + 2) * 64);
        uint32_t su = sb + (c % 3) * P2_STG;
#pragma unroll
        for (int s = 0; s < 4; s++) {
            uint32_t a[4][4];
#pragma unroll
            for (int mi = 0; mi < 4; mi++) {
                uint32_t ao = (uint32_t)(wm + mi * 16 + arow) * 144 + s * 32 + akh * 16;
                ldsm4(a[mi], su + P2_A + ao);
            }
#pragma unroll
            for (int np = 0; np < 2; np++) {
                uint32_t b[4];
                uint32_t bo = (uint32_t)(wn + np * 16 + brow) * 144 + s * 32 + bkh * 16;
                ldsm4(b, su + P2_B + bo);
#pragma unroll
                for (int mi = 0; mi < 4; mi++)
#pragma unroll
                    for (int h = 0; h < 2; h++)
                        mma16816(acc[mi][np * 2 + h], a[mi], &b[h * 2]);
            }
        }
    }

#pragma unroll
    for (int mi = 0; mi < 4; mi++)
#pragma unroll
        for (int half = 0; half < 2; half++) {
            int t = mBase + wm + mi * 16 + (lane >> 2) + half * 8;
            float* cp = out + (size_t)t * DIMC + nBase + wn + (lane & 3) * 2;
#pragma unroll
            for (int nt = 0; nt < 4; nt++)
                *(float2*)(cp + nt * 8) = make_float2(acc[mi][nt][half * 2 + 0],
                                                      acc[mi][nt][half * 2 + 1]);
        }
}

// ===================== host =====================
extern "C" void kernel_launch(void* const* d_in, const int* in_sizes, int n_in,
                              void* d_out, int out_size)
{
    const float* x      = (const float*)d_in[0];
    const float* w1_s   = (const float*)d_in[1];
    const float* w2_s   = (const float*)d_in[2];
    const float* w3_s   = (const float*)d_in[3];
    const float* w1_r   = (const float*)d_in[4];
    const float* w2_r   = (const float*)d_in[5];
    const float* w3_r   = (const float*)d_in[6];
    const float* gate_w = (const float*)d_in[7];
    const float* out_w  = (const float*)d_in[8];
    float* out = (float*)d_out;

    cudaFuncSetAttribute(mm1_all_kernel, cudaFuncAttributeMaxDynamicSharedMemorySize, P1_SMEM);
    cudaFuncSetAttribute(mm2sh_kernel,  cudaFuncAttributeMaxDynamicSharedMemorySize, P2_SMEM);
    cudaFuncSetAttribute(mm2rt_kernel,  cudaFuncAttributeMaxDynamicSharedMemorySize, P2_SMEM);
    cudaFuncSetAttribute(outproj_kernel, cudaFuncAttributeMaxDynamicSharedMemorySize, P2_SMEM);

    // 1: activations (+counter zeroing)
    convx_kernel<<<(NTOK * DIMC) / 512, 256>>>(x);
    // 2: gate (routing lists, ranks, softmax stats)
    gate_kernel<<<NTOK / 8, 256>>>(x, gate_w);
    // 3: all 25 weight matrices
    {
        dim3 g(64, 64, 25);
        convt_all_kernel<<<g, 256>>>(w1_s, w3_s, w2_s, w1_r, w3_r, w2_r, out_w);
    }
    // 4: all 8 pass-1 GEMMs (profiled by ncu)
    {
        dim3 g(HIDC / 128, NTOK / 128, 8);
        mm1_all_kernel<<<g, 256, P1_SMEM>>>();
    }
    // 5: shared-expert pass-2 (both experts fused)
    {
        dim3 g(DIMC / 128, NTOK / 128);
        mm2sh_kernel<<<g, 256, P2_SMEM>>>();
    }
    // 6: all 6 routed pass-2 GEMMs (rank-disjoint scatter, no atomics)
    {
        dim3 g(DIMC / 128, NTOK / 128, NRE);
        mm2rt_kernel<<<g, 256, P2_SMEM>>>();
    }
    // 7: combine comb + bufA + bufB -> fp16
    convc3_kernel<<<(NTOK * DIMC) / 512, 256>>>();
    // 8: out projection
    {
        dim3 g(DIMC / 128, NTOK / 128);
        outproj_kernel<<<g, 256, P2_SMEM>>>(out);
    }
    // 9: aux loss
    if (out_size > NTOK * DIMC)
        aux_kernel<<<1, 1>>>(out + (out_size - 1));
}

// round 10
// speedup vs baseline: 8.0526x; 1.0913x over previous
#include <cuda_runtime.h>
#include <cuda_fp16.h>
#include <math.h>
#include <stdint.h>

typedef __half fp16;

#define NTOK 8192
#define DIMC 1024
#define HIDC 2048
#define NRE  6
#define E2   (2ull<<20)

#define W1S_OFF 0ull
#define W3S_OFF (4ull<<20)
#define W2S_OFF (8ull<<20)
#define W1R_OFF (12ull<<20)
#define W3R_OFF (24ull<<20)
#define W2R_OFF (36ull<<20)
#define OUTW_OFF (48ull<<20)
#define WT_TOTAL (49ull<<20)

__device__ fp16 g_wt[WT_TOTAL];                      // weights fp16 [N][K]
__device__ fp16 g_x[(size_t)NTOK * DIMC];            // activations fp16
__device__ fp16 g_hall[8ull * NTOK * HIDC];          // h per expert slice
__device__ float g_comb[(size_t)NTOK * DIMC];        // shared-expert sum fp32
__device__ float g_bufA[(size_t)NTOK * DIMC];        // routed top-1 contribution
__device__ float g_bufB[(size_t)NTOK * DIMC];        // routed top-2 contribution
__device__ fp16 g_hc[(size_t)NTOK * DIMC];           // combined fp16 for out-proj
__device__ int   g_list[NRE * NTOK];
__device__ float g_lw[NRE * NTOK];
__device__ int   g_lrank[NRE * NTOK];
__device__ int   g_cnt[NRE];
__device__ int   g_top1[NRE];
__device__ float g_psum[NRE];

// ===================== helpers =====================
__device__ __forceinline__ uint32_t s2u(const void* p) {
    return (uint32_t)__cvta_generic_to_shared(p);
}
__device__ __forceinline__ void cpa(uint32_t s, const void* g) {
    asm volatile("cp.async.cg.shared.global [%0], [%1], 16;" :: "r"(s), "l"(g));
}
__device__ __forceinline__ void cpa_commit() {
    asm volatile("cp.async.commit_group;" ::: "memory");
}
__device__ __forceinline__ void ldsm4(uint32_t* r, uint32_t addr) {
    asm volatile("ldmatrix.sync.aligned.m8n8.x4.shared.b16 {%0,%1,%2,%3}, [%4];"
        : "=r"(r[0]), "=r"(r[1]), "=r"(r[2]), "=r"(r[3]) : "r"(addr));
}
__device__ __forceinline__ void mma16816(float* d, const uint32_t* a, const uint32_t* b) {
    asm volatile("mma.sync.aligned.m16n8k16.row.col.f32.f16.f16.f32 "
        "{%0,%1,%2,%3}, {%4,%5,%6,%7}, {%8,%9}, {%0,%1,%2,%3};"
        : "+f"(d[0]), "+f"(d[1]), "+f"(d[2]), "+f"(d[3])
        : "r"(a[0]), "r"(a[1]), "r"(a[2]), "r"(a[3]), "r"(b[0]), "r"(b[1]));
}

// ===================== small kernels =====================
__global__ void __launch_bounds__(256) convx_kernel(const float* __restrict__ x) {
    if (blockIdx.x == 0 && threadIdx.x < NRE) {
        g_cnt[threadIdx.x] = 0; g_top1[threadIdx.x] = 0; g_psum[threadIdx.x] = 0.f;
    }
    size_t i = ((size_t)blockIdx.x * 256 + threadIdx.x) * 2;
    float2 v = *(const float2*)(x + i);
    *(uint32_t*)(g_x + i) = *(uint32_t*)&__floats2half2_rn(v.x, v.y);
}

__global__ void __launch_bounds__(256) gate_kernel(const float* __restrict__ x,
                                                   const float* __restrict__ gw) {
    __shared__ float sgw[DIMC * NRE];
    int tid = threadIdx.x;
    for (int i = tid; i < DIMC * NRE; i += 256) sgw[i] = gw[i];
    __syncthreads();
    int warp = tid >> 5, lane = tid & 31;
    int token = blockIdx.x * 8 + warp;
    if (token >= NTOK) return;
    const float* xr = x + (size_t)token * DIMC;
    float acc[NRE] = {0.f, 0.f, 0.f, 0.f, 0.f, 0.f};
    for (int k = lane; k < DIMC; k += 32) {
        float xv = xr[k];
#pragma unroll
        for (int e = 0; e < NRE; e++) acc[e] += xv * sgw[k * NRE + e];
    }
#pragma unroll
    for (int e = 0; e < NRE; e++)
#pragma unroll
        for (int o = 16; o > 0; o >>= 1)
            acc[e] += __shfl_xor_sync(0xffffffffu, acc[e], o);
    if (lane == 0) {
        int i0 = 0; float v0 = acc[0];
        for (int e = 1; e < NRE; e++) if (acc[e] > v0) { v0 = acc[e]; i0 = e; }
        int i1 = -1; float v1 = -1e30f;
        for (int e = 0; e < NRE; e++) if (e != i0 && acc[e] > v1) { v1 = acc[e]; i1 = e; }
        float e2 = expf(v1 - v0);
        float inv = 1.0f / (1.0f + e2);
        float w0 = inv, w1 = e2 * inv;
        float p[NRE]; float s = 0.f;
        for (int e = 0; e < NRE; e++) { p[e] = expf(acc[e] - v0); s += p[e]; }
        float is = 1.0f / s;
        for (int e = 0; e < NRE; e++) atomicAdd(&g_psum[e], p[e] * is);
        atomicAdd(&g_top1[i0], 1);
        int p0 = atomicAdd(&g_cnt[i0], 1);
        g_list[i0 * NTOK + p0] = token; g_lw[i0 * NTOK + p0] = w0; g_lrank[i0 * NTOK + p0] = 0;
        int p1 = atomicAdd(&g_cnt[i1], 1);
        g_list[i1 * NTOK + p1] = token; g_lw[i1 * NTOK + p1] = w1; g_lrank[i1 * NTOK + p1] = 1;
    }
}

__global__ void aux_kernel(float* dst) {
    float a = 0.f;
    for (int e = 0; e < NRE; e++) {
        float f = (float)g_top1[e] / (float)NTOK;
        float pm = g_psum[e] / (float)NTOK;
        a += f * pm;
    }
    *dst = 0.01f * (float)NRE * a;
}

__global__ void __launch_bounds__(256) convt_all_kernel(
    const float* w1_s, const float* w3_s, const float* w2_s,
    const float* w1_r, const float* w3_r, const float* w2_r,
    const float* out_w)
{
    __shared__ float t[32][33];
    int z = blockIdx.z;
    int K, N; const float* src; fp16* dst;
    if (z < 16) {
        K = DIMC; N = HIDC;
        if (z < 2)       { src = w1_s + (size_t)z * E2;        dst = g_wt + W1S_OFF + (size_t)z * E2; }
        else if (z < 4)  { int e = z - 2;  src = w3_s + (size_t)e * E2; dst = g_wt + W3S_OFF + (size_t)e * E2; }
        else if (z < 10) { int e = z - 4;  src = w1_r + (size_t)e * E2; dst = g_wt + W1R_OFF + (size_t)e * E2; }
        else             { int e = z - 10; src = w3_r + (size_t)e * E2; dst = g_wt + W3R_OFF + (size_t)e * E2; }
    } else if (z < 24) {
        K = HIDC; N = DIMC;
        if (z < 18) { int e = z - 16; src = w2_s + (size_t)e * E2; dst = g_wt + W2S_OFF + (size_t)e * E2; }
        else        { int e = z - 18; src = w2_r + (size_t)e * E2; dst = g_wt + W2R_OFF + (size_t)e * E2; }
    } else {
        K = DIMC; N = DIMC; src = out_w; dst = g_wt + OUTW_OFF;
    }
    int k0 = blockIdx.y * 32, n0 = blockIdx.x * 32;
    if (k0 >= K || n0 >= N) return;
    int tx = threadIdx.x & 31, ty = threadIdx.x >> 5;
#pragma unroll
    for (int i = 0; i < 4; i++)
        t[ty + i * 8][tx] = src[(size_t)(k0 + ty + i * 8) * N + n0 + tx];
    __syncthreads();
#pragma unroll
    for (int i = 0; i < 4; i++)
        dst[(size_t)(n0 + ty + i * 8) * K + k0 + tx] = __float2half_rn(t[tx][ty + i * 8]);
}

__global__ void __launch_bounds__(256) convc3_kernel() {
    size_t i = ((size_t)blockIdx.x * 256 + threadIdx.x) * 2;
    float2 a = *(const float2*)(g_comb + i);
    float2 b = *(const float2*)(g_bufA + i);
    float2 c = *(const float2*)(g_bufB + i);
    *(uint32_t*)(g_hc + i) = *(uint32_t*)&__floats2half2_rn(a.x + b.x + c.x, a.y + b.y + c.y);
}

// ===================== mm1_all: all 8 pass-1 GEMMs, occ 2 =====================
// tile 128M x 64N dual(B1,B3), chunk K=64, 3-stage, warps 4(M)x2(N), warp 32x32
#define P1_PITCH 144
#define P1_A  0
#define P1_B1 18432
#define P1_B3 27648
#define P1_STG 36864
#define P1_SIDX (3*P1_STG)           // 110592
#define P1_SMEM (P1_SIDX + 512)      // 111104

__global__ void __launch_bounds__(256, 2) mm1_all_kernel()
{
    extern __shared__ char smem[];
    const int z = blockIdx.z;
    const fp16* W1; const fp16* W3;
    const int* gidx; const float* gscale; int M;
    if (z < 2) {
        W1 = g_wt + W1S_OFF + (size_t)z * E2;
        W3 = g_wt + W3S_OFF + (size_t)z * E2;
        gidx = nullptr; gscale = nullptr; M = NTOK;
    } else {
        int e = z - 2;
        W1 = g_wt + W1R_OFF + (size_t)e * E2;
        W3 = g_wt + W3R_OFF + (size_t)e * E2;
        gidx = g_list + e * NTOK; gscale = g_lw + e * NTOK; M = g_cnt[e];
    }
    fp16* hout = g_hall + (size_t)z * NTOK * HIDC;

    const int mBase = blockIdx.y * 128;
    if (mBase >= M) return;
    const int nBase = blockIdx.x * 64;
    const uint32_t sb = s2u(smem);
    const int tid = threadIdx.x;

    int* sIdx = (int*)(smem + P1_SIDX);
    if (tid < 128) {
        int r = mBase + tid;
        sIdx[tid] = (r < M) ? (gidx ? gidx[r] : r) : 0;
    }
    __syncthreads();

    auto load = [&](int buf, int k0) {
        uint32_t su = sb + buf * P1_STG;
#pragma unroll
        for (int it = 0; it < 4; it++) {
            int idx = tid + it * 256;
            int row = idx >> 3, seg = idx & 7;
            uint32_t so = row * P1_PITCH + seg * 16;
            cpa(su + P1_A + so, g_x + (size_t)sIdx[row] * DIMC + k0 + seg * 8);
        }
#pragma unroll
        for (int it = 0; it < 2; it++) {
            int idx = tid + it * 256;
            int row = idx >> 3, seg = idx & 7;     // row in [0,64)
            uint32_t so = row * P1_PITCH + seg * 16;
            size_t gw = (size_t)(nBase + row) * DIMC + k0 + seg * 8;
            cpa(su + P1_B1 + so, W1 + gw);
            cpa(su + P1_B3 + so, W3 + gw);
        }
        cpa_commit();
    };

    const int lane = tid & 31, wid = tid >> 5;
    const int wm = (wid & 3) * 32;
    const int wn = (wid >> 2) * 32;
    const int arow = (lane & 7) + ((lane >> 3) & 1) * 8;
    const int akh  = (lane >> 4) & 1;
    const int brow = (lane & 7) + ((lane >> 4) & 1) * 8;
    const int bkh  = (lane >> 3) & 1;

    float acc1[2][4][4], acc3[2][4][4];
#pragma unroll
    for (int i = 0; i < 2; i++)
#pragma unroll
        for (int j = 0; j < 4; j++)
#pragma unroll
            for (int k = 0; k < 4; k++) { acc1[i][j][k] = 0.f; acc3[i][j][k] = 0.f; }

    const int nc = DIMC / 64;   // 16
    load(0, 0);
    load(1, 64);
    for (int c = 0; c < nc; c++) {
        if (c + 1 < nc) asm volatile("cp.async.wait_group 1;" ::: "memory");
        else            asm volatile("cp.async.wait_group 0;" ::: "memory");
        __syncthreads();
        if (c + 2 < nc) load((c + 2) % 3, (c + 2) * 64);
        uint32_t su = sb + (c % 3) * P1_STG;
#pragma unroll
        for (int s = 0; s < 4; s++) {
            uint32_t a[2][4];
#pragma unroll
            for (int mi = 0; mi < 2; mi++) {
                uint32_t ao = (uint32_t)(wm + mi * 16 + arow) * P1_PITCH + s * 32 + akh * 16;
                ldsm4(a[mi], su + P1_A + ao);
            }
#pragma unroll
            for (int np = 0; np < 2; np++) {
                uint32_t b1[4], b3[4];
                uint32_t bo = (uint32_t)(wn + np * 16 + brow) * P1_PITCH + s * 32 + bkh * 16;
                ldsm4(b1, su + P1_B1 + bo);
                ldsm4(b3, su + P1_B3 + bo);
#pragma unroll
                for (int mi = 0; mi < 2; mi++)
#pragma unroll
                    for (int h = 0; h < 2; h++) {
                        int nt = np * 2 + h;
                        mma16816(acc1[mi][nt], a[mi], &b1[h * 2]);
                        mma16816(acc3[mi][nt], a[mi], &b3[h * 2]);
                    }
            }
        }
    }

#pragma unroll
    for (int mi = 0; mi < 2; mi++)
#pragma unroll
        for (int half = 0; half < 2; half++) {
            int slot = mBase + wm + mi * 16 + (lane >> 2) + half * 8;
            if (slot < M) {
                float sc = gscale ? gscale[slot] : 1.0f;
                size_t rb = (size_t)slot * HIDC + nBase + wn + (lane & 3) * 2;
#pragma unroll
                for (int nt = 0; nt < 4; nt++) {
                    float u0 = acc1[mi][nt][half * 2 + 0];
                    float u1 = acc1[mi][nt][half * 2 + 1];
                    float v0 = acc3[mi][nt][half * 2 + 0];
                    float v1 = acc3[mi][nt][half * 2 + 1];
                    float h0 = u0 / (1.f + __expf(-u0)) * v0 * sc;
                    float h1 = u1 / (1.f + __expf(-u1)) * v1 * sc;
                    __half2 hp = __floats2half2_rn(h0, h1);
                    *(uint32_t*)(hout + rb + nt * 8) = *(uint32_t*)&hp;
                }
            }
        }
}

// ===================== mm2 core (128x128, chunk 64, 3-stage, occ 2) =====================
#define P2_A 0
#define P2_B 18432
#define P2_STG 36864
#define P2_SMEM (3*P2_STG)   // 110592

__global__ void __launch_bounds__(256, 2) mm2sh_kernel()
{
    extern __shared__ char smem[];
    const int mBase = blockIdx.y * 128;
    const int nBase = blockIdx.x * 128;
    const uint32_t sb = s2u(smem);
    const int tid = threadIdx.x;

    const int lane = tid & 31, wid = tid >> 5;
    const int wm = (wid & 1) * 64;
    const int wn = (wid >> 1) * 32;
    const int arow = (lane & 7) + ((lane >> 3) & 1) * 8;
    const int akh  = (lane >> 4) & 1;
    const int brow = (lane & 7) + ((lane >> 4) & 1) * 8;
    const int bkh  = (lane >> 3) & 1;

    float acc[4][4][4];
#pragma unroll
    for (int i = 0; i < 4; i++)
#pragma unroll
        for (int j = 0; j < 4; j++)
#pragma unroll
            for (int k = 0; k < 4; k++) acc[i][j][k] = 0.f;

    for (int ss = 0; ss < 2; ss++) {
        const fp16* A = g_hall + (size_t)ss * NTOK * HIDC;
        const fp16* B = g_wt + W2S_OFF + (size_t)ss * E2;
        auto load = [&](int buf, int k0) {
            uint32_t su = sb + buf * P2_STG;
#pragma unroll
            for (int it = 0; it < 4; it++) {
                int idx = tid + it * 256;
                int row = idx >> 3, seg = idx & 7;
                uint32_t so = row * 144 + seg * 16;
                cpa(su + P2_A + so, A + (size_t)(mBase + row) * HIDC + k0 + seg * 8);
                cpa(su + P2_B + so, B + (size_t)(nBase + row) * HIDC + k0 + seg * 8);
            }
            cpa_commit();
        };
        const int nc = HIDC / 64;
        load(0, 0);
        load(1, 64);
        for (int c = 0; c < nc; c++) {
            if (c + 1 < nc) asm volatile("cp.async.wait_group 1;" ::: "memory");
            else            asm volatile("cp.async.wait_group 0;" ::: "memory");
            __syncthreads();
            if (c + 2 < nc) load((c + 2) % 3, (c + 2) * 64);
            uint32_t su = sb + (c % 3) * P2_STG;
#pragma unroll
            for (int s = 0; s < 4; s++) {
                uint32_t a[4][4];
#pragma unroll
                for (int mi = 0; mi < 4; mi++) {
                    uint32_t ao = (uint32_t)(wm + mi * 16 + arow) * 144 + s * 32 + akh * 16;
                    ldsm4(a[mi], su + P2_A + ao);
                }
#pragma unroll
                for (int np = 0; np < 2; np++) {
                    uint32_t b[4];
                    uint32_t bo = (uint32_t)(wn + np * 16 + brow) * 144 + s * 32 + bkh * 16;
                    ldsm4(b, su + P2_B + bo);
#pragma unroll
                    for (int mi = 0; mi < 4; mi++)
#pragma unroll
                        for (int h = 0; h < 2; h++)
                            mma16816(acc[mi][np * 2 + h], a[mi], &b[h * 2]);
                }
            }
        }
        __syncthreads();
    }

#pragma unroll
    for (int mi = 0; mi < 4; mi++)
#pragma unroll
        for (int half = 0; half < 2; half++) {
            int t = mBase + wm + mi * 16 + (lane >> 2) + half * 8;
            float* cp = g_comb + (size_t)t * DIMC + nBase + wn + (lane & 3) * 2;
#pragma unroll
            for (int nt = 0; nt < 4; nt++)
                *(float2*)(cp + nt * 8) = make_float2(acc[mi][nt][half * 2 + 0],
                                                      acc[mi][nt][half * 2 + 1]);
        }
}

__global__ void __launch_bounds__(256, 2) mm2rt_kernel()
{
    extern __shared__ char smem[];
    const int e = blockIdx.z;
    const int M = g_cnt[e];
    const int mBase = blockIdx.y * 128;
    if (mBase >= M) return;
    const int nBase = blockIdx.x * 128;
    const fp16* A = g_hall + (size_t)(2 + e) * NTOK * HIDC;
    const fp16* B = g_wt + W2R_OFF + (size_t)e * E2;
    const uint32_t sb = s2u(smem);
    const int tid = threadIdx.x;

    auto load = [&](int buf, int k0) {
        uint32_t su = sb + buf * P2_STG;
#pragma unroll
        for (int it = 0; it < 4; it++) {
            int idx = tid + it * 256;
            int row = idx >> 3, seg = idx & 7;
            uint32_t so = row * 144 + seg * 16;
            int ar = mBase + row; if (ar >= M) ar = mBase;
            cpa(su + P2_A + so, A + (size_t)ar * HIDC + k0 + seg * 8);
            cpa(su + P2_B + so, B + (size_t)(nBase + row) * HIDC + k0 + seg * 8);
        }
        cpa_commit();
    };

    const int lane = tid & 31, wid = tid >> 5;
    const int wm = (wid & 1) * 64;
    const int wn = (wid >> 1) * 32;
    const int arow = (lane & 7) + ((lane >> 3) & 1) * 8;
    const int akh  = (lane >> 4) & 1;
    const int brow = (lane & 7) + ((lane >> 4) & 1) * 8;
    const int bkh  = (lane >> 3) & 1;

    float acc[4][4][4];
#pragma unroll
    for (int i = 0; i < 4; i++)
#pragma unroll
        for (int j = 0; j < 4; j++)
#pragma unroll
            for (int k = 0; k < 4; k++) acc[i][j][k] = 0.f;

    const int nc = HIDC / 64;
    load(0, 0);
    load(1, 64);
    for (int c = 0; c < nc; c++) {
        if (c + 1 < nc) asm volatile("cp.async.wait_group 1;" ::: "memory");
        else            asm volatile("cp.async.wait_group 0;" ::: "memory");
        __syncthreads();
        if (c + 2 < nc) load((c + 2) % 3, (c + 2) * 64);
        uint32_t su = sb + (c % 3) * P2_STG;
#pragma unroll
        for (int s = 0; s < 4; s++) {
            uint32_t a[4][4];
#pragma unroll
            for (int mi = 0; mi < 4; mi++) {
                uint32_t ao = (uint32_t)(wm + mi * 16 + arow) * 144 + s * 32 + akh * 16;
                ldsm4(a[mi], su + P2_A + ao);
            }
#pragma unroll
            for (int np = 0; np < 2; np++) {
                uint32_t b[4];
                uint32_t bo = (uint32_t)(wn + np * 16 + brow) * 144 + s * 32 + bkh * 16;
                ldsm4(b, su + P2_B + bo);
#pragma unroll
                for (int mi = 0; mi < 4; mi++)
#pragma unroll
                    for (int h = 0; h < 2; h++)
                        mma16816(acc[mi][np * 2 + h], a[mi], &b[h * 2]);
            }
        }
    }

#pragma unroll
    for (int mi = 0; mi < 4; mi++)
#pragma unroll
        for (int half = 0; half < 2; half++) {
            int slot = mBase + wm + mi * 16 + (lane >> 2) + half * 8;
            if (slot < M) {
                int t = g_list[e * NTOK + slot];
                int rk = g_lrank[e * NTOK + slot];
                float* base = rk ? g_bufB : g_bufA;
                float* cp = base + (size_t)t * DIMC + nBase + wn + (lane & 3) * 2;
#pragma unroll
                for (int nt = 0; nt < 4; nt++)
                    *(float2*)(cp + nt * 8) = make_float2(acc[mi][nt][half * 2 + 0],
                                                          acc[mi][nt][half * 2 + 1]);
            }
        }
}

__global__ void __launch_bounds__(256, 2) outproj_kernel(float* __restrict__ out)
{
    extern __shared__ char smem[];
    const int mBase = blockIdx.y * 128;
    const int nBase = blockIdx.x * 128;
    const fp16* B = g_wt + OUTW_OFF;
    const uint32_t sb = s2u(smem);
    const int tid = threadIdx.x;

    auto load = [&](int buf, int k0) {
        uint32_t su = sb + buf * P2_STG;
#pragma unroll
        for (int it = 0; it < 4; it++) {
            int idx = tid + it * 256;
            int row = idx >> 3, seg = idx & 7;
            uint32_t so = row * 144 + seg * 16;
            cpa(su + P2_A + so, g_hc + (size_t)(mBase + row) * DIMC + k0 + seg * 8);
            cpa(su + P2_B + so, B + (size_t)(nBase + row) * DIMC + k0 + seg * 8);
        }
        cpa_commit();
    };

    const int lane = tid & 31, wid = tid >> 5;
    const int wm = (wid & 1) * 64;
    const int wn = (wid >> 1) * 32;
    const int arow = (lane & 7) + ((lane >> 3) & 1) * 8;
    const int akh  = (lane >> 4) & 1;
    const int brow = (lane & 7) + ((lane >> 4) & 1) * 8;
    const int bkh  = (lane >> 3) & 1;

    float acc[4][4][4];
#pragma unroll
    for (int i = 0; i < 4; i++)
#pragma unroll
        for (int j = 0; j < 4; j++)
#pragma unroll
            for (int k = 0; k < 4; k++) acc[i][j][k] = 0.f;

    const int nc = DIMC / 64;
    load(0, 0);
    load(1, 64);
    for (int c = 0; c < nc; c++) {
        if (c + 1 < nc) asm volatile("cp.async.wait_group 1;" ::: "memory");
        else            asm volatile("cp.async.wait_group 0;" ::: "memory");
        __syncthreads();
        if (c + 2 < nc) load((c + 2) % 3, (c + 2) * 64);
        uint32_t su = sb + (c % 3) * P2_STG;
#pragma unroll
        for (int s = 0; s < 4; s++) {
            uint32_t a[4][4];
#pragma unroll
            for (int mi = 0; mi < 4; mi++) {
                uint32_t ao = (uint32_t)(wm + mi * 16 + arow) * 144 + s * 32 + akh * 16;
                ldsm4(a[mi], su + P2_A + ao);
            }
#pragma unroll
            for (int np = 0; np < 2; np++) {
                uint32_t b[4];
                uint32_t bo = (uint32_t)(wn + np * 16 + brow) * 144 + s * 32 + bkh * 16;
                ldsm4(b, su + P2_B + bo);
#pragma unroll
                for (int mi = 0; mi < 4; mi++)
#pragma unroll
                    for (int h = 0; h < 2; h++)
                        mma16816(acc[mi][np * 2 + h], a[mi], &b[h * 2]);
            }
        }
    }

#pragma unroll
    for (int mi = 0; mi < 4; mi++)
#pragma unroll
        for (int half = 0; half < 2; half++) {
            int t = mBase + wm + mi * 16 + (lane >> 2) + half * 8;
            float* cp = out + (size_t)t * DIMC + nBase + wn + (lane & 3) * 2;
#pragma unroll
            for (int nt = 0; nt < 4; nt++)
                *(float2*)(cp + nt * 8) = make_float2(acc[mi][nt][half * 2 + 0],
                                                      acc[mi][nt][half * 2 + 1]);
        }
}

// ===================== host =====================
extern "C" void kernel_launch(void* const* d_in, const int* in_sizes, int n_in,
                              void* d_out, int out_size)
{
    const float* x      = (const float*)d_in[0];
    const float* w1_s   = (const float*)d_in[1];
    const float* w2_s   = (const float*)d_in[2];
    const float* w3_s   = (const float*)d_in[3];
    const float* w1_r   = (const float*)d_in[4];
    const float* w2_r   = (const float*)d_in[5];
    const float* w3_r   = (const float*)d_in[6];
    const float* gate_w = (const float*)d_in[7];
    const float* out_w  = (const float*)d_in[8];
    float* out = (float*)d_out;

    cudaFuncSetAttribute(mm1_all_kernel, cudaFuncAttributeMaxDynamicSharedMemorySize, P1_SMEM);
    cudaFuncSetAttribute(mm2sh_kernel,  cudaFuncAttributeMaxDynamicSharedMemorySize, P2_SMEM);
    cudaFuncSetAttribute(mm2rt_kernel,  cudaFuncAttributeMaxDynamicSharedMemorySize, P2_SMEM);
    cudaFuncSetAttribute(outproj_kernel, cudaFuncAttributeMaxDynamicSharedMemorySize, P2_SMEM);

    // 1: activations (+counter zeroing)
    convx_kernel<<<(NTOK * DIMC) / 512, 256>>>(x);
    // 2: gate
    gate_kernel<<<NTOK / 8, 256>>>(x, gate_w);
    // 3: all 25 weight matrices
    {
        dim3 g(64, 64, 25);
        convt_all_kernel<<<g, 256>>>(w1_s, w3_s, w2_s, w1_r, w3_r, w2_r, out_w);
    }
    // 4: all 8 pass-1 GEMMs (profiled by ncu)
    {
        dim3 g(HIDC / 64, NTOK / 128, 8);
        mm1_all_kernel<<<g, 256, P1_SMEM>>>();
    }
    // 5: shared-expert pass-2 (both experts fused)
    {
        dim3 g(DIMC / 128, NTOK / 128);
        mm2sh_kernel<<<g, 256, P2_SMEM>>>();
    }
    // 6: all 6 routed pass-2 GEMMs
    {
        dim3 g(DIMC / 128, NTOK / 128, NRE);
        mm2rt_kernel<<<g, 256, P2_SMEM>>>();
    }
    // 7: combine
    convc3_kernel<<<(NTOK * DIMC) / 512, 256>>>();
    // 8: out projection
    {
        dim3 g(DIMC / 128, NTOK / 128);
        outproj_kernel<<<g, 256, P2_SMEM>>>(out);
    }
    // 9: aux loss
    if (out_size > NTOK * DIMC)
        aux_kernel<<<1, 1>>>(out + (out_size - 1));
}

// round 11
// speedup vs baseline: 8.0709x; 1.0023x over previous
#include <cuda_runtime.h>
#include <cuda_fp16.h>
#include <math.h>
#include <stdint.h>

typedef __half fp16;

#define NTOK 8192
#define DIMC 1024
#define HIDC 2048
#define NRE  6
#define E2   (2ull<<20)

#define W1S_OFF 0ull
#define W3S_OFF (4ull<<20)
#define W2S_OFF (8ull<<20)
#define W1R_OFF (12ull<<20)
#define W3R_OFF (24ull<<20)
#define W2R_OFF (36ull<<20)
#define OUTW_OFF (48ull<<20)
#define WT_TOTAL (49ull<<20)

__device__ fp16 g_wt[WT_TOTAL];                      // weights fp16 [N][K]
__device__ fp16 g_x[(size_t)NTOK * DIMC];            // activations fp16
__device__ fp16 g_hall[8ull * NTOK * HIDC];          // h per expert slice
__device__ float g_comb[(size_t)NTOK * DIMC];        // shared expert 0
__device__ float g_bufC[(size_t)NTOK * DIMC];        // shared expert 1
__device__ float g_bufA[(size_t)NTOK * DIMC];        // routed top-1
__device__ float g_bufB[(size_t)NTOK * DIMC];        // routed top-2
__device__ fp16 g_hc[(size_t)NTOK * DIMC];           // combined fp16
__device__ int   g_list[NRE * NTOK];
__device__ float g_lw[NRE * NTOK];
__device__ int   g_lrank[NRE * NTOK];
__device__ int   g_cnt[NRE];
__device__ int   g_top1[NRE];
__device__ float g_psum[NRE];

// ===================== helpers =====================
__device__ __forceinline__ uint32_t s2u(const void* p) {
    return (uint32_t)__cvta_generic_to_shared(p);
}
__device__ __forceinline__ void cpa(uint32_t s, const void* g) {
    asm volatile("cp.async.cg.shared.global [%0], [%1], 16;" :: "r"(s), "l"(g));
}
__device__ __forceinline__ void cpa_commit() {
    asm volatile("cp.async.commit_group;" ::: "memory");
}
__device__ __forceinline__ void ldsm4(uint32_t* r, uint32_t addr) {
    asm volatile("ldmatrix.sync.aligned.m8n8.x4.shared.b16 {%0,%1,%2,%3}, [%4];"
        : "=r"(r[0]), "=r"(r[1]), "=r"(r[2]), "=r"(r[3]) : "r"(addr));
}
__device__ __forceinline__ void mma16816(float* d, const uint32_t* a, const uint32_t* b) {
    asm volatile("mma.sync.aligned.m16n8k16.row.col.f32.f16.f16.f32 "
        "{%0,%1,%2,%3}, {%4,%5,%6,%7}, {%8,%9}, {%0,%1,%2,%3};"
        : "+f"(d[0]), "+f"(d[1]), "+f"(d[2]), "+f"(d[3])
        : "r"(a[0]), "r"(a[1]), "r"(a[2]), "r"(a[3]), "r"(b[0]), "r"(b[1]));
}

// ===================== small kernels =====================
__global__ void __launch_bounds__(256) convx_kernel(const float* __restrict__ x) {
    if (blockIdx.x == 0 && threadIdx.x < NRE) {
        g_cnt[threadIdx.x] = 0; g_top1[threadIdx.x] = 0; g_psum[threadIdx.x] = 0.f;
    }
    size_t i = ((size_t)blockIdx.x * 256 + threadIdx.x) * 2;
    float2 v = *(const float2*)(x + i);
    *(uint32_t*)(g_x + i) = *(uint32_t*)&__floats2half2_rn(v.x, v.y);
}

__global__ void __launch_bounds__(256) gate_kernel(const float* __restrict__ x,
                                                   const float* __restrict__ gw) {
    __shared__ float sgw[DIMC * NRE];
    int tid = threadIdx.x;
    for (int i = tid; i < DIMC * NRE; i += 256) sgw[i] = gw[i];
    __syncthreads();
    int warp = tid >> 5, lane = tid & 31;
    int token = blockIdx.x * 8 + warp;
    if (token >= NTOK) return;
    const float* xr = x + (size_t)token * DIMC;
    float acc[NRE] = {0.f, 0.f, 0.f, 0.f, 0.f, 0.f};
    for (int k = lane; k < DIMC; k += 32) {
        float xv = xr[k];
#pragma unroll
        for (int e = 0; e < NRE; e++) acc[e] += xv * sgw[k * NRE + e];
    }
#pragma unroll
    for (int e = 0; e < NRE; e++)
#pragma unroll
        for (int o = 16; o > 0; o >>= 1)
            acc[e] += __shfl_xor_sync(0xffffffffu, acc[e], o);
    if (lane == 0) {
        int i0 = 0; float v0 = acc[0];
        for (int e = 1; e < NRE; e++) if (acc[e] > v0) { v0 = acc[e]; i0 = e; }
        int i1 = -1; float v1 = -1e30f;
        for (int e = 0; e < NRE; e++) if (e != i0 && acc[e] > v1) { v1 = acc[e]; i1 = e; }
        float e2 = expf(v1 - v0);
        float inv = 1.0f / (1.0f + e2);
        float w0 = inv, w1 = e2 * inv;
        float p[NRE]; float s = 0.f;
        for (int e = 0; e < NRE; e++) { p[e] = expf(acc[e] - v0); s += p[e]; }
        float is = 1.0f / s;
        for (int e = 0; e < NRE; e++) atomicAdd(&g_psum[e], p[e] * is);
        atomicAdd(&g_top1[i0], 1);
        int p0 = atomicAdd(&g_cnt[i0], 1);
        g_list[i0 * NTOK + p0] = token; g_lw[i0 * NTOK + p0] = w0; g_lrank[i0 * NTOK + p0] = 0;
        int p1 = atomicAdd(&g_cnt[i1], 1);
        g_list[i1 * NTOK + p1] = token; g_lw[i1 * NTOK + p1] = w1; g_lrank[i1 * NTOK + p1] = 1;
    }
}

__global__ void __launch_bounds__(256) convt_all_kernel(
    const float* w1_s, const float* w3_s, const float* w2_s,
    const float* w1_r, const float* w3_r, const float* w2_r,
    const float* out_w)
{
    __shared__ float t[32][33];
    int z = blockIdx.z;
    int K, N; const float* src; fp16* dst;
    if (z < 16) {
        K = DIMC; N = HIDC;
        if (z < 2)       { src = w1_s + (size_t)z * E2;        dst = g_wt + W1S_OFF + (size_t)z * E2; }
        else if (z < 4)  { int e = z - 2;  src = w3_s + (size_t)e * E2; dst = g_wt + W3S_OFF + (size_t)e * E2; }
        else if (z < 10) { int e = z - 4;  src = w1_r + (size_t)e * E2; dst = g_wt + W1R_OFF + (size_t)e * E2; }
        else             { int e = z - 10; src = w3_r + (size_t)e * E2; dst = g_wt + W3R_OFF + (size_t)e * E2; }
    } else if (z < 24) {
        K = HIDC; N = DIMC;
        if (z < 18) { int e = z - 16; src = w2_s + (size_t)e * E2; dst = g_wt + W2S_OFF + (size_t)e * E2; }
        else        { int e = z - 18; src = w2_r + (size_t)e * E2; dst = g_wt + W2R_OFF + (size_t)e * E2; }
    } else {
        K = DIMC; N = DIMC; src = out_w; dst = g_wt + OUTW_OFF;
    }
    int k0 = blockIdx.y * 32, n0 = blockIdx.x * 32;
    if (k0 >= K || n0 >= N) return;
    int tx = threadIdx.x & 31, ty = threadIdx.x >> 5;
#pragma unroll
    for (int i = 0; i < 4; i++)
        t[ty + i * 8][tx] = src[(size_t)(k0 + ty + i * 8) * N + n0 + tx];
    __syncthreads();
#pragma unroll
    for (int i = 0; i < 4; i++)
        dst[(size_t)(n0 + ty + i * 8) * K + k0 + tx] = __float2half_rn(t[tx][ty + i * 8]);
}

// comb + bufC + bufA + bufB -> fp16 ; block 0 thread 0 also writes aux loss
__global__ void __launch_bounds__(256) convc4_kernel(float* auxDst) {
    if (auxDst && blockIdx.x == 0 && threadIdx.x == 0) {
        float a = 0.f;
        for (int e = 0; e < NRE; e++) {
            float f = (float)g_top1[e] / (float)NTOK;
            float pm = g_psum[e] / (float)NTOK;
            a += f * pm;
        }
        *auxDst = 0.01f * (float)NRE * a;
    }
    size_t i = ((size_t)blockIdx.x * 256 + threadIdx.x) * 2;
    float2 a = *(const float2*)(g_comb + i);
    float2 d = *(const float2*)(g_bufC + i);
    float2 b = *(const float2*)(g_bufA + i);
    float2 c = *(const float2*)(g_bufB + i);
    *(uint32_t*)(g_hc + i) = *(uint32_t*)&__floats2half2_rn(a.x + d.x + b.x + c.x,
                                                            a.y + d.y + b.y + c.y);
}

// ===================== mm1_all: all 8 pass-1 GEMMs, occ 2 =====================
#define P1_PITCH 144
#define P1_A  0
#define P1_B1 18432
#define P1_B3 27648
#define P1_STG 36864
#define P1_SIDX (3*P1_STG)           // 110592
#define P1_SMEM (P1_SIDX + 512)      // 111104

__global__ void __launch_bounds__(256, 2) mm1_all_kernel()
{
    extern __shared__ char smem[];
    const int z = blockIdx.z;
    const fp16* W1; const fp16* W3;
    const int* gidx; const float* gscale; int M;
    if (z < 2) {
        W1 = g_wt + W1S_OFF + (size_t)z * E2;
        W3 = g_wt + W3S_OFF + (size_t)z * E2;
        gidx = nullptr; gscale = nullptr; M = NTOK;
    } else {
        int e = z - 2;
        W1 = g_wt + W1R_OFF + (size_t)e * E2;
        W3 = g_wt + W3R_OFF + (size_t)e * E2;
        gidx = g_list + e * NTOK; gscale = g_lw + e * NTOK; M = g_cnt[e];
    }
    fp16* hout = g_hall + (size_t)z * NTOK * HIDC;

    const int mBase = blockIdx.y * 128;
    if (mBase >= M) return;
    const int nBase = blockIdx.x * 64;
    const uint32_t sb = s2u(smem);
    const int tid = threadIdx.x;

    int* sIdx = (int*)(smem + P1_SIDX);
    if (tid < 128) {
        int r = mBase + tid;
        sIdx[tid] = (r < M) ? (gidx ? gidx[r] : r) : 0;
    }
    __syncthreads();

    // preload gather rows for this thread's 4 A-load slots
    int aRow[4];
#pragma unroll
    for (int it = 0; it < 4; it++) aRow[it] = sIdx[(tid + it * 256) >> 3];

    auto load = [&](int buf, int k0) {
        uint32_t su = sb + buf * P1_STG;
#pragma unroll
        for (int it = 0; it < 4; it++) {
            int idx = tid + it * 256;
            int row = idx >> 3, seg = idx & 7;
            uint32_t so = row * P1_PITCH + seg * 16;
            cpa(su + P1_A + so, g_x + (size_t)aRow[it] * DIMC + k0 + seg * 8);
        }
#pragma unroll
        for (int it = 0; it < 2; it++) {
            int idx = tid + it * 256;
            int row = idx >> 3, seg = idx & 7;
            uint32_t so = row * P1_PITCH + seg * 16;
            size_t gw = (size_t)(nBase + row) * DIMC + k0 + seg * 8;
            cpa(su + P1_B1 + so, W1 + gw);
            cpa(su + P1_B3 + so, W3 + gw);
        }
        cpa_commit();
    };

    const int lane = tid & 31, wid = tid >> 5;
    const int wm = (wid & 3) * 32;
    const int wn = (wid >> 2) * 32;
    const int arow = (lane & 7) + ((lane >> 3) & 1) * 8;
    const int akh  = (lane >> 4) & 1;
    const int brow = (lane & 7) + ((lane >> 4) & 1) * 8;
    const int bkh  = (lane >> 3) & 1;

    float acc1[2][4][4], acc3[2][4][4];
#pragma unroll
    for (int i = 0; i < 2; i++)
#pragma unroll
        for (int j = 0; j < 4; j++)
#pragma unroll
            for (int k = 0; k < 4; k++) { acc1[i][j][k] = 0.f; acc3[i][j][k] = 0.f; }

    const int nc = DIMC / 64;   // 16
    load(0, 0);
    load(1, 64);
    for (int c = 0; c < nc; c++) {
        if (c + 1 < nc) asm volatile("cp.async.wait_group 1;" ::: "memory");
        else            asm volatile("cp.async.wait_group 0;" ::: "memory");
        __syncthreads();
        if (c + 2 < nc) load((c + 2) % 3, (c + 2) * 64);
        uint32_t su = sb + (c % 3) * P1_STG;
#pragma unroll
        for (int s = 0; s < 4; s++) {
            uint32_t a[2][4];
#pragma unroll
            for (int mi = 0; mi < 2; mi++) {
                uint32_t ao = (uint32_t)(wm + mi * 16 + arow) * P1_PITCH + s * 32 + akh * 16;
                ldsm4(a[mi], su + P1_A + ao);
            }
#pragma unroll
            for (int np = 0; np < 2; np++) {
                uint32_t b1[4], b3[4];
                uint32_t bo = (uint32_t)(wn + np * 16 + brow) * P1_PITCH + s * 32 + bkh * 16;
                ldsm4(b1, su + P1_B1 + bo);
                ldsm4(b3, su + P1_B3 + bo);
#pragma unroll
                for (int mi = 0; mi < 2; mi++)
#pragma unroll
                    for (int h = 0; h < 2; h++) {
                        int nt = np * 2 + h;
                        mma16816(acc1[mi][nt], a[mi], &b1[h * 2]);
                        mma16816(acc3[mi][nt], a[mi], &b3[h * 2]);
                    }
            }
        }
    }

#pragma unroll
    for (int mi = 0; mi < 2; mi++)
#pragma unroll
        for (int half = 0; half < 2; half++) {
            int slot = mBase + wm + mi * 16 + (lane >> 2) + half * 8;
            if (slot < M) {
                float sc = gscale ? gscale[slot] : 1.0f;
                size_t rb = (size_t)slot * HIDC + nBase + wn + (lane & 3) * 2;
#pragma unroll
                for (int nt = 0; nt < 4; nt++) {
                    float u0 = acc1[mi][nt][half * 2 + 0];
                    float u1 = acc1[mi][nt][half * 2 + 1];
                    float v0 = acc3[mi][nt][half * 2 + 0];
                    float v1 = acc3[mi][nt][half * 2 + 1];
                    float h0 = u0 / (1.f + __expf(-u0)) * v0 * sc;
                    float h1 = u1 / (1.f + __expf(-u1)) * v1 * sc;
                    __half2 hp = __floats2half2_rn(h0, h1);
                    *(uint32_t*)(hout + rb + nt * 8) = *(uint32_t*)&hp;
                }
            }
        }
}

// ===================== mm2_all: all 8 pass-2 GEMMs (128x128, chunk 64, 3-stage, occ 2) =====================
// z 0,1: shared experts -> comb / bufC (dense). z 2..7: routed -> bufA/bufB by rank.
#define P2_A 0
#define P2_B 18432
#define P2_STG 36864
#define P2_SMEM (3*P2_STG)   // 110592

__global__ void __launch_bounds__(256, 2) mm2_all_kernel()
{
    extern __shared__ char smem[];
    const int z = blockIdx.z;
    const fp16* A = g_hall + (size_t)z * NTOK * HIDC;
    const fp16* B;
    int M; int e = z - 2;
    if (z < 2) { B = g_wt + W2S_OFF + (size_t)z * E2; M = NTOK; }
    else       { B = g_wt + W2R_OFF + (size_t)e * E2; M = g_cnt[e]; }
    const int mBase = blockIdx.y * 128;
    if (mBase >= M) return;
    const int nBase = blockIdx.x * 128;
    const uint32_t sb = s2u(smem);
    const int tid = threadIdx.x;

    auto load = [&](int buf, int k0) {
        uint32_t su = sb + buf * P2_STG;
#pragma unroll
        for (int it = 0; it < 4; it++) {
            int idx = tid + it * 256;
            int row = idx >> 3, seg = idx & 7;
            uint32_t so = row * 144 + seg * 16;
            int ar = mBase + row; if (ar >= M) ar = mBase;
            cpa(su + P2_A + so, A + (size_t)ar * HIDC + k0 + seg * 8);
            cpa(su + P2_B + so, B + (size_t)(nBase + row) * HIDC + k0 + seg * 8);
        }
        cpa_commit();
    };

    const int lane = tid & 31, wid = tid >> 5;
    const int wm = (wid & 1) * 64;
    const int wn = (wid >> 1) * 32;
    const int arow = (lane & 7) + ((lane >> 3) & 1) * 8;
    const int akh  = (lane >> 4) & 1;
    const int brow = (lane & 7) + ((lane >> 4) & 1) * 8;
    const int bkh  = (lane >> 3) & 1;

    float acc[4][4][4];
#pragma unroll
    for (int i = 0; i < 4; i++)
#pragma unroll
        for (int j = 0; j < 4; j++)
#pragma unroll
            for (int k = 0; k < 4; k++) acc[i][j][k] = 0.f;

    const int nc = HIDC / 64;
    load(0, 0);
    load(1, 64);
    for (int c = 0; c < nc; c++) {
        if (c + 1 < nc) asm volatile("cp.async.wait_group 1;" ::: "memory");
        else            asm volatile("cp.async.wait_group 0;" ::: "memory");
        __syncthreads();
        if (c + 2 < nc) load((c + 2) % 3, (c + 2) * 64);
        uint32_t su = sb + (c % 3) * P2_STG;
#pragma unroll
        for (int s = 0; s < 4; s++) {
            uint32_t a[4][4];
#pragma unroll
            for (int mi = 0; mi < 4; mi++) {
                uint32_t ao = (uint32_t)(wm + mi * 16 + arow) * 144 + s * 32 + akh * 16;
                ldsm4(a[mi], su + P2_A + ao);
            }
#pragma unroll
            for (int np = 0; np < 2; np++) {
                uint32_t b[4];
                uint32_t bo = (uint32_t)(wn + np * 16 + brow) * 144 + s * 32 + bkh * 16;
                ldsm4(b, su + P2_B + bo);
#pragma unroll
                for (int mi = 0; mi < 4; mi++)
#pragma unroll
                    for (int h = 0; h < 2; h++)
                        mma16816(acc[mi][np * 2 + h], a[mi], &b[h * 2]);
            }
        }
    }

#pragma unroll
    for (int mi = 0; mi < 4; mi++)
#pragma unroll
        for (int half = 0; half < 2; half++) {
            int slot = mBase + wm + mi * 16 + (lane >> 2) + half * 8;
            if (slot < M) {
                float* base;
                int t;
                if (z < 2) {
                    base = z ? g_bufC : g_comb; t = slot;
                } else {
                    t = g_list[e * NTOK + slot];
                    base = g_lrank[e * NTOK + slot] ? g_bufB : g_bufA;
                }
                float* cp = base + (size_t)t * DIMC + nBase + wn + (lane & 3) * 2;
#pragma unroll
                for (int nt = 0; nt < 4; nt++)
                    *(float2*)(cp + nt * 8) = make_float2(acc[mi][nt][half * 2 + 0],
                                                          acc[mi][nt][half * 2 + 1]);
            }
        }
}

// outproj: out = g_hc @ outw (K=1024)
__global__ void __launch_bounds__(256, 2) outproj_kernel(float* __restrict__ out)
{
    extern __shared__ char smem[];
    const int mBase = blockIdx.y * 128;
    const int nBase = blockIdx.x * 128;
    const fp16* B = g_wt + OUTW_OFF;
    const uint32_t sb = s2u(smem);
    const int tid = threadIdx.x;

    auto load = [&](int buf, int k0) {
        uint32_t su = sb + buf * P2_STG;
#pragma unroll
        for (int it = 0; it < 4; it++) {
            int idx = tid + it * 256;
            int row = idx >> 3, seg = idx & 7;
            uint32_t so = row * 144 + seg * 16;
            cpa(su + P2_A + so, g_hc + (size_t)(mBase + row) * DIMC + k0 + seg * 8);
            cpa(su + P2_B + so, B + (size_t)(nBase + row) * DIMC + k0 + seg * 8);
        }
        cpa_commit();
    };

    const int lane = tid & 31, wid = tid >> 5;
    const int wm = (wid & 1) * 64;
    const int wn = (wid >> 1) * 32;
    const int arow = (lane & 7) + ((lane >> 3) & 1) * 8;
    const int akh  = (lane >> 4) & 1;
    const int brow = (lane & 7) + ((lane >> 4) & 1) * 8;
    const int bkh  = (lane >> 3) & 1;

    float acc[4][4][4];
#pragma unroll
    for (int i = 0; i < 4; i++)
#pragma unroll
        for (int j = 0; j < 4; j++)
#pragma unroll
            for (int k = 0; k < 4; k++) acc[i][j][k] = 0.f;

    const int nc = DIMC / 64;
    load(0, 0);
    load(1, 64);
    for (int c = 0; c < nc; c++) {
        if (c + 1 < nc) asm volatile("cp.async.wait_group 1;" ::: "memory");
        else            asm volatile("cp.async.wait_group 0;" ::: "memory");
        __syncthreads();
        if (c + 2 < nc) load((c + 2) % 3, (c + 2) * 64);
        uint32_t su = sb + (c % 3) * P2_STG;
#pragma unroll
        for (int s = 0; s < 4; s++) {
            uint32_t a[4][4];
#pragma unroll
            for (int mi = 0; mi < 4; mi++) {
                uint32_t ao = (uint32_t)(wm + mi * 16 + arow) * 144 + s * 32 + akh * 16;
                ldsm4(a[mi], su + P2_A + ao);
            }
#pragma unroll
            for (int np = 0; np < 2; np++) {
                uint32_t b[4];
                uint32_t bo = (uint32_t)(wn + np * 16 + brow) * 144 + s * 32 + bkh * 16;
                ldsm4(b, su + P2_B + bo);
#pragma unroll
                for (int mi = 0; mi < 4; mi++)
#pragma unroll
                    for (int h = 0; h < 2; h++)
                        mma16816(acc[mi][np * 2 + h], a[mi], &b[h * 2]);
            }
        }
    }

#pragma unroll
    for (int mi = 0; mi < 4; mi++)
#pragma unroll
        for (int half = 0; half < 2; half++) {
            int t = mBase + wm + mi * 16 + (lane >> 2) + half * 8;
            float* cp = out + (size_t)t * DIMC + nBase + wn + (lane & 3) * 2;
#pragma unroll
            for (int nt = 0; nt < 4; nt++)
                *(float2*)(cp + nt * 8) = make_float2(acc[mi][nt][half * 2 + 0],
                                                      acc[mi][nt][half * 2 + 1]);
        }
}

// ===================== host =====================
extern "C" void kernel_launch(void* const* d_in, const int* in_sizes, int n_in,
                              void* d_out, int out_size)
{
    const float* x      = (const float*)d_in[0];
    const float* w1_s   = (const float*)d_in[1];
    const float* w2_s   = (const float*)d_in[2];
    const float* w3_s   = (const float*)d_in[3];
    const float* w1_r   = (const float*)d_in[4];
    const float* w2_r   = (const float*)d_in[5];
    const float* w3_r   = (const float*)d_in[6];
    const float* gate_w = (const float*)d_in[7];
    const float* out_w  = (const float*)d_in[8];
    float* out = (float*)d_out;

    cudaFuncSetAttribute(mm1_all_kernel, cudaFuncAttributeMaxDynamicSharedMemorySize, P1_SMEM);
    cudaFuncSetAttribute(mm2_all_kernel, cudaFuncAttributeMaxDynamicSharedMemorySize, P2_SMEM);
    cudaFuncSetAttribute(outproj_kernel, cudaFuncAttributeMaxDynamicSharedMemorySize, P2_SMEM);

    // 1: activations (+counter zeroing)
    convx_kernel<<<(NTOK * DIMC) / 512, 256>>>(x);
    // 2: gate
    gate_kernel<<<NTOK / 8, 256>>>(x, gate_w);
    // 3: all 25 weight matrices
    {
        dim3 g(64, 64, 25);
        convt_all_kernel<<<g, 256>>>(w1_s, w3_s, w2_s, w1_r, w3_r, w2_r, out_w);
    }
    // 4: all 8 pass-1 GEMMs (profiled by ncu)
    {
        dim3 g(HIDC / 64, NTOK / 128, 8);
        mm1_all_kernel<<<g, 256, P1_SMEM>>>();
    }
    // 5: all 8 pass-2 GEMMs (shared + routed merged)
    {
        dim3 g(DIMC / 128, NTOK / 128, 8);
        mm2_all_kernel<<<g, 256, P2_SMEM>>>();
    }
    // 6: combine (+aux loss)
    convc4_kernel<<<(NTOK * DIMC) / 512, 256>>>(
        out_size > NTOK * DIMC ? out + (out_size - 1) : nullptr);
    // 7: out projection
    {
        dim3 g(DIMC / 128, NTOK / 128);
        outproj_kernel<<<g, 256, P2_SMEM>>>(out);
    }
}